// round 10
// baseline (speedup 1.0000x reference)
#include <cuda_runtime.h>
#include <math.h>
#include <stdint.h>

// ---------------- problem constants ----------------
#define BB 4
#define TT 512
#define DD 768
#define HH 12
#define DKC 64
#define FFC 3072
#define TBN 64
#define NEGV (-1e9f)
#define E_CONST 2.718281828459045f
#define MROWS (BB*TT)            // 2048

// ---------------- scratch layout (floats) ----------------
#define OF_H    0ull
#define OF_BIAS 6291456ull
#define OF_S    7340032ull
#define OF_QKV  OF_S
#define OF_BQKV (OF_S + 4718592ull)
#define OF_A    19922944ull
#define OF_X2   21495808ull
#define OF_F    23068672ull
#define OF_WQT  29360128ull
#define OF_WPT  31129600ull
#define OF_F1T  31719424ull
#define OF_F2T  34078720ull
#define SCRATCH_TOTAL 36438016ull

__device__ float g_scratch[SCRATCH_TOTAL];

// ---------------- helpers ----------------
__device__ __forceinline__ uint32_t smem_u32(const void* p) {
    uint32_t a;
    asm("{ .reg .u64 t; cvta.to.shared.u64 t, %1; cvt.u32.u64 %0, t; }" : "=r"(a) : "l"(p));
    return a;
}
__device__ __forceinline__ float f2tf32f(float f) {
    uint32_t r; asm("cvt.rna.tf32.f32 %0, %1;" : "=r"(r) : "f"(f));
    return __uint_as_float(r);
}
#define CP_ASYNC16(dst_u32, src_ptr) \
    asm volatile("cp.async.cg.shared.global [%0], [%1], 16;\n" :: "r"(dst_u32), "l"(__cvta_generic_to_global(src_ptr)))
#define CP_COMMIT() asm volatile("cp.async.commit_group;\n" ::: "memory")
#define CP_WAIT2()  asm volatile("cp.async.wait_group 2;\n" ::: "memory")
#define CP_WAIT1()  asm volatile("cp.async.wait_group 1;\n" ::: "memory")
#define CP_WAIT0()  asm volatile("cp.async.wait_group 0;\n" ::: "memory")

#define MMA_TF32(c0,c1,c2,c3,a0,a1,a2,a3,b0,b1) \
    asm volatile("mma.sync.aligned.m16n8k8.row.col.f32.tf32.tf32.f32 " \
                 "{%0,%1,%2,%3}, {%4,%5,%6,%7}, {%8,%9}, {%0,%1,%2,%3};\n" \
                 : "+f"(c0), "+f"(c1), "+f"(c2), "+f"(c3) \
                 : "r"(a0), "r"(a1), "r"(a2), "r"(a3), "r"(b0), "r"(b1))

#define LDSM_X4(d0,d1,d2,d3,addr) \
    asm volatile("ldmatrix.sync.aligned.m8n8.x4.shared.b16 {%0,%1,%2,%3}, [%4];\n" \
                 : "=r"(d0), "=r"(d1), "=r"(d2), "=r"(d3) : "r"(addr))

#define LDT 20
#define BM 128

// =======================================================================
// big-tile GEMM — 128x128, 3-stage, warp tile 32x64. For QKV (N=2304).
// =======================================================================
#define BN2 128
#define GST2 3
#define GEMM_SMEM2 ((GST2*(BM+BN2)*LDT)*4)   // 61440

template <int EPI>  // 0 bias
__global__ __launch_bounds__(256, 2) void gemm_big(const float* __restrict__ A,
                                                   const float* __restrict__ Wt,
                                                   const float* __restrict__ bias,
                                                   float* __restrict__ C,
                                                   int N, int K) {
    extern __shared__ float dsm[];
    float* AsBase = dsm;
    float* BsBase = dsm + GST2 * BM * LDT;

    int tid = threadIdx.x;
    int warp = tid >> 5, lane = tid & 31;
    int wm = warp >> 1, wn = warp & 1;
    int g = lane >> 2, tig = lane & 3;
    int m0 = blockIdx.y * BM, n0 = blockIdx.x * BN2;

    int r0 = tid >> 2,            c0_ = (tid & 3) * 4;
    int r1 = (tid + 256) >> 2,    c1_ = ((tid + 256) & 3) * 4;

    uint32_t sA = smem_u32(AsBase);
    uint32_t sB = smem_u32(BsBase);
    const uint32_t bufA = BM * LDT * 4, bufB = BN2 * LDT * 4;

    int q = lane >> 3, l7 = lane & 7;
    int a_row = wm * 32 + (q & 1) * 8 + l7,  a_col = (q >> 1) * 4;
    int b_row = wn * 64 + (q >> 1) * 8 + l7, b_col = (q & 1) * 4;
    uint32_t aAddr0 = sA + (uint32_t)(a_row * LDT + a_col) * 4;
    uint32_t bAddr0 = sB + (uint32_t)(b_row * LDT + b_col) * 4;

    const int nk = K >> 4;

    #pragma unroll
    for (int pf = 0; pf < 2; pf++) {
        int k0 = pf * 16;
        CP_ASYNC16(sA + pf * bufA + (r0 * LDT + c0_) * 4, A + (size_t)(m0 + r0) * K + k0 + c0_);
        CP_ASYNC16(sA + pf * bufA + (r1 * LDT + c1_) * 4, A + (size_t)(m0 + r1) * K + k0 + c1_);
        CP_ASYNC16(sB + pf * bufB + (r0 * LDT + c0_) * 4, Wt + (size_t)(n0 + r0) * K + k0 + c0_);
        CP_ASYNC16(sB + pf * bufB + (r1 * LDT + c1_) * 4, Wt + (size_t)(n0 + r1) * K + k0 + c1_);
        CP_COMMIT();
    }

    float c[2][8][4];
    #pragma unroll
    for (int i = 0; i < 2; i++)
        #pragma unroll
        for (int j = 0; j < 8; j++)
            #pragma unroll
            for (int e = 0; e < 4; e++) c[i][j][e] = 0.f;

    for (int kt = 0; kt < nk; kt++) {
        int buf = kt % GST2;
        CP_WAIT1();
        __syncthreads();

        uint32_t aBuf = aAddr0 + buf * bufA;
        uint32_t bBuf = bAddr0 + buf * bufB;
        #pragma unroll
        for (int ks = 0; ks < 2; ks++) {
            uint32_t kOff = (uint32_t)(ks * 8) * 4;
            uint32_t a[2][4], b[8][2];
            #pragma unroll
            for (int i = 0; i < 2; i++)
                LDSM_X4(a[i][0], a[i][1], a[i][2], a[i][3],
                        aBuf + (uint32_t)(i * 16 * LDT) * 4 + kOff);
            #pragma unroll
            for (int p = 0; p < 4; p++)
                LDSM_X4(b[2*p][0], b[2*p][1], b[2*p+1][0], b[2*p+1][1],
                        bBuf + (uint32_t)(p * 16 * LDT) * 4 + kOff);
            #pragma unroll
            for (int i = 0; i < 2; i++)
                #pragma unroll
                for (int j = 0; j < 8; j++)
                    MMA_TF32(c[i][j][0], c[i][j][1], c[i][j][2], c[i][j][3],
                             a[i][0], a[i][1], a[i][2], a[i][3], b[j][0], b[j][1]);
        }

        if (kt + 2 < nk) {
            int k0 = (kt + 2) * 16;
            int nbuf = (kt + 2) % GST2;
            CP_ASYNC16(sA + nbuf * bufA + (r0 * LDT + c0_) * 4, A + (size_t)(m0 + r0) * K + k0 + c0_);
            CP_ASYNC16(sA + nbuf * bufA + (r1 * LDT + c1_) * 4, A + (size_t)(m0 + r1) * K + k0 + c1_);
            CP_ASYNC16(sB + nbuf * bufB + (r0 * LDT + c0_) * 4, Wt + (size_t)(n0 + r0) * K + k0 + c0_);
            CP_ASYNC16(sB + nbuf * bufB + (r1 * LDT + c1_) * 4, Wt + (size_t)(n0 + r1) * K + k0 + c1_);
        }
        CP_COMMIT();
    }

    #pragma unroll
    for (int i = 0; i < 2; i++) {
        int row0 = m0 + wm * 32 + i * 16 + g;
        #pragma unroll
        for (int j = 0; j < 8; j++) {
            int col = n0 + wn * 64 + j * 8 + 2 * tig;
            float b0 = bias[col], b1 = bias[col + 1];
            #pragma unroll
            for (int half = 0; half < 2; half++) {
                int r = row0 + half * 8;
                float2 o;
                o.x = c[i][j][half * 2 + 0] + b0;
                o.y = c[i][j][half * 2 + 1] + b1;
                *(float2*)(C + (size_t)r * N + col) = o;
            }
        }
    }
}

// =======================================================================
// n96 GEMM — 128x96 tile, 4-stage, warp tile 32x48.
// EPI 1 = bias+residual (proj, FFN2); EPI 2 = bias+GELU+tf32round (FFN1).
// =======================================================================
#define BN3 96
#define GST3 4
#define GEMM_SMEM3 ((GST3*(BM+BN3)*LDT)*4)   // 71680

template <int EPI>
__global__ __launch_bounds__(256, 2) void gemm_n96(const float* __restrict__ A,
                                                   const float* __restrict__ Wt,
                                                   const float* __restrict__ bias,
                                                   const float* __restrict__ res,
                                                   float* __restrict__ C,
                                                   int N, int K) {
    extern __shared__ float dsm[];
    float* AsBase = dsm;
    float* BsBase = dsm + GST3 * BM * LDT;

    int tid = threadIdx.x;
    int warp = tid >> 5, lane = tid & 31;
    int wm = warp >> 1, wn = warp & 1;
    int g = lane >> 2, tig = lane & 3;
    int m0 = blockIdx.y * BM, n0 = blockIdx.x * BN3;

    int ar0 = tid >> 2,            ac0 = (tid & 3) * 4;
    int ar1 = (tid + 256) >> 2,    ac1 = ((tid + 256) & 3) * 4;
    int br0 = tid >> 2,            bc0 = (tid & 3) * 4;
    int br1 = (tid + 256) >> 2,    bc1 = ((tid + 256) & 3) * 4;
    bool hasB1 = (tid < 128);

    uint32_t sA = smem_u32(AsBase);
    uint32_t sB = smem_u32(BsBase);
    const uint32_t bufA = BM * LDT * 4, bufB = BN3 * LDT * 4;

    int q = lane >> 3, l7 = lane & 7;
    int a_row = wm * 32 + (q & 1) * 8 + l7,  a_col = (q >> 1) * 4;
    int b_row = wn * 48 + (q >> 1) * 8 + l7, b_col = (q & 1) * 4;
    uint32_t aAddr0 = sA + (uint32_t)(a_row * LDT + a_col) * 4;
    uint32_t bAddr0 = sB + (uint32_t)(b_row * LDT + b_col) * 4;

    const int nk = K >> 4;

    #pragma unroll
    for (int pf = 0; pf < 3; pf++) {
        int k0 = pf * 16;
        CP_ASYNC16(sA + pf * bufA + (ar0 * LDT + ac0) * 4, A + (size_t)(m0 + ar0) * K + k0 + ac0);
        CP_ASYNC16(sA + pf * bufA + (ar1 * LDT + ac1) * 4, A + (size_t)(m0 + ar1) * K + k0 + ac1);
        CP_ASYNC16(sB + pf * bufB + (br0 * LDT + bc0) * 4, Wt + (size_t)(n0 + br0) * K + k0 + bc0);
        if (hasB1)
            CP_ASYNC16(sB + pf * bufB + (br1 * LDT + bc1) * 4, Wt + (size_t)(n0 + br1) * K + k0 + bc1);
        CP_COMMIT();
    }

    float c[2][6][4];
    #pragma unroll
    for (int i = 0; i < 2; i++)
        #pragma unroll
        for (int j = 0; j < 6; j++)
            #pragma unroll
            for (int e = 0; e < 4; e++) c[i][j][e] = 0.f;

    for (int kt = 0; kt < nk; kt++) {
        int buf = kt & (GST3 - 1);
        CP_WAIT2();
        __syncthreads();

        uint32_t aBuf = aAddr0 + buf * bufA;
        uint32_t bBuf = bAddr0 + buf * bufB;
        #pragma unroll
        for (int ks = 0; ks < 2; ks++) {
            uint32_t kOff = (uint32_t)(ks * 8) * 4;
            uint32_t a[2][4], b[6][2];
            #pragma unroll
            for (int i = 0; i < 2; i++)
                LDSM_X4(a[i][0], a[i][1], a[i][2], a[i][3],
                        aBuf + (uint32_t)(i * 16 * LDT) * 4 + kOff);
            #pragma unroll
            for (int p = 0; p < 3; p++)
                LDSM_X4(b[2*p][0], b[2*p][1], b[2*p+1][0], b[2*p+1][1],
                        bBuf + (uint32_t)(p * 16 * LDT) * 4 + kOff);
            #pragma unroll
            for (int i = 0; i < 2; i++)
                #pragma unroll
                for (int j = 0; j < 6; j++)
                    MMA_TF32(c[i][j][0], c[i][j][1], c[i][j][2], c[i][j][3],
                             a[i][0], a[i][1], a[i][2], a[i][3], b[j][0], b[j][1]);
        }

        if (kt + 3 < nk) {
            int k0 = (kt + 3) * 16;
            int nbuf = (kt + 3) & (GST3 - 1);
            CP_ASYNC16(sA + nbuf * bufA + (ar0 * LDT + ac0) * 4, A + (size_t)(m0 + ar0) * K + k0 + ac0);
            CP_ASYNC16(sA + nbuf * bufA + (ar1 * LDT + ac1) * 4, A + (size_t)(m0 + ar1) * K + k0 + ac1);
            CP_ASYNC16(sB + nbuf * bufB + (br0 * LDT + bc0) * 4, Wt + (size_t)(n0 + br0) * K + k0 + bc0);
            if (hasB1)
                CP_ASYNC16(sB + nbuf * bufB + (br1 * LDT + bc1) * 4, Wt + (size_t)(n0 + br1) * K + k0 + bc1);
        }
        CP_COMMIT();
    }

    #pragma unroll
    for (int i = 0; i < 2; i++) {
        int row0 = m0 + wm * 32 + i * 16 + g;
        #pragma unroll
        for (int j = 0; j < 6; j++) {
            int col = n0 + wn * 48 + j * 8 + 2 * tig;
            float b0 = bias[col], b1 = bias[col + 1];
            #pragma unroll
            for (int half = 0; half < 2; half++) {
                int r = row0 + half * 8;
                float v0 = c[i][j][half * 2 + 0] + b0;
                float v1 = c[i][j][half * 2 + 1] + b1;
                if (EPI == 1) {
                    float2 r2 = *(const float2*)(res + (size_t)r * N + col);
                    v0 += r2.x; v1 += r2.y;
                }
                if (EPI == 2) {
                    v0 = 0.5f * v0 * (1.f + erff(v0 * 0.70710678118654752f));
                    v1 = 0.5f * v1 * (1.f + erff(v1 * 0.70710678118654752f));
                    v0 = f2tf32f(v0); v1 = f2tf32f(v1);
                }
                float2 o; o.x = v0; o.y = v1;
                *(float2*)(C + (size_t)r * N + col) = o;
            }
        }
    }
}

// ---------------- merged transposes (tf32-rounded) ----------------
__global__ __launch_bounds__(256) void transpose_attn(const float* __restrict__ wq,
                                                      const float* __restrict__ wk,
                                                      const float* __restrict__ wv,
                                                      const float* __restrict__ wp,
                                                      float* __restrict__ dst) {
    __shared__ float t[32][33];
    int z = blockIdx.z;
    const float* W = (z == 0) ? wq : (z == 1) ? wk : (z == 2) ? wv : wp;
    float* Wt = dst + (size_t)z * 589824;
    int n0 = blockIdx.x * 32, k0 = blockIdx.y * 32;
    int tx = threadIdx.x, ty = threadIdx.y;
    #pragma unroll
    for (int i = 0; i < 32; i += 8)
        t[ty + i][tx] = W[(size_t)(k0 + ty + i) * DD + n0 + tx];
    __syncthreads();
    #pragma unroll
    for (int i = 0; i < 32; i += 8)
        Wt[(size_t)(n0 + ty + i) * DD + k0 + tx] = f2tf32f(t[tx][ty + i]);
}

__global__ __launch_bounds__(256) void transpose_ffn(const float* __restrict__ f1w,
                                                     float* __restrict__ f1T,
                                                     const float* __restrict__ f2w,
                                                     float* __restrict__ f2T) {
    __shared__ float t[32][33];
    int z = blockIdx.z;
    const float* W; float* Wt; int K, N, n0, k0;
    if (z == 0) { W = f1w; Wt = f1T; K = DD;  N = FFC; n0 = blockIdx.x * 32; k0 = blockIdx.y * 32; }
    else        { W = f2w; Wt = f2T; K = FFC; N = DD;  n0 = blockIdx.y * 32; k0 = blockIdx.x * 32; }
    int tx = threadIdx.x, ty = threadIdx.y;
    #pragma unroll
    for (int i = 0; i < 32; i += 8)
        t[ty + i][tx] = W[(size_t)(k0 + ty + i) * N + n0 + tx];
    __syncthreads();
    #pragma unroll
    for (int i = 0; i < 32; i += 8)
        Wt[(size_t)(n0 + ty + i) * K + k0 + tx] = f2tf32f(t[tx][ty + i]);
}

__global__ void concat_bias(const float* __restrict__ a, const float* __restrict__ b,
                            const float* __restrict__ c, float* __restrict__ o) {
    int t = blockIdx.x * 256 + threadIdx.x;
    if (t < 768) o[t] = a[t];
    else if (t < 1536) o[t] = b[t - 768];
    else if (t < 2304) o[t] = c[t - 1536];
}

// ---------------- LayerNorm (tf32-rounded output) ----------------
__global__ __launch_bounds__(256) void ln_kernel(const float* __restrict__ x,
                                                 const float* __restrict__ g,
                                                 const float* __restrict__ b,
                                                 float* __restrict__ out) {
    int row = blockIdx.x;
    const float* xr = x + (size_t)row * DD;
    float s = 0.f, s2 = 0.f;
    for (int i = threadIdx.x; i < DD; i += 256) { float v = xr[i]; s += v; s2 += v * v; }
    #pragma unroll
    for (int o = 16; o > 0; o >>= 1) {
        s  += __shfl_xor_sync(0xffffffffu, s,  o);
        s2 += __shfl_xor_sync(0xffffffffu, s2, o);
    }
    __shared__ float ws[8], ws2[8];
    int w = threadIdx.x >> 5, l = threadIdx.x & 31;
    if (l == 0) { ws[w] = s; ws2[w] = s2; }
    __syncthreads();
    if (w == 0) {
        s  = (l < 8) ? ws[l]  : 0.f;
        s2 = (l < 8) ? ws2[l] : 0.f;
        #pragma unroll
        for (int o = 4; o > 0; o >>= 1) {
            s  += __shfl_xor_sync(0xffffffffu, s,  o);
            s2 += __shfl_xor_sync(0xffffffffu, s2, o);
        }
        if (l == 0) { ws[0] = s; ws2[0] = s2; }
    }
    __syncthreads();
    float mean = ws[0] * (1.f / DD);
    float var  = ws2[0] * (1.f / DD) - mean * mean;
    float inv  = rsqrtf(var + 1e-5f);
    float* orow = out + (size_t)row * DD;
    for (int i = threadIdx.x; i < DD; i += 256)
        orow[i] = f2tf32f((xr[i] - mean) * inv * g[i] + b[i]);
}

// ---------------- temporal bias w/ masks baked in (fast math) ----------------
__global__ __launch_bounds__(256) void bias_kernel(const float* __restrict__ tm,
                                                   const int* __restrict__ pm,
                                                   const float* __restrict__ t1w,
                                                   const float* __restrict__ t1b,
                                                   const float* __restrict__ t2w,
                                                   const float* __restrict__ t2b) {
    __shared__ float w1[TBN], b1[TBN], w2[TBN];
    int t = threadIdx.x;
    if (t < TBN) { w1[t] = t1w[t]; b1[t] = t1b[t]; w2[t] = t2w[t]; }
    __syncthreads();
    size_t idx = (size_t)blockIdx.x * 256 + t;
    int rem = (int)(idx % (TT * TT));
    int i = rem / TT, j = rem % TT;
    float u = __fdividef(1.f, __logf(E_CONST + tm[idx]));
    float s = t2b[0];
    #pragma unroll
    for (int k = 0; k < TBN; k++) {
        float z = fmaf(u, w1[k], b1[k]);
        z = (z > 0.f) ? z : 0.2f * z;
        s = fmaf(z, w2[k], s);
    }
    bool masked = (pm[idx] == 0) || (j > i && i > 0);
    g_scratch[OF_BIAS + idx] = masked ? NEGV : s;
}

// =======================================================================
// flash attention — ldmatrix fragment loads for Q/K/P (bit-identical data)
// =======================================================================
#define SQ_LD 68
#define SV_LD 72
#define FS_Q    0
#define FS_K    (64*68)
#define FS_V    (FS_K + 2*64*68)
#define FS_P    (FS_V + 2*64*72)
#define FS_STAT (FS_P + 64*68)
#define FS_TOT  ((FS_STAT + 256) * 4)

__global__ __launch_bounds__(256, 2) void flash_kernel(const float* __restrict__ qkv,
                                                       float* __restrict__ outA) {
    extern __shared__ float fs[];
    float* sQ = fs + FS_Q;
    float* sK = fs + FS_K;
    float* sV = fs + FS_V;
    float* sP = fs + FS_P;
    float* sMax = fs + FS_STAT;
    float* sSum = fs + FS_STAT + 128;
    uint32_t sQu = smem_u32(sQ), sKu = smem_u32(sK), sVu = smem_u32(sV), sPu = smem_u32(sP);

    int tid = threadIdx.x;
    int warp = tid >> 5, lane = tid & 31;
    int wm = warp >> 1, wn = warp & 1;
    int g = lane >> 2, tig = lane & 3;
    int i0 = blockIdx.x * 64;
    int bh = blockIdx.y, b = bh / HH, h = bh % HH;

    const float* base = qkv + (size_t)b * TT * 2304 + h * 64;
    const float* biasB = g_scratch + OF_BIAS + (size_t)b * TT * TT;

    // ldmatrix fragment addresses
    int q = lane >> 3, l7 = lane & 7;
    uint32_t qFrag = sQu + (uint32_t)((wm * 16 + (q & 1) * 8 + l7) * SQ_LD + (q >> 1) * 4) * 4;
    uint32_t kFrag = sKu + (uint32_t)((wn * 32 + (q >> 1) * 8 + l7) * SQ_LD + (q & 1) * 4) * 4;
    uint32_t pFrag = sPu + (uint32_t)((wm * 16 + (q & 1) * 8 + l7) * SQ_LD + (q >> 1) * 4) * 4;

    // load Q tile, scale by 1/8, round to tf32
    for (int ch = tid; ch < 1024; ch += 256) {
        int r = ch >> 4, cc = (ch & 15) * 4;
        float4 v = *(const float4*)(base + (size_t)(i0 + r) * 2304 + cc);
        float4 o;
        o.x = f2tf32f(v.x * 0.125f); o.y = f2tf32f(v.y * 0.125f);
        o.z = f2tf32f(v.z * 0.125f); o.w = f2tf32f(v.w * 0.125f);
        *(float4*)(sQ + r * SQ_LD + cc) = o;
    }

    float o[4][4];
    #pragma unroll
    for (int j = 0; j < 4; j++)
        #pragma unroll
        for (int e = 0; e < 4; e++) o[j][e] = 0.f;
    float m0r = -INFINITY, m1r = -INFINITY, l0 = 0.f, l1 = 0.f;

    int ntiles = (i0 == 0) ? (TT / 64) : (i0 >> 6) + 1;
    int rw0 = wm * 16 + g, rw1 = rw0 + 8;

    {
        const float* kb_ = base + 768;
        const float* vb_ = base + 1536;
        for (int ch = tid; ch < 1024; ch += 256) {
            int r = ch >> 4, cc = (ch & 15) * 4;
            CP_ASYNC16(sKu + (r * SQ_LD + cc) * 4, kb_ + (size_t)r * 2304 + cc);
            CP_ASYNC16(sVu + (r * SV_LD + cc) * 4, vb_ + (size_t)r * 2304 + cc);
        }
        CP_COMMIT();
    }

    for (int t = 0; t < ntiles; t++) {
        int j0 = t * 64, buf = t & 1;
        CP_WAIT0();
        __syncthreads();

        // ---- S = Qs @ Ks^T (ldmatrix fragments) ----
        float c[4][4];
        #pragma unroll
        for (int j = 0; j < 4; j++)
            #pragma unroll
            for (int e = 0; e < 4; e++) c[j][e] = 0.f;
        uint32_t kBuf = kFrag + (uint32_t)(buf * 64 * SQ_LD) * 4;
        #pragma unroll
        for (int kb = 0; kb < 64; kb += 8) {
            uint32_t kOff = (uint32_t)kb * 4;
            uint32_t a[4], bfr[4][2];
            LDSM_X4(a[0], a[1], a[2], a[3], qFrag + kOff);
            LDSM_X4(bfr[0][0], bfr[0][1], bfr[1][0], bfr[1][1], kBuf + kOff);
            LDSM_X4(bfr[2][0], bfr[2][1], bfr[3][0], bfr[3][1],
                    kBuf + (uint32_t)(16 * SQ_LD) * 4 + kOff);
            #pragma unroll
            for (int j = 0; j < 4; j++)
                MMA_TF32(c[j][0], c[j][1], c[j][2], c[j][3],
                         a[0], a[1], a[2], a[3], bfr[j][0], bfr[j][1]);
        }

        int gi0 = i0 + rw0, gi1 = i0 + rw1;
        #pragma unroll
        for (int j = 0; j < 4; j++) {
            int gj = j0 + wn * 32 + j * 8 + 2 * tig;
            float2 b0 = *(const float2*)(biasB + (size_t)gi0 * TT + gj);
            float2 b1 = *(const float2*)(biasB + (size_t)gi1 * TT + gj);
            c[j][0] += b0.x; c[j][1] += b0.y;
            c[j][2] += b1.x; c[j][3] += b1.y;
        }

        float mx0 = c[0][0], mx1 = c[0][2];
        #pragma unroll
        for (int j = 0; j < 4; j++) {
            mx0 = fmaxf(mx0, fmaxf(c[j][0], c[j][1]));
            mx1 = fmaxf(mx1, fmaxf(c[j][2], c[j][3]));
        }
        mx0 = fmaxf(mx0, __shfl_xor_sync(0xffffffffu, mx0, 1));
        mx0 = fmaxf(mx0, __shfl_xor_sync(0xffffffffu, mx0, 2));
        mx1 = fmaxf(mx1, __shfl_xor_sync(0xffffffffu, mx1, 1));
        mx1 = fmaxf(mx1, __shfl_xor_sync(0xffffffffu, mx1, 2));
        if (tig == 0) { sMax[wn * 64 + rw0] = mx0; sMax[wn * 64 + rw1] = mx1; }
        __syncthreads();
        float mxc0 = fmaxf(sMax[rw0], sMax[64 + rw0]);
        float mxc1 = fmaxf(sMax[rw1], sMax[64 + rw1]);

        float mn0 = fmaxf(m0r, mxc0), mn1 = fmaxf(m1r, mxc1);
        float al0 = __expf(m0r - mn0), al1 = __expf(m1r - mn1);

        float sum0 = 0.f, sum1 = 0.f;
        #pragma unroll
        for (int j = 0; j < 4; j++) {
            int cw = wn * 32 + j * 8 + 2 * tig;
            float p00 = __expf(c[j][0] - mn0), p01 = __expf(c[j][1] - mn0);
            float p10 = __expf(c[j][2] - mn1), p11 = __expf(c[j][3] - mn1);
            sum0 += p00 + p01; sum1 += p10 + p11;
            float2 q0; q0.x = p00; q0.y = p01;
            float2 q1; q1.x = p10; q1.y = p11;
            *(float2*)(sP + rw0 * SQ_LD + cw) = q0;
            *(float2*)(sP + rw1 * SQ_LD + cw) = q1;
        }
        sum0 += __shfl_xor_sync(0xffffffffu, sum0, 1);
        sum0 += __shfl_xor_sync(0xffffffffu, sum0, 2);
        sum1 += __shfl_xor_sync(0xffffffffu, sum1, 1);
        sum1 += __shfl_xor_sync(0xffffffffu, sum1, 2);
        if (tig == 0) { sSum[wn * 64 + rw0] = sum0; sSum[wn * 64 + rw1] = sum1; }
        __syncthreads();
        float sc0 = sSum[rw0] + sSum[64 + rw0];
        float sc1 = sSum[rw1] + sSum[64 + rw1];

        l0 = l0 * al0 + sc0;  l1 = l1 * al1 + sc1;
        m0r = mn0;  m1r = mn1;
        #pragma unroll
        for (int j = 0; j < 4; j++) {
            o[j][0] *= al0; o[j][1] *= al0;
            o[j][2] *= al1; o[j][3] *= al1;
        }

        if (t + 1 < ntiles) {
            int nj0 = (t + 1) * 64, nb = buf ^ 1;
            const float* kb_ = base + 768;
            const float* vb_ = base + 1536;
            for (int ch = tid; ch < 1024; ch += 256) {
                int r = ch >> 4, cc = (ch & 15) * 4;
                CP_ASYNC16(sKu + (nb * 64 * SQ_LD + r * SQ_LD + cc) * 4, kb_ + (size_t)(nj0 + r) * 2304 + cc);
                CP_ASYNC16(sVu + (nb * 64 * SV_LD + r * SV_LD + cc) * 4, vb_ + (size_t)(nj0 + r) * 2304 + cc);
            }
            CP_COMMIT();
        }

        // ---- O += P @ V (P via ldmatrix; V scalar, k-major) ----
        const float* vS = sV + buf * 64 * SV_LD;
        #pragma unroll
        for (int kb = 0; kb < 64; kb += 8) {
            uint32_t a[4], bfr[4][2];
            LDSM_X4(a[0], a[1], a[2], a[3], pFrag + (uint32_t)kb * 4);
            #pragma unroll
            for (int j = 0; j < 4; j++) {
                int nc = wn * 32 + j * 8 + g;
                bfr[j][0] = __float_as_uint(vS[(kb + tig)     * SV_LD + nc]);
                bfr[j][1] = __float_as_uint(vS[(kb + tig + 4) * SV_LD + nc]);
            }
            #pragma unroll
            for (int j = 0; j < 4; j++)
                MMA_TF32(o[j][0], o[j][1], o[j][2], o[j][3],
                         a[0], a[1], a[2], a[3], bfr[j][0], bfr[j][1]);
        }
        __syncthreads();
    }

    float inv0 = 1.f / l0, inv1 = 1.f / l1;
    int gr0 = b * TT + i0 + wm * 16 + g, gr1 = gr0 + 8;
    #pragma unroll
    for (int j = 0; j < 4; j++) {
        int col = h * 64 + wn * 32 + j * 8 + 2 * tig;
        float2 o0, o1;
        o0.x = f2tf32f(o[j][0] * inv0); o0.y = f2tf32f(o[j][1] * inv0);
        o1.x = f2tf32f(o[j][2] * inv1); o1.y = f2tf32f(o[j][3] * inv1);
        *(float2*)(outA + (size_t)gr0 * DD + col) = o0;
        *(float2*)(outA + (size_t)gr1 * DD + col) = o1;
    }
}

// ---------------- launch ----------------
extern "C" void kernel_launch(void* const* d_in, const int* in_sizes, int n_in,
                              void* d_out, int out_size) {
    const float* x     = (const float*)d_in[0];
    const float* tmat  = (const float*)d_in[1];
    const int*   pm    = (const int*)d_in[2];
    const float* wq = (const float*)d_in[3],  *bq = (const float*)d_in[4];
    const float* wk = (const float*)d_in[5],  *bk = (const float*)d_in[6];
    const float* wv = (const float*)d_in[7],  *bv = (const float*)d_in[8];
    const float* wp = (const float*)d_in[9],  *bp = (const float*)d_in[10];
    const float* t1w = (const float*)d_in[11], *t1b = (const float*)d_in[12];
    const float* t2w = (const float*)d_in[13], *t2b = (const float*)d_in[14];
    const float* f1w = (const float*)d_in[15], *f1b = (const float*)d_in[16];
    const float* f2w = (const float*)d_in[17], *f2b = (const float*)d_in[18];
    const float* ln1g = (const float*)d_in[19], *ln1b = (const float*)d_in[20];
    const float* ln2g = (const float*)d_in[21], *ln2b = (const float*)d_in[22];
    float* out = (float*)d_out;

    float* sc = nullptr;
    cudaGetSymbolAddress((void**)&sc, g_scratch);
    float* gH    = sc + OF_H;
    float* gQKV  = sc + OF_QKV;
    float* gBQKV = sc + OF_BQKV;
    float* gA    = sc + OF_A;
    float* gX2   = sc + OF_X2;
    float* gF    = sc + OF_F;
    float* wcT   = sc + OF_WQT;
    float* wpT   = sc + OF_WPT;
    float* f1T   = sc + OF_F1T;
    float* f2T   = sc + OF_F2T;

    static cudaStream_t sBias = nullptr, sTr = nullptr;
    static cudaEvent_t eFork = nullptr, eBias = nullptr, eTr = nullptr;
    if (sBias == nullptr) {
        cudaStreamCreateWithFlags(&sBias, cudaStreamNonBlocking);
        cudaStreamCreateWithFlags(&sTr, cudaStreamNonBlocking);
        cudaEventCreateWithFlags(&eFork, cudaEventDisableTiming);
        cudaEventCreateWithFlags(&eBias, cudaEventDisableTiming);
        cudaEventCreateWithFlags(&eTr, cudaEventDisableTiming);
        cudaFuncSetAttribute(gemm_big<0>, cudaFuncAttributeMaxDynamicSharedMemorySize, GEMM_SMEM2);
        cudaFuncSetAttribute(gemm_n96<1>, cudaFuncAttributeMaxDynamicSharedMemorySize, GEMM_SMEM3);
        cudaFuncSetAttribute(gemm_n96<2>, cudaFuncAttributeMaxDynamicSharedMemorySize, GEMM_SMEM3);
        cudaFuncSetAttribute(flash_kernel, cudaFuncAttributeMaxDynamicSharedMemorySize, FS_TOT);
    }

    dim3 tb(32, 8);

    // fork
    cudaEventRecord(eFork, 0);
    cudaStreamWaitEvent(sBias, eFork, 0);
    cudaStreamWaitEvent(sTr, eFork, 0);

    // branch B: temporal bias (needed only by flash)
    bias_kernel<<<(BB * TT * TT) / 256, 256, 0, sBias>>>(tmat, pm, t1w, t1b, t2w, t2b);
    cudaEventRecord(eBias, sBias);

    // branch C: weight transposes + bias concat (needed by GEMMs)
    transpose_attn<<<dim3(24, 24, 4), tb, 0, sTr>>>(wq, wk, wv, wp, wcT);
    transpose_ffn<<<dim3(96, 24, 2), tb, 0, sTr>>>(f1w, f1T, f2w, f2T);
    concat_bias<<<9, 256, 0, sTr>>>(bq, bk, bv, gBQKV);
    cudaEventRecord(eTr, sTr);

    // main chain
    ln_kernel<<<MROWS, 256>>>(x, ln1g, ln1b, gH);
    cudaStreamWaitEvent(0, eTr, 0);
    gemm_big<0><<<dim3(2304 / BN2, MROWS / BM), 256, GEMM_SMEM2>>>(gH, wcT, gBQKV, gQKV, 2304, DD);

    cudaStreamWaitEvent(0, eBias, 0);
    flash_kernel<<<dim3(TT / 64, BB * HH), 256, FS_TOT>>>(gQKV, gA);

    gemm_n96<1><<<dim3(DD / BN3, MROWS / BM), 256, GEMM_SMEM3>>>(gA, wpT, bp, x, gX2, DD, DD);

    ln_kernel<<<MROWS, 256>>>(gX2, ln2g, ln2b, gH);
    gemm_n96<2><<<dim3(FFC / BN3, MROWS / BM), 256, GEMM_SMEM3>>>(gH, f1T, f1b, nullptr, gF, FFC, DD);
    gemm_n96<1><<<dim3(DD / BN3, MROWS / BM), 256, GEMM_SMEM3>>>(gF, f2T, f2b, gX2, out, DD, FFC);
}

// round 11
// speedup vs baseline: 1.0346x; 1.0346x over previous
#include <cuda_runtime.h>
#include <math.h>
#include <stdint.h>

// ---------------- problem constants ----------------
#define BB 4
#define TT 512
#define DD 768
#define HH 12
#define DKC 64
#define FFC 3072
#define TBN 64
#define NEGV (-1e9f)
#define E_CONST 2.718281828459045f
#define MROWS (BB*TT)            // 2048

// ---------------- scratch layout (floats) ----------------
#define OF_H    0ull
#define OF_BIAS 6291456ull
#define OF_S    7340032ull
#define OF_QKV  OF_S
#define OF_A    19922944ull
#define OF_X2   21495808ull
#define OF_F    23068672ull
#define OF_WQT  29360128ull
#define OF_WPT  31129600ull
#define OF_F1T  31719424ull
#define OF_F2T  34078720ull
#define SCRATCH_TOTAL 36438016ull

__device__ float g_scratch[SCRATCH_TOTAL];

// ---------------- helpers ----------------
__device__ __forceinline__ uint32_t smem_u32(const void* p) {
    uint32_t a;
    asm("{ .reg .u64 t; cvta.to.shared.u64 t, %1; cvt.u32.u64 %0, t; }" : "=r"(a) : "l"(p));
    return a;
}
__device__ __forceinline__ float f2tf32f(float f) {
    uint32_t r; asm("cvt.rna.tf32.f32 %0, %1;" : "=r"(r) : "f"(f));
    return __uint_as_float(r);
}
#define CP_ASYNC16(dst_u32, src_ptr) \
    asm volatile("cp.async.cg.shared.global [%0], [%1], 16;\n" :: "r"(dst_u32), "l"(__cvta_generic_to_global(src_ptr)))
#define CP_COMMIT() asm volatile("cp.async.commit_group;\n" ::: "memory")
#define CP_WAIT2()  asm volatile("cp.async.wait_group 2;\n" ::: "memory")
#define CP_WAIT1()  asm volatile("cp.async.wait_group 1;\n" ::: "memory")
#define CP_WAIT0()  asm volatile("cp.async.wait_group 0;\n" ::: "memory")

#define MMA_TF32(c0,c1,c2,c3,a0,a1,a2,a3,b0,b1) \
    asm volatile("mma.sync.aligned.m16n8k8.row.col.f32.tf32.tf32.f32 " \
                 "{%0,%1,%2,%3}, {%4,%5,%6,%7}, {%8,%9}, {%0,%1,%2,%3};\n" \
                 : "+f"(c0), "+f"(c1), "+f"(c2), "+f"(c3) \
                 : "r"(a0), "r"(a1), "r"(a2), "r"(a3), "r"(b0), "r"(b1))

#define LDSM_X4(d0,d1,d2,d3,addr) \
    asm volatile("ldmatrix.sync.aligned.m8n8.x4.shared.b16 {%0,%1,%2,%3}, [%4];\n" \
                 : "=r"(d0), "=r"(d1), "=r"(d2), "=r"(d3) : "r"(addr))

#define LDT 20
#define BM 128

// =======================================================================
// big-tile GEMM — 128x128, 3-stage, warp tile 32x64.
// EPI 0 = split QKV bias (bq|bk|bv by column); EPI 2 = bias+GELU+tf32round.
// =======================================================================
#define BN2 128
#define GST2 3
#define GEMM_SMEM2 ((GST2*(BM+BN2)*LDT)*4)   // 61440

template <int EPI>
__global__ __launch_bounds__(256, 2) void gemm_big(const float* __restrict__ A,
                                                   const float* __restrict__ Wt,
                                                   const float* __restrict__ bias0,
                                                   const float* __restrict__ bias1,
                                                   const float* __restrict__ bias2,
                                                   float* __restrict__ C,
                                                   int N, int K) {
    extern __shared__ float dsm[];
    float* AsBase = dsm;
    float* BsBase = dsm + GST2 * BM * LDT;

    int tid = threadIdx.x;
    int warp = tid >> 5, lane = tid & 31;
    int wm = warp >> 1, wn = warp & 1;
    int g = lane >> 2, tig = lane & 3;
    int m0 = blockIdx.y * BM, n0 = blockIdx.x * BN2;

    int r0 = tid >> 2,            c0_ = (tid & 3) * 4;
    int r1 = (tid + 256) >> 2,    c1_ = ((tid + 256) & 3) * 4;

    uint32_t sA = smem_u32(AsBase);
    uint32_t sB = smem_u32(BsBase);
    const uint32_t bufA = BM * LDT * 4, bufB = BN2 * LDT * 4;

    int q = lane >> 3, l7 = lane & 7;
    int a_row = wm * 32 + (q & 1) * 8 + l7,  a_col = (q >> 1) * 4;
    int b_row = wn * 64 + (q >> 1) * 8 + l7, b_col = (q & 1) * 4;
    uint32_t aAddr0 = sA + (uint32_t)(a_row * LDT + a_col) * 4;
    uint32_t bAddr0 = sB + (uint32_t)(b_row * LDT + b_col) * 4;

    const int nk = K >> 4;

    #pragma unroll
    for (int pf = 0; pf < 2; pf++) {
        int k0 = pf * 16;
        CP_ASYNC16(sA + pf * bufA + (r0 * LDT + c0_) * 4, A + (size_t)(m0 + r0) * K + k0 + c0_);
        CP_ASYNC16(sA + pf * bufA + (r1 * LDT + c1_) * 4, A + (size_t)(m0 + r1) * K + k0 + c1_);
        CP_ASYNC16(sB + pf * bufB + (r0 * LDT + c0_) * 4, Wt + (size_t)(n0 + r0) * K + k0 + c0_);
        CP_ASYNC16(sB + pf * bufB + (r1 * LDT + c1_) * 4, Wt + (size_t)(n0 + r1) * K + k0 + c1_);
        CP_COMMIT();
    }

    float c[2][8][4];
    #pragma unroll
    for (int i = 0; i < 2; i++)
        #pragma unroll
        for (int j = 0; j < 8; j++)
            #pragma unroll
            for (int e = 0; e < 4; e++) c[i][j][e] = 0.f;

    for (int kt = 0; kt < nk; kt++) {
        int buf = kt % GST2;
        CP_WAIT1();
        __syncthreads();

        uint32_t aBuf = aAddr0 + buf * bufA;
        uint32_t bBuf = bAddr0 + buf * bufB;
        #pragma unroll
        for (int ks = 0; ks < 2; ks++) {
            uint32_t kOff = (uint32_t)(ks * 8) * 4;
            uint32_t a[2][4], b[8][2];
            #pragma unroll
            for (int i = 0; i < 2; i++)
                LDSM_X4(a[i][0], a[i][1], a[i][2], a[i][3],
                        aBuf + (uint32_t)(i * 16 * LDT) * 4 + kOff);
            #pragma unroll
            for (int p = 0; p < 4; p++)
                LDSM_X4(b[2*p][0], b[2*p][1], b[2*p+1][0], b[2*p+1][1],
                        bBuf + (uint32_t)(p * 16 * LDT) * 4 + kOff);
            #pragma unroll
            for (int i = 0; i < 2; i++)
                #pragma unroll
                for (int j = 0; j < 8; j++)
                    MMA_TF32(c[i][j][0], c[i][j][1], c[i][j][2], c[i][j][3],
                             a[i][0], a[i][1], a[i][2], a[i][3], b[j][0], b[j][1]);
        }

        if (kt + 2 < nk) {
            int k0 = (kt + 2) * 16;
            int nbuf = (kt + 2) % GST2;
            CP_ASYNC16(sA + nbuf * bufA + (r0 * LDT + c0_) * 4, A + (size_t)(m0 + r0) * K + k0 + c0_);
            CP_ASYNC16(sA + nbuf * bufA + (r1 * LDT + c1_) * 4, A + (size_t)(m0 + r1) * K + k0 + c1_);
            CP_ASYNC16(sB + nbuf * bufB + (r0 * LDT + c0_) * 4, Wt + (size_t)(n0 + r0) * K + k0 + c0_);
            CP_ASYNC16(sB + nbuf * bufB + (r1 * LDT + c1_) * 4, Wt + (size_t)(n0 + r1) * K + k0 + c1_);
        }
        CP_COMMIT();
    }

    #pragma unroll
    for (int i = 0; i < 2; i++) {
        int row0 = m0 + wm * 32 + i * 16 + g;
        #pragma unroll
        for (int j = 0; j < 8; j++) {
            int col = n0 + wn * 64 + j * 8 + 2 * tig;
            float b0, b1;
            if (EPI == 0) {
                // split QKV bias: col in [0,768)->bias0, [768,1536)->bias1, [1536,2304)->bias2
                const float* bp = (col < 768) ? bias0 : (col < 1536) ? bias1 : bias2;
                int bo = (col < 768) ? col : (col < 1536) ? col - 768 : col - 1536;
                b0 = bp[bo]; b1 = bp[bo + 1];
            } else {
                b0 = bias0[col]; b1 = bias0[col + 1];
            }
            #pragma unroll
            for (int half = 0; half < 2; half++) {
                int r = row0 + half * 8;
                float v0 = c[i][j][half * 2 + 0] + b0;
                float v1 = c[i][j][half * 2 + 1] + b1;
                if (EPI == 2) {
                    v0 = 0.5f * v0 * (1.f + erff(v0 * 0.70710678118654752f));
                    v1 = 0.5f * v1 * (1.f + erff(v1 * 0.70710678118654752f));
                    v0 = f2tf32f(v0); v1 = f2tf32f(v1);
                }
                float2 o; o.x = v0; o.y = v1;
                *(float2*)(C + (size_t)r * N + col) = o;
            }
        }
    }
}

// =======================================================================
// n96 GEMM — 128x96 tile, 4-stage, warp tile 32x48, bias+residual.
// For N=768 GEMMs (proj, FFN2): 128 CTAs = one balanced wave.
// =======================================================================
#define BN3 96
#define GST3 4
#define GEMM_SMEM3 ((GST3*(BM+BN3)*LDT)*4)   // 71680

__global__ __launch_bounds__(256, 2) void gemm_n96(const float* __restrict__ A,
                                                   const float* __restrict__ Wt,
                                                   const float* __restrict__ bias,
                                                   const float* __restrict__ res,
                                                   float* __restrict__ C,
                                                   int N, int K) {
    extern __shared__ float dsm[];
    float* AsBase = dsm;
    float* BsBase = dsm + GST3 * BM * LDT;

    int tid = threadIdx.x;
    int warp = tid >> 5, lane = tid & 31;
    int wm = warp >> 1, wn = warp & 1;
    int g = lane >> 2, tig = lane & 3;
    int m0 = blockIdx.y * BM, n0 = blockIdx.x * BN3;

    int ar0 = tid >> 2,            ac0 = (tid & 3) * 4;
    int ar1 = (tid + 256) >> 2,    ac1 = ((tid + 256) & 3) * 4;
    int br0 = tid >> 2,            bc0 = (tid & 3) * 4;
    int br1 = (tid + 256) >> 2,    bc1 = ((tid + 256) & 3) * 4;
    bool hasB1 = (tid < 128);

    uint32_t sA = smem_u32(AsBase);
    uint32_t sB = smem_u32(BsBase);
    const uint32_t bufA = BM * LDT * 4, bufB = BN3 * LDT * 4;

    int q = lane >> 3, l7 = lane & 7;
    int a_row = wm * 32 + (q & 1) * 8 + l7,  a_col = (q >> 1) * 4;
    int b_row = wn * 48 + (q >> 1) * 8 + l7, b_col = (q & 1) * 4;
    uint32_t aAddr0 = sA + (uint32_t)(a_row * LDT + a_col) * 4;
    uint32_t bAddr0 = sB + (uint32_t)(b_row * LDT + b_col) * 4;

    const int nk = K >> 4;

    #pragma unroll
    for (int pf = 0; pf < 3; pf++) {
        int k0 = pf * 16;
        CP_ASYNC16(sA + pf * bufA + (ar0 * LDT + ac0) * 4, A + (size_t)(m0 + ar0) * K + k0 + ac0);
        CP_ASYNC16(sA + pf * bufA + (ar1 * LDT + ac1) * 4, A + (size_t)(m0 + ar1) * K + k0 + ac1);
        CP_ASYNC16(sB + pf * bufB + (br0 * LDT + bc0) * 4, Wt + (size_t)(n0 + br0) * K + k0 + bc0);
        if (hasB1)
            CP_ASYNC16(sB + pf * bufB + (br1 * LDT + bc1) * 4, Wt + (size_t)(n0 + br1) * K + k0 + bc1);
        CP_COMMIT();
    }

    float c[2][6][4];
    #pragma unroll
    for (int i = 0; i < 2; i++)
        #pragma unroll
        for (int j = 0; j < 6; j++)
            #pragma unroll
            for (int e = 0; e < 4; e++) c[i][j][e] = 0.f;

    for (int kt = 0; kt < nk; kt++) {
        int buf = kt & (GST3 - 1);
        CP_WAIT2();
        __syncthreads();

        uint32_t aBuf = aAddr0 + buf * bufA;
        uint32_t bBuf = bAddr0 + buf * bufB;
        #pragma unroll
        for (int ks = 0; ks < 2; ks++) {
            uint32_t kOff = (uint32_t)(ks * 8) * 4;
            uint32_t a[2][4], b[6][2];
            #pragma unroll
            for (int i = 0; i < 2; i++)
                LDSM_X4(a[i][0], a[i][1], a[i][2], a[i][3],
                        aBuf + (uint32_t)(i * 16 * LDT) * 4 + kOff);
            #pragma unroll
            for (int p = 0; p < 3; p++)
                LDSM_X4(b[2*p][0], b[2*p][1], b[2*p+1][0], b[2*p+1][1],
                        bBuf + (uint32_t)(p * 16 * LDT) * 4 + kOff);
            #pragma unroll
            for (int i = 0; i < 2; i++)
                #pragma unroll
                for (int j = 0; j < 6; j++)
                    MMA_TF32(c[i][j][0], c[i][j][1], c[i][j][2], c[i][j][3],
                             a[i][0], a[i][1], a[i][2], a[i][3], b[j][0], b[j][1]);
        }

        if (kt + 3 < nk) {
            int k0 = (kt + 3) * 16;
            int nbuf = (kt + 3) & (GST3 - 1);
            CP_ASYNC16(sA + nbuf * bufA + (ar0 * LDT + ac0) * 4, A + (size_t)(m0 + ar0) * K + k0 + ac0);
            CP_ASYNC16(sA + nbuf * bufA + (ar1 * LDT + ac1) * 4, A + (size_t)(m0 + ar1) * K + k0 + ac1);
            CP_ASYNC16(sB + nbuf * bufB + (br0 * LDT + bc0) * 4, Wt + (size_t)(n0 + br0) * K + k0 + bc0);
            if (hasB1)
                CP_ASYNC16(sB + nbuf * bufB + (br1 * LDT + bc1) * 4, Wt + (size_t)(n0 + br1) * K + k0 + bc1);
        }
        CP_COMMIT();
    }

    #pragma unroll
    for (int i = 0; i < 2; i++) {
        int row0 = m0 + wm * 32 + i * 16 + g;
        #pragma unroll
        for (int j = 0; j < 6; j++) {
            int col = n0 + wn * 48 + j * 8 + 2 * tig;
            float b0 = bias[col], b1 = bias[col + 1];
            #pragma unroll
            for (int half = 0; half < 2; half++) {
                int r = row0 + half * 8;
                float2 r2 = *(const float2*)(res + (size_t)r * N + col);
                float2 o;
                o.x = c[i][j][half * 2 + 0] + b0 + r2.x;
                o.y = c[i][j][half * 2 + 1] + b1 + r2.y;
                *(float2*)(C + (size_t)r * N + col) = o;
            }
        }
    }
}

// ---------------- merged transposes (tf32-rounded) ----------------
__global__ __launch_bounds__(256) void transpose_attn(const float* __restrict__ wq,
                                                      const float* __restrict__ wk,
                                                      const float* __restrict__ wv,
                                                      const float* __restrict__ wp,
                                                      float* __restrict__ dst) {
    __shared__ float t[32][33];
    int z = blockIdx.z;
    const float* W = (z == 0) ? wq : (z == 1) ? wk : (z == 2) ? wv : wp;
    float* Wt = dst + (size_t)z * 589824;
    int n0 = blockIdx.x * 32, k0 = blockIdx.y * 32;
    int tx = threadIdx.x, ty = threadIdx.y;
    #pragma unroll
    for (int i = 0; i < 32; i += 8)
        t[ty + i][tx] = W[(size_t)(k0 + ty + i) * DD + n0 + tx];
    __syncthreads();
    #pragma unroll
    for (int i = 0; i < 32; i += 8)
        Wt[(size_t)(n0 + ty + i) * DD + k0 + tx] = f2tf32f(t[tx][ty + i]);
}

__global__ __launch_bounds__(256) void transpose_ffn(const float* __restrict__ f1w,
                                                     float* __restrict__ f1T,
                                                     const float* __restrict__ f2w,
                                                     float* __restrict__ f2T) {
    __shared__ float t[32][33];
    int z = blockIdx.z;
    const float* W; float* Wt; int K, N, n0, k0;
    if (z == 0) { W = f1w; Wt = f1T; K = DD;  N = FFC; n0 = blockIdx.x * 32; k0 = blockIdx.y * 32; }
    else        { W = f2w; Wt = f2T; K = FFC; N = DD;  n0 = blockIdx.y * 32; k0 = blockIdx.x * 32; }
    int tx = threadIdx.x, ty = threadIdx.y;
    #pragma unroll
    for (int i = 0; i < 32; i += 8)
        t[ty + i][tx] = W[(size_t)(k0 + ty + i) * N + n0 + tx];
    __syncthreads();
    #pragma unroll
    for (int i = 0; i < 32; i += 8)
        Wt[(size_t)(n0 + ty + i) * K + k0 + tx] = f2tf32f(t[tx][ty + i]);
}

// ---------------- LayerNorm (tf32-rounded output) ----------------
__global__ __launch_bounds__(256) void ln_kernel(const float* __restrict__ x,
                                                 const float* __restrict__ g,
                                                 const float* __restrict__ b,
                                                 float* __restrict__ out) {
    int row = blockIdx.x;
    const float* xr = x + (size_t)row * DD;
    float s = 0.f, s2 = 0.f;
    for (int i = threadIdx.x; i < DD; i += 256) { float v = xr[i]; s += v; s2 += v * v; }
    #pragma unroll
    for (int o = 16; o > 0; o >>= 1) {
        s  += __shfl_xor_sync(0xffffffffu, s,  o);
        s2 += __shfl_xor_sync(0xffffffffu, s2, o);
    }
    __shared__ float ws[8], ws2[8];
    int w = threadIdx.x >> 5, l = threadIdx.x & 31;
    if (l == 0) { ws[w] = s; ws2[w] = s2; }
    __syncthreads();
    if (w == 0) {
        s  = (l < 8) ? ws[l]  : 0.f;
        s2 = (l < 8) ? ws2[l] : 0.f;
        #pragma unroll
        for (int o = 4; o > 0; o >>= 1) {
            s  += __shfl_xor_sync(0xffffffffu, s,  o);
            s2 += __shfl_xor_sync(0xffffffffu, s2, o);
        }
        if (l == 0) { ws[0] = s; ws2[0] = s2; }
    }
    __syncthreads();
    float mean = ws[0] * (1.f / DD);
    float var  = ws2[0] * (1.f / DD) - mean * mean;
    float inv  = rsqrtf(var + 1e-5f);
    float* orow = out + (size_t)row * DD;
    for (int i = threadIdx.x; i < DD; i += 256)
        orow[i] = f2tf32f((xr[i] - mean) * inv * g[i] + b[i]);
}

// ---------------- temporal bias w/ masks baked in (fast math) ----------------
__global__ __launch_bounds__(256) void bias_kernel(const float* __restrict__ tm,
                                                   const int* __restrict__ pm,
                                                   const float* __restrict__ t1w,
                                                   const float* __restrict__ t1b,
                                                   const float* __restrict__ t2w,
                                                   const float* __restrict__ t2b) {
    __shared__ float w1[TBN], b1[TBN], w2[TBN];
    int t = threadIdx.x;
    if (t < TBN) { w1[t] = t1w[t]; b1[t] = t1b[t]; w2[t] = t2w[t]; }
    __syncthreads();
    size_t idx = (size_t)blockIdx.x * 256 + t;
    int rem = (int)(idx % (TT * TT));
    int i = rem / TT, j = rem % TT;
    float u = __fdividef(1.f, __logf(E_CONST + tm[idx]));
    float s = t2b[0];
    #pragma unroll
    for (int k = 0; k < TBN; k++) {
        float z = fmaf(u, w1[k], b1[k]);
        z = (z > 0.f) ? z : 0.2f * z;
        s = fmaf(z, w2[k], s);
    }
    bool masked = (pm[idx] == 0) || (j > i && i > 0);
    g_scratch[OF_BIAS + idx] = masked ? NEGV : s;
}

// =======================================================================
// flash attention (validated R5/R9 scalar version) — unchanged
// =======================================================================
#define SQ_LD 68
#define SV_LD 72
#define FS_Q    0
#define FS_K    (64*68)
#define FS_V    (FS_K + 2*64*68)
#define FS_P    (FS_V + 2*64*72)
#define FS_STAT (FS_P + 64*68)
#define FS_TOT  ((FS_STAT + 256) * 4)

__global__ __launch_bounds__(256, 2) void flash_kernel(const float* __restrict__ qkv,
                                                       float* __restrict__ outA) {
    extern __shared__ float fs[];
    float* sQ = fs + FS_Q;
    float* sK = fs + FS_K;
    float* sV = fs + FS_V;
    float* sP = fs + FS_P;
    float* sMax = fs + FS_STAT;
    float* sSum = fs + FS_STAT + 128;
    uint32_t sKu = smem_u32(sK), sVu = smem_u32(sV);

    int tid = threadIdx.x;
    int warp = tid >> 5, lane = tid & 31;
    int wm = warp >> 1, wn = warp & 1;
    int g = lane >> 2, tig = lane & 3;
    int i0 = blockIdx.x * 64;
    int bh = blockIdx.y, b = bh / HH, h = bh % HH;

    const float* base = qkv + (size_t)b * TT * 2304 + h * 64;
    const float* biasB = g_scratch + OF_BIAS + (size_t)b * TT * TT;

    for (int ch = tid; ch < 1024; ch += 256) {
        int r = ch >> 4, cc = (ch & 15) * 4;
        float4 v = *(const float4*)(base + (size_t)(i0 + r) * 2304 + cc);
        float4 o;
        o.x = f2tf32f(v.x * 0.125f); o.y = f2tf32f(v.y * 0.125f);
        o.z = f2tf32f(v.z * 0.125f); o.w = f2tf32f(v.w * 0.125f);
        *(float4*)(sQ + r * SQ_LD + cc) = o;
    }

    float o[4][4];
    #pragma unroll
    for (int j = 0; j < 4; j++)
        #pragma unroll
        for (int e = 0; e < 4; e++) o[j][e] = 0.f;
    float m0r = -INFINITY, m1r = -INFINITY, l0 = 0.f, l1 = 0.f;

    int ntiles = (i0 == 0) ? (TT / 64) : (i0 >> 6) + 1;
    int rw0 = wm * 16 + g, rw1 = rw0 + 8;

    {
        const float* kb_ = base + 768;
        const float* vb_ = base + 1536;
        for (int ch = tid; ch < 1024; ch += 256) {
            int r = ch >> 4, cc = (ch & 15) * 4;
            CP_ASYNC16(sKu + (r * SQ_LD + cc) * 4, kb_ + (size_t)r * 2304 + cc);
            CP_ASYNC16(sVu + (r * SV_LD + cc) * 4, vb_ + (size_t)r * 2304 + cc);
        }
        CP_COMMIT();
    }

    for (int t = 0; t < ntiles; t++) {
        int j0 = t * 64, buf = t & 1;
        CP_WAIT0();
        __syncthreads();

        float c[4][4];
        #pragma unroll
        for (int j = 0; j < 4; j++)
            #pragma unroll
            for (int e = 0; e < 4; e++) c[j][e] = 0.f;
        const float* kS = sK + buf * 64 * SQ_LD;
        #pragma unroll
        for (int kb = 0; kb < 64; kb += 8) {
            uint32_t a[4], bfr[4][2];
            int qr = wm * 16;
            a[0] = __float_as_uint(sQ[(qr + g)     * SQ_LD + kb + tig]);
            a[1] = __float_as_uint(sQ[(qr + 8 + g) * SQ_LD + kb + tig]);
            a[2] = __float_as_uint(sQ[(qr + g)     * SQ_LD + kb + tig + 4]);
            a[3] = __float_as_uint(sQ[(qr + 8 + g) * SQ_LD + kb + tig + 4]);
            #pragma unroll
            for (int j = 0; j < 4; j++) {
                int r = wn * 32 + j * 8 + g;
                bfr[j][0] = __float_as_uint(kS[r * SQ_LD + kb + tig]);
                bfr[j][1] = __float_as_uint(kS[r * SQ_LD + kb + tig + 4]);
            }
            #pragma unroll
            for (int j = 0; j < 4; j++)
                MMA_TF32(c[j][0], c[j][1], c[j][2], c[j][3],
                         a[0], a[1], a[2], a[3], bfr[j][0], bfr[j][1]);
        }

        int gi0 = i0 + rw0, gi1 = i0 + rw1;
        #pragma unroll
        for (int j = 0; j < 4; j++) {
            int gj = j0 + wn * 32 + j * 8 + 2 * tig;
            float2 b0 = *(const float2*)(biasB + (size_t)gi0 * TT + gj);
            float2 b1 = *(const float2*)(biasB + (size_t)gi1 * TT + gj);
            c[j][0] += b0.x; c[j][1] += b0.y;
            c[j][2] += b1.x; c[j][3] += b1.y;
        }

        float mx0 = c[0][0], mx1 = c[0][2];
        #pragma unroll
        for (int j = 0; j < 4; j++) {
            mx0 = fmaxf(mx0, fmaxf(c[j][0], c[j][1]));
            mx1 = fmaxf(mx1, fmaxf(c[j][2], c[j][3]));
        }
        mx0 = fmaxf(mx0, __shfl_xor_sync(0xffffffffu, mx0, 1));
        mx0 = fmaxf(mx0, __shfl_xor_sync(0xffffffffu, mx0, 2));
        mx1 = fmaxf(mx1, __shfl_xor_sync(0xffffffffu, mx1, 1));
        mx1 = fmaxf(mx1, __shfl_xor_sync(0xffffffffu, mx1, 2));
        if (tig == 0) { sMax[wn * 64 + rw0] = mx0; sMax[wn * 64 + rw1] = mx1; }
        __syncthreads();
        float mxc0 = fmaxf(sMax[rw0], sMax[64 + rw0]);
        float mxc1 = fmaxf(sMax[rw1], sMax[64 + rw1]);

        float mn0 = fmaxf(m0r, mxc0), mn1 = fmaxf(m1r, mxc1);
        float al0 = __expf(m0r - mn0), al1 = __expf(m1r - mn1);

        float sum0 = 0.f, sum1 = 0.f;
        #pragma unroll
        for (int j = 0; j < 4; j++) {
            int cw = wn * 32 + j * 8 + 2 * tig;
            float p00 = __expf(c[j][0] - mn0), p01 = __expf(c[j][1] - mn0);
            float p10 = __expf(c[j][2] - mn1), p11 = __expf(c[j][3] - mn1);
            sum0 += p00 + p01; sum1 += p10 + p11;
            float2 q0; q0.x = p00; q0.y = p01;
            float2 q1; q1.x = p10; q1.y = p11;
            *(float2*)(sP + rw0 * SQ_LD + cw) = q0;
            *(float2*)(sP + rw1 * SQ_LD + cw) = q1;
        }
        sum0 += __shfl_xor_sync(0xffffffffu, sum0, 1);
        sum0 += __shfl_xor_sync(0xffffffffu, sum0, 2);
        sum1 += __shfl_xor_sync(0xffffffffu, sum1, 1);
        sum1 += __shfl_xor_sync(0xffffffffu, sum1, 2);
        if (tig == 0) { sSum[wn * 64 + rw0] = sum0; sSum[wn * 64 + rw1] = sum1; }
        __syncthreads();
        float sc0 = sSum[rw0] + sSum[64 + rw0];
        float sc1 = sSum[rw1] + sSum[64 + rw1];

        l0 = l0 * al0 + sc0;  l1 = l1 * al1 + sc1;
        m0r = mn0;  m1r = mn1;
        #pragma unroll
        for (int j = 0; j < 4; j++) {
            o[j][0] *= al0; o[j][1] *= al0;
            o[j][2] *= al1; o[j][3] *= al1;
        }

        if (t + 1 < ntiles) {
            int nj0 = (t + 1) * 64, nb = buf ^ 1;
            const float* kb_ = base + 768;
            const float* vb_ = base + 1536;
            for (int ch = tid; ch < 1024; ch += 256) {
                int r = ch >> 4, cc = (ch & 15) * 4;
                CP_ASYNC16(sKu + (nb * 64 * SQ_LD + r * SQ_LD + cc) * 4, kb_ + (size_t)(nj0 + r) * 2304 + cc);
                CP_ASYNC16(sVu + (nb * 64 * SV_LD + r * SV_LD + cc) * 4, vb_ + (size_t)(nj0 + r) * 2304 + cc);
            }
            CP_COMMIT();
        }

        const float* vS = sV + buf * 64 * SV_LD;
        #pragma unroll
        for (int kb = 0; kb < 64; kb += 8) {
            uint32_t a[4], bfr[4][2];
            int pr = wm * 16;
            a[0] = __float_as_uint(sP[(pr + g)     * SQ_LD + kb + tig]);
            a[1] = __float_as_uint(sP[(pr + 8 + g) * SQ_LD + kb + tig]);
            a[2] = __float_as_uint(sP[(pr + g)     * SQ_LD + kb + tig + 4]);
            a[3] = __float_as_uint(sP[(pr + 8 + g) * SQ_LD + kb + tig + 4]);
            #pragma unroll
            for (int j = 0; j < 4; j++) {
                int nc = wn * 32 + j * 8 + g;
                bfr[j][0] = __float_as_uint(vS[(kb + tig)     * SV_LD + nc]);
                bfr[j][1] = __float_as_uint(vS[(kb + tig + 4) * SV_LD + nc]);
            }
            #pragma unroll
            for (int j = 0; j < 4; j++)
                MMA_TF32(o[j][0], o[j][1], o[j][2], o[j][3],
                         a[0], a[1], a[2], a[3], bfr[j][0], bfr[j][1]);
        }
        __syncthreads();
    }

    float inv0 = 1.f / l0, inv1 = 1.f / l1;
    int gr0 = b * TT + i0 + wm * 16 + g, gr1 = gr0 + 8;
    #pragma unroll
    for (int j = 0; j < 4; j++) {
        int col = h * 64 + wn * 32 + j * 8 + 2 * tig;
        float2 o0, o1;
        o0.x = f2tf32f(o[j][0] * inv0); o0.y = f2tf32f(o[j][1] * inv0);
        o1.x = f2tf32f(o[j][2] * inv1); o1.y = f2tf32f(o[j][3] * inv1);
        *(float2*)(outA + (size_t)gr0 * DD + col) = o0;
        *(float2*)(outA + (size_t)gr1 * DD + col) = o1;
    }
}

// ---------------- launch ----------------
extern "C" void kernel_launch(void* const* d_in, const int* in_sizes, int n_in,
                              void* d_out, int out_size) {
    const float* x     = (const float*)d_in[0];
    const float* tmat  = (const float*)d_in[1];
    const int*   pm    = (const int*)d_in[2];
    const float* wq = (const float*)d_in[3],  *bq = (const float*)d_in[4];
    const float* wk = (const float*)d_in[5],  *bk = (const float*)d_in[6];
    const float* wv = (const float*)d_in[7],  *bv = (const float*)d_in[8];
    const float* wp = (const float*)d_in[9],  *bp = (const float*)d_in[10];
    const float* t1w = (const float*)d_in[11], *t1b = (const float*)d_in[12];
    const float* t2w = (const float*)d_in[13], *t2b = (const float*)d_in[14];
    const float* f1w = (const float*)d_in[15], *f1b = (const float*)d_in[16];
    const float* f2w = (const float*)d_in[17], *f2b = (const float*)d_in[18];
    const float* ln1g = (const float*)d_in[19], *ln1b = (const float*)d_in[20];
    const float* ln2g = (const float*)d_in[21], *ln2b = (const float*)d_in[22];
    float* out = (float*)d_out;

    float* sc = nullptr;
    cudaGetSymbolAddress((void**)&sc, g_scratch);
    float* gH    = sc + OF_H;
    float* gQKV  = sc + OF_QKV;
    float* gA    = sc + OF_A;
    float* gX2   = sc + OF_X2;
    float* gF    = sc + OF_F;
    float* wcT   = sc + OF_WQT;
    float* wpT   = sc + OF_WPT;
    float* f1T   = sc + OF_F1T;
    float* f2T   = sc + OF_F2T;

    static cudaStream_t sBias = nullptr, sTr = nullptr;
    static cudaEvent_t eFork = nullptr, eBias = nullptr, eTr = nullptr, eTr2 = nullptr;
    if (sBias == nullptr) {
        cudaStreamCreateWithFlags(&sBias, cudaStreamNonBlocking);
        cudaStreamCreateWithFlags(&sTr, cudaStreamNonBlocking);
        cudaEventCreateWithFlags(&eFork, cudaEventDisableTiming);
        cudaEventCreateWithFlags(&eBias, cudaEventDisableTiming);
        cudaEventCreateWithFlags(&eTr, cudaEventDisableTiming);
        cudaEventCreateWithFlags(&eTr2, cudaEventDisableTiming);
        cudaFuncSetAttribute(gemm_big<0>, cudaFuncAttributeMaxDynamicSharedMemorySize, GEMM_SMEM2);
        cudaFuncSetAttribute(gemm_big<2>, cudaFuncAttributeMaxDynamicSharedMemorySize, GEMM_SMEM2);
        cudaFuncSetAttribute(gemm_n96, cudaFuncAttributeMaxDynamicSharedMemorySize, GEMM_SMEM3);
        cudaFuncSetAttribute(flash_kernel, cudaFuncAttributeMaxDynamicSharedMemorySize, FS_TOT);
    }

    dim3 tb(32, 8);

    // fork
    cudaEventRecord(eFork, 0);
    cudaStreamWaitEvent(sBias, eFork, 0);
    cudaStreamWaitEvent(sTr, eFork, 0);

    // branch B: temporal bias (needed only by flash)
    bias_kernel<<<(BB * TT * TT) / 256, 256, 0, sBias>>>(tmat, pm, t1w, t1b, t2w, t2b);
    cudaEventRecord(eBias, sBias);

    // branch C: attn transpose first (QKV dep), then FFN transpose (FFN dep, hidden)
    transpose_attn<<<dim3(24, 24, 4), tb, 0, sTr>>>(wq, wk, wv, wp, wcT);
    cudaEventRecord(eTr, sTr);
    transpose_ffn<<<dim3(96, 24, 2), tb, 0, sTr>>>(f1w, f1T, f2w, f2T);
    cudaEventRecord(eTr2, sTr);

    // main chain
    ln_kernel<<<MROWS, 256>>>(x, ln1g, ln1b, gH);
    cudaStreamWaitEvent(0, eTr, 0);
    gemm_big<0><<<dim3(2304 / BN2, MROWS / BM), 256, GEMM_SMEM2>>>(gH, wcT, bq, bk, bv, gQKV, 2304, DD);

    cudaStreamWaitEvent(0, eBias, 0);
    flash_kernel<<<dim3(TT / 64, BB * HH), 256, FS_TOT>>>(gQKV, gA);

    gemm_n96<<<dim3(DD / BN3, MROWS / BM), 256, GEMM_SMEM3>>>(gA, wpT, bp, x, gX2, DD, DD);

    ln_kernel<<<MROWS, 256>>>(gX2, ln2g, ln2b, gH);
    cudaStreamWaitEvent(0, eTr2, 0);
    gemm_big<2><<<dim3(FFC / BN2, MROWS / BM), 256, GEMM_SMEM2>>>(gH, f1T, f1b, nullptr, nullptr, gF, FFC, DD);
    gemm_n96<<<dim3(DD / BN3, MROWS / BM), 256, GEMM_SMEM3>>>(gF, f2T, f2b, gX2, out, DD, FFC);
}

// round 12
// speedup vs baseline: 1.0539x; 1.0186x over previous
#include <cuda_runtime.h>
#include <math.h>
#include <stdint.h>

// ---------------- problem constants ----------------
#define BB 4
#define TT 512
#define DD 768
#define HH 12
#define DKC 64
#define FFC 3072
#define TBN 64
#define NEGV (-1e9f)
#define E_CONST 2.718281828459045f
#define MROWS (BB*TT)            // 2048

// ---------------- scratch layout (floats) ----------------
#define OF_H    0ull
#define OF_BIAS 6291456ull
#define OF_S    7340032ull
#define OF_QKV  OF_S
#define OF_A    19922944ull
#define OF_X2   21495808ull
#define OF_F    23068672ull
#define OF_WQT  29360128ull
#define OF_WPT  31129600ull
#define OF_F1T  31719424ull
#define OF_F2T  34078720ull
#define SCRATCH_TOTAL 36438016ull

__device__ float g_scratch[SCRATCH_TOTAL];

// ---------------- helpers ----------------
__device__ __forceinline__ uint32_t smem_u32(const void* p) {
    uint32_t a;
    asm("{ .reg .u64 t; cvta.to.shared.u64 t, %1; cvt.u32.u64 %0, t; }" : "=r"(a) : "l"(p));
    return a;
}
__device__ __forceinline__ float f2tf32f(float f) {
    uint32_t r; asm("cvt.rna.tf32.f32 %0, %1;" : "=r"(r) : "f"(f));
    return __uint_as_float(r);
}
#define CP_ASYNC16(dst_u32, src_ptr) \
    asm volatile("cp.async.cg.shared.global [%0], [%1], 16;\n" :: "r"(dst_u32), "l"(__cvta_generic_to_global(src_ptr)))
#define CP_COMMIT() asm volatile("cp.async.commit_group;\n" ::: "memory")
#define CP_WAIT2()  asm volatile("cp.async.wait_group 2;\n" ::: "memory")
#define CP_WAIT0()  asm volatile("cp.async.wait_group 0;\n" ::: "memory")

#define MMA_TF32(c0,c1,c2,c3,a0,a1,a2,a3,b0,b1) \
    asm volatile("mma.sync.aligned.m16n8k8.row.col.f32.tf32.tf32.f32 " \
                 "{%0,%1,%2,%3}, {%4,%5,%6,%7}, {%8,%9}, {%0,%1,%2,%3};\n" \
                 : "+f"(c0), "+f"(c1), "+f"(c2), "+f"(c3) \
                 : "r"(a0), "r"(a1), "r"(a2), "r"(a3), "r"(b0), "r"(b1))

#define LDSM_X4(d0,d1,d2,d3,addr) \
    asm volatile("ldmatrix.sync.aligned.m8n8.x4.shared.b16 {%0,%1,%2,%3}, [%4];\n" \
                 : "=r"(d0), "=r"(d1), "=r"(d2), "=r"(d3) : "r"(addr))

#define LDT 20
#define BM 128

// =======================================================================
// big-tile GEMM — 128x128, now 4-stage, warp tile 32x64.
// EPI 0 = split QKV bias (bq|bk|bv by column); EPI 2 = bias+GELU+tf32round.
// smem 81920 B/CTA; 2 CTAs co-reside in B200's 228KB SM carveout.
// =======================================================================
#define BN2 128
#define GST2 4
#define GEMM_SMEM2 ((GST2*(BM+BN2)*LDT)*4)   // 81920

template <int EPI>
__global__ __launch_bounds__(256, 2) void gemm_big(const float* __restrict__ A,
                                                   const float* __restrict__ Wt,
                                                   const float* __restrict__ bias0,
                                                   const float* __restrict__ bias1,
                                                   const float* __restrict__ bias2,
                                                   float* __restrict__ C,
                                                   int N, int K) {
    extern __shared__ float dsm[];
    float* AsBase = dsm;
    float* BsBase = dsm + GST2 * BM * LDT;

    int tid = threadIdx.x;
    int warp = tid >> 5, lane = tid & 31;
    int wm = warp >> 1, wn = warp & 1;
    int g = lane >> 2, tig = lane & 3;
    int m0 = blockIdx.y * BM, n0 = blockIdx.x * BN2;

    int r0 = tid >> 2,            c0_ = (tid & 3) * 4;
    int r1 = (tid + 256) >> 2,    c1_ = ((tid + 256) & 3) * 4;

    uint32_t sA = smem_u32(AsBase);
    uint32_t sB = smem_u32(BsBase);
    const uint32_t bufA = BM * LDT * 4, bufB = BN2 * LDT * 4;

    int q = lane >> 3, l7 = lane & 7;
    int a_row = wm * 32 + (q & 1) * 8 + l7,  a_col = (q >> 1) * 4;
    int b_row = wn * 64 + (q >> 1) * 8 + l7, b_col = (q & 1) * 4;
    uint32_t aAddr0 = sA + (uint32_t)(a_row * LDT + a_col) * 4;
    uint32_t bAddr0 = sB + (uint32_t)(b_row * LDT + b_col) * 4;

    const int nk = K >> 4;

    #pragma unroll
    for (int pf = 0; pf < 3; pf++) {
        int k0 = pf * 16;
        CP_ASYNC16(sA + pf * bufA + (r0 * LDT + c0_) * 4, A + (size_t)(m0 + r0) * K + k0 + c0_);
        CP_ASYNC16(sA + pf * bufA + (r1 * LDT + c1_) * 4, A + (size_t)(m0 + r1) * K + k0 + c1_);
        CP_ASYNC16(sB + pf * bufB + (r0 * LDT + c0_) * 4, Wt + (size_t)(n0 + r0) * K + k0 + c0_);
        CP_ASYNC16(sB + pf * bufB + (r1 * LDT + c1_) * 4, Wt + (size_t)(n0 + r1) * K + k0 + c1_);
        CP_COMMIT();
    }

    float c[2][8][4];
    #pragma unroll
    for (int i = 0; i < 2; i++)
        #pragma unroll
        for (int j = 0; j < 8; j++)
            #pragma unroll
            for (int e = 0; e < 4; e++) c[i][j][e] = 0.f;

    for (int kt = 0; kt < nk; kt++) {
        int buf = kt & (GST2 - 1);
        CP_WAIT2();
        __syncthreads();

        uint32_t aBuf = aAddr0 + buf * bufA;
        uint32_t bBuf = bAddr0 + buf * bufB;
        #pragma unroll
        for (int ks = 0; ks < 2; ks++) {
            uint32_t kOff = (uint32_t)(ks * 8) * 4;
            uint32_t a[2][4], b[8][2];
            #pragma unroll
            for (int i = 0; i < 2; i++)
                LDSM_X4(a[i][0], a[i][1], a[i][2], a[i][3],
                        aBuf + (uint32_t)(i * 16 * LDT) * 4 + kOff);
            #pragma unroll
            for (int p = 0; p < 4; p++)
                LDSM_X4(b[2*p][0], b[2*p][1], b[2*p+1][0], b[2*p+1][1],
                        bBuf + (uint32_t)(p * 16 * LDT) * 4 + kOff);
            #pragma unroll
            for (int i = 0; i < 2; i++)
                #pragma unroll
                for (int j = 0; j < 8; j++)
                    MMA_TF32(c[i][j][0], c[i][j][1], c[i][j][2], c[i][j][3],
                             a[i][0], a[i][1], a[i][2], a[i][3], b[j][0], b[j][1]);
        }

        if (kt + 3 < nk) {
            int k0 = (kt + 3) * 16;
            int nbuf = (kt + 3) & (GST2 - 1);
            CP_ASYNC16(sA + nbuf * bufA + (r0 * LDT + c0_) * 4, A + (size_t)(m0 + r0) * K + k0 + c0_);
            CP_ASYNC16(sA + nbuf * bufA + (r1 * LDT + c1_) * 4, A + (size_t)(m0 + r1) * K + k0 + c1_);
            CP_ASYNC16(sB + nbuf * bufB + (r0 * LDT + c0_) * 4, Wt + (size_t)(n0 + r0) * K + k0 + c0_);
            CP_ASYNC16(sB + nbuf * bufB + (r1 * LDT + c1_) * 4, Wt + (size_t)(n0 + r1) * K + k0 + c1_);
        }
        CP_COMMIT();
    }

    #pragma unroll
    for (int i = 0; i < 2; i++) {
        int row0 = m0 + wm * 32 + i * 16 + g;
        #pragma unroll
        for (int j = 0; j < 8; j++) {
            int col = n0 + wn * 64 + j * 8 + 2 * tig;
            float b0, b1;
            if (EPI == 0) {
                const float* bp = (col < 768) ? bias0 : (col < 1536) ? bias1 : bias2;
                int bo = (col < 768) ? col : (col < 1536) ? col - 768 : col - 1536;
                b0 = bp[bo]; b1 = bp[bo + 1];
            } else {
                b0 = bias0[col]; b1 = bias0[col + 1];
            }
            #pragma unroll
            for (int half = 0; half < 2; half++) {
                int r = row0 + half * 8;
                float v0 = c[i][j][half * 2 + 0] + b0;
                float v1 = c[i][j][half * 2 + 1] + b1;
                if (EPI == 2) {
                    v0 = 0.5f * v0 * (1.f + erff(v0 * 0.70710678118654752f));
                    v1 = 0.5f * v1 * (1.f + erff(v1 * 0.70710678118654752f));
                    v0 = f2tf32f(v0); v1 = f2tf32f(v1);
                }
                float2 o; o.x = v0; o.y = v1;
                *(float2*)(C + (size_t)r * N + col) = o;
            }
        }
    }
}

// =======================================================================
// n96 GEMM — 128x96 tile, 4-stage, warp tile 32x48, bias+residual.
// =======================================================================
#define BN3 96
#define GST3 4
#define GEMM_SMEM3 ((GST3*(BM+BN3)*LDT)*4)   // 71680

__global__ __launch_bounds__(256, 2) void gemm_n96(const float* __restrict__ A,
                                                   const float* __restrict__ Wt,
                                                   const float* __restrict__ bias,
                                                   const float* __restrict__ res,
                                                   float* __restrict__ C,
                                                   int N, int K) {
    extern __shared__ float dsm[];
    float* AsBase = dsm;
    float* BsBase = dsm + GST3 * BM * LDT;

    int tid = threadIdx.x;
    int warp = tid >> 5, lane = tid & 31;
    int wm = warp >> 1, wn = warp & 1;
    int g = lane >> 2, tig = lane & 3;
    int m0 = blockIdx.y * BM, n0 = blockIdx.x * BN3;

    int ar0 = tid >> 2,            ac0 = (tid & 3) * 4;
    int ar1 = (tid + 256) >> 2,    ac1 = ((tid + 256) & 3) * 4;
    int br0 = tid >> 2,            bc0 = (tid & 3) * 4;
    int br1 = (tid + 256) >> 2,    bc1 = ((tid + 256) & 3) * 4;
    bool hasB1 = (tid < 128);

    uint32_t sA = smem_u32(AsBase);
    uint32_t sB = smem_u32(BsBase);
    const uint32_t bufA = BM * LDT * 4, bufB = BN3 * LDT * 4;

    int q = lane >> 3, l7 = lane & 7;
    int a_row = wm * 32 + (q & 1) * 8 + l7,  a_col = (q >> 1) * 4;
    int b_row = wn * 48 + (q >> 1) * 8 + l7, b_col = (q & 1) * 4;
    uint32_t aAddr0 = sA + (uint32_t)(a_row * LDT + a_col) * 4;
    uint32_t bAddr0 = sB + (uint32_t)(b_row * LDT + b_col) * 4;

    const int nk = K >> 4;

    #pragma unroll
    for (int pf = 0; pf < 3; pf++) {
        int k0 = pf * 16;
        CP_ASYNC16(sA + pf * bufA + (ar0 * LDT + ac0) * 4, A + (size_t)(m0 + ar0) * K + k0 + ac0);
        CP_ASYNC16(sA + pf * bufA + (ar1 * LDT + ac1) * 4, A + (size_t)(m0 + ar1) * K + k0 + ac1);
        CP_ASYNC16(sB + pf * bufB + (br0 * LDT + bc0) * 4, Wt + (size_t)(n0 + br0) * K + k0 + bc0);
        if (hasB1)
            CP_ASYNC16(sB + pf * bufB + (br1 * LDT + bc1) * 4, Wt + (size_t)(n0 + br1) * K + k0 + bc1);
        CP_COMMIT();
    }

    float c[2][6][4];
    #pragma unroll
    for (int i = 0; i < 2; i++)
        #pragma unroll
        for (int j = 0; j < 6; j++)
            #pragma unroll
            for (int e = 0; e < 4; e++) c[i][j][e] = 0.f;

    for (int kt = 0; kt < nk; kt++) {
        int buf = kt & (GST3 - 1);
        CP_WAIT2();
        __syncthreads();

        uint32_t aBuf = aAddr0 + buf * bufA;
        uint32_t bBuf = bAddr0 + buf * bufB;
        #pragma unroll
        for (int ks = 0; ks < 2; ks++) {
            uint32_t kOff = (uint32_t)(ks * 8) * 4;
            uint32_t a[2][4], b[6][2];
            #pragma unroll
            for (int i = 0; i < 2; i++)
                LDSM_X4(a[i][0], a[i][1], a[i][2], a[i][3],
                        aBuf + (uint32_t)(i * 16 * LDT) * 4 + kOff);
            #pragma unroll
            for (int p = 0; p < 3; p++)
                LDSM_X4(b[2*p][0], b[2*p][1], b[2*p+1][0], b[2*p+1][1],
                        bBuf + (uint32_t)(p * 16 * LDT) * 4 + kOff);
            #pragma unroll
            for (int i = 0; i < 2; i++)
                #pragma unroll
                for (int j = 0; j < 6; j++)
                    MMA_TF32(c[i][j][0], c[i][j][1], c[i][j][2], c[i][j][3],
                             a[i][0], a[i][1], a[i][2], a[i][3], b[j][0], b[j][1]);
        }

        if (kt + 3 < nk) {
            int k0 = (kt + 3) * 16;
            int nbuf = (kt + 3) & (GST3 - 1);
            CP_ASYNC16(sA + nbuf * bufA + (ar0 * LDT + ac0) * 4, A + (size_t)(m0 + ar0) * K + k0 + ac0);
            CP_ASYNC16(sA + nbuf * bufA + (ar1 * LDT + ac1) * 4, A + (size_t)(m0 + ar1) * K + k0 + ac1);
            CP_ASYNC16(sB + nbuf * bufB + (br0 * LDT + bc0) * 4, Wt + (size_t)(n0 + br0) * K + k0 + bc0);
            if (hasB1)
                CP_ASYNC16(sB + nbuf * bufB + (br1 * LDT + bc1) * 4, Wt + (size_t)(n0 + br1) * K + k0 + bc1);
        }
        CP_COMMIT();
    }

    #pragma unroll
    for (int i = 0; i < 2; i++) {
        int row0 = m0 + wm * 32 + i * 16 + g;
        #pragma unroll
        for (int j = 0; j < 6; j++) {
            int col = n0 + wn * 48 + j * 8 + 2 * tig;
            float b0 = bias[col], b1 = bias[col + 1];
            #pragma unroll
            for (int half = 0; half < 2; half++) {
                int r = row0 + half * 8;
                float2 r2 = *(const float2*)(res + (size_t)r * N + col);
                float2 o;
                o.x = c[i][j][half * 2 + 0] + b0 + r2.x;
                o.y = c[i][j][half * 2 + 1] + b1 + r2.y;
                *(float2*)(C + (size_t)r * N + col) = o;
            }
        }
    }
}

// ---------------- merged transposes (tf32-rounded) ----------------
__global__ __launch_bounds__(256) void transpose_attn(const float* __restrict__ wq,
                                                      const float* __restrict__ wk,
                                                      const float* __restrict__ wv,
                                                      const float* __restrict__ wp,
                                                      float* __restrict__ dst) {
    __shared__ float t[32][33];
    int z = blockIdx.z;
    const float* W = (z == 0) ? wq : (z == 1) ? wk : (z == 2) ? wv : wp;
    float* Wt = dst + (size_t)z * 589824;
    int n0 = blockIdx.x * 32, k0 = blockIdx.y * 32;
    int tx = threadIdx.x, ty = threadIdx.y;
    #pragma unroll
    for (int i = 0; i < 32; i += 8)
        t[ty + i][tx] = W[(size_t)(k0 + ty + i) * DD + n0 + tx];
    __syncthreads();
    #pragma unroll
    for (int i = 0; i < 32; i += 8)
        Wt[(size_t)(n0 + ty + i) * DD + k0 + tx] = f2tf32f(t[tx][ty + i]);
}

__global__ __launch_bounds__(256) void transpose_ffn(const float* __restrict__ f1w,
                                                     float* __restrict__ f1T,
                                                     const float* __restrict__ f2w,
                                                     float* __restrict__ f2T) {
    __shared__ float t[32][33];
    int z = blockIdx.z;
    const float* W; float* Wt; int K, N, n0, k0;
    if (z == 0) { W = f1w; Wt = f1T; K = DD;  N = FFC; n0 = blockIdx.x * 32; k0 = blockIdx.y * 32; }
    else        { W = f2w; Wt = f2T; K = FFC; N = DD;  n0 = blockIdx.y * 32; k0 = blockIdx.x * 32; }
    int tx = threadIdx.x, ty = threadIdx.y;
    #pragma unroll
    for (int i = 0; i < 32; i += 8)
        t[ty + i][tx] = W[(size_t)(k0 + ty + i) * N + n0 + tx];
    __syncthreads();
    #pragma unroll
    for (int i = 0; i < 32; i += 8)
        Wt[(size_t)(n0 + ty + i) * K + k0 + tx] = f2tf32f(t[tx][ty + i]);
}

// ---------------- LayerNorm — float4 vectorized (tf32-rounded output) ----------------
__global__ __launch_bounds__(256) void ln_kernel(const float* __restrict__ x,
                                                 const float* __restrict__ gw,
                                                 const float* __restrict__ bw,
                                                 float* __restrict__ out) {
    int row = blockIdx.x;
    int tid = threadIdx.x;
    const float4* xr = (const float4*)(x + (size_t)row * DD);   // 192 float4
    float4 v = make_float4(0.f, 0.f, 0.f, 0.f);
    float s = 0.f, s2 = 0.f;
    if (tid < 192) {
        v = xr[tid];
        s  = v.x + v.y + v.z + v.w;
        s2 = v.x * v.x + v.y * v.y + v.z * v.z + v.w * v.w;
    }
    #pragma unroll
    for (int o = 16; o > 0; o >>= 1) {
        s  += __shfl_xor_sync(0xffffffffu, s,  o);
        s2 += __shfl_xor_sync(0xffffffffu, s2, o);
    }
    __shared__ float ws[8], ws2[8];
    int w = tid >> 5, l = tid & 31;
    if (l == 0) { ws[w] = s; ws2[w] = s2; }
    __syncthreads();
    if (w == 0) {
        s  = (l < 8) ? ws[l]  : 0.f;
        s2 = (l < 8) ? ws2[l] : 0.f;
        #pragma unroll
        for (int o = 4; o > 0; o >>= 1) {
            s  += __shfl_xor_sync(0xffffffffu, s,  o);
            s2 += __shfl_xor_sync(0xffffffffu, s2, o);
        }
        if (l == 0) { ws[0] = s; ws2[0] = s2; }
    }
    __syncthreads();
    float mean = ws[0] * (1.f / DD);
    float var  = ws2[0] * (1.f / DD) - mean * mean;
    float inv  = rsqrtf(var + 1e-5f);
    if (tid < 192) {
        float4 gg = ((const float4*)gw)[tid];
        float4 bb = ((const float4*)bw)[tid];
        float4 o;
        o.x = f2tf32f((v.x - mean) * inv * gg.x + bb.x);
        o.y = f2tf32f((v.y - mean) * inv * gg.y + bb.y);
        o.z = f2tf32f((v.z - mean) * inv * gg.z + bb.z);
        o.w = f2tf32f((v.w - mean) * inv * gg.w + bb.w);
        ((float4*)(out + (size_t)row * DD))[tid] = o;
    }
}

// ---------------- temporal bias w/ masks baked in (fast math) ----------------
__global__ __launch_bounds__(256) void bias_kernel(const float* __restrict__ tm,
                                                   const int* __restrict__ pm,
                                                   const float* __restrict__ t1w,
                                                   const float* __restrict__ t1b,
                                                   const float* __restrict__ t2w,
                                                   const float* __restrict__ t2b) {
    __shared__ float w1[TBN], b1[TBN], w2[TBN];
    int t = threadIdx.x;
    if (t < TBN) { w1[t] = t1w[t]; b1[t] = t1b[t]; w2[t] = t2w[t]; }
    __syncthreads();
    size_t idx = (size_t)blockIdx.x * 256 + t;
    int rem = (int)(idx % (TT * TT));
    int i = rem / TT, j = rem % TT;
    float u = __fdividef(1.f, __logf(E_CONST + tm[idx]));
    float s = t2b[0];
    #pragma unroll
    for (int k = 0; k < TBN; k++) {
        float z = fmaf(u, w1[k], b1[k]);
        z = (z > 0.f) ? z : 0.2f * z;
        s = fmaf(z, w2[k], s);
    }
    bool masked = (pm[idx] == 0) || (j > i && i > 0);
    g_scratch[OF_BIAS + idx] = masked ? NEGV : s;
}

// =======================================================================
// flash attention (validated R5/R9 scalar version) — unchanged
// =======================================================================
#define SQ_LD 68
#define SV_LD 72
#define FS_Q    0
#define FS_K    (64*68)
#define FS_V    (FS_K + 2*64*68)
#define FS_P    (FS_V + 2*64*72)
#define FS_STAT (FS_P + 64*68)
#define FS_TOT  ((FS_STAT + 256) * 4)

__global__ __launch_bounds__(256, 2) void flash_kernel(const float* __restrict__ qkv,
                                                       float* __restrict__ outA) {
    extern __shared__ float fs[];
    float* sQ = fs + FS_Q;
    float* sK = fs + FS_K;
    float* sV = fs + FS_V;
    float* sP = fs + FS_P;
    float* sMax = fs + FS_STAT;
    float* sSum = fs + FS_STAT + 128;
    uint32_t sKu = smem_u32(sK), sVu = smem_u32(sV);

    int tid = threadIdx.x;
    int warp = tid >> 5, lane = tid & 31;
    int wm = warp >> 1, wn = warp & 1;
    int g = lane >> 2, tig = lane & 3;
    int i0 = blockIdx.x * 64;
    int bh = blockIdx.y, b = bh / HH, h = bh % HH;

    const float* base = qkv + (size_t)b * TT * 2304 + h * 64;
    const float* biasB = g_scratch + OF_BIAS + (size_t)b * TT * TT;

    for (int ch = tid; ch < 1024; ch += 256) {
        int r = ch >> 4, cc = (ch & 15) * 4;
        float4 v = *(const float4*)(base + (size_t)(i0 + r) * 2304 + cc);
        float4 o;
        o.x = f2tf32f(v.x * 0.125f); o.y = f2tf32f(v.y * 0.125f);
        o.z = f2tf32f(v.z * 0.125f); o.w = f2tf32f(v.w * 0.125f);
        *(float4*)(sQ + r * SQ_LD + cc) = o;
    }

    float o[4][4];
    #pragma unroll
    for (int j = 0; j < 4; j++)
        #pragma unroll
        for (int e = 0; e < 4; e++) o[j][e] = 0.f;
    float m0r = -INFINITY, m1r = -INFINITY, l0 = 0.f, l1 = 0.f;

    int ntiles = (i0 == 0) ? (TT / 64) : (i0 >> 6) + 1;
    int rw0 = wm * 16 + g, rw1 = rw0 + 8;

    {
        const float* kb_ = base + 768;
        const float* vb_ = base + 1536;
        for (int ch = tid; ch < 1024; ch += 256) {
            int r = ch >> 4, cc = (ch & 15) * 4;
            CP_ASYNC16(sKu + (r * SQ_LD + cc) * 4, kb_ + (size_t)r * 2304 + cc);
            CP_ASYNC16(sVu + (r * SV_LD + cc) * 4, vb_ + (size_t)r * 2304 + cc);
        }
        CP_COMMIT();
    }

    for (int t = 0; t < ntiles; t++) {
        int j0 = t * 64, buf = t & 1;
        CP_WAIT0();
        __syncthreads();

        float c[4][4];
        #pragma unroll
        for (int j = 0; j < 4; j++)
            #pragma unroll
            for (int e = 0; e < 4; e++) c[j][e] = 0.f;
        const float* kS = sK + buf * 64 * SQ_LD;
        #pragma unroll
        for (int kb = 0; kb < 64; kb += 8) {
            uint32_t a[4], bfr[4][2];
            int qr = wm * 16;
            a[0] = __float_as_uint(sQ[(qr + g)     * SQ_LD + kb + tig]);
            a[1] = __float_as_uint(sQ[(qr + 8 + g) * SQ_LD + kb + tig]);
            a[2] = __float_as_uint(sQ[(qr + g)     * SQ_LD + kb + tig + 4]);
            a[3] = __float_as_uint(sQ[(qr + 8 + g) * SQ_LD + kb + tig + 4]);
            #pragma unroll
            for (int j = 0; j < 4; j++) {
                int r = wn * 32 + j * 8 + g;
                bfr[j][0] = __float_as_uint(kS[r * SQ_LD + kb + tig]);
                bfr[j][1] = __float_as_uint(kS[r * SQ_LD + kb + tig + 4]);
            }
            #pragma unroll
            for (int j = 0; j < 4; j++)
                MMA_TF32(c[j][0], c[j][1], c[j][2], c[j][3],
                         a[0], a[1], a[2], a[3], bfr[j][0], bfr[j][1]);
        }

        int gi0 = i0 + rw0, gi1 = i0 + rw1;
        #pragma unroll
        for (int j = 0; j < 4; j++) {
            int gj = j0 + wn * 32 + j * 8 + 2 * tig;
            float2 b0 = *(const float2*)(biasB + (size_t)gi0 * TT + gj);
            float2 b1 = *(const float2*)(biasB + (size_t)gi1 * TT + gj);
            c[j][0] += b0.x; c[j][1] += b0.y;
            c[j][2] += b1.x; c[j][3] += b1.y;
        }

        float mx0 = c[0][0], mx1 = c[0][2];
        #pragma unroll
        for (int j = 0; j < 4; j++) {
            mx0 = fmaxf(mx0, fmaxf(c[j][0], c[j][1]));
            mx1 = fmaxf(mx1, fmaxf(c[j][2], c[j][3]));
        }
        mx0 = fmaxf(mx0, __shfl_xor_sync(0xffffffffu, mx0, 1));
        mx0 = fmaxf(mx0, __shfl_xor_sync(0xffffffffu, mx0, 2));
        mx1 = fmaxf(mx1, __shfl_xor_sync(0xffffffffu, mx1, 1));
        mx1 = fmaxf(mx1, __shfl_xor_sync(0xffffffffu, mx1, 2));
        if (tig == 0) { sMax[wn * 64 + rw0] = mx0; sMax[wn * 64 + rw1] = mx1; }
        __syncthreads();
        float mxc0 = fmaxf(sMax[rw0], sMax[64 + rw0]);
        float mxc1 = fmaxf(sMax[rw1], sMax[64 + rw1]);

        float mn0 = fmaxf(m0r, mxc0), mn1 = fmaxf(m1r, mxc1);
        float al0 = __expf(m0r - mn0), al1 = __expf(m1r - mn1);

        float sum0 = 0.f, sum1 = 0.f;
        #pragma unroll
        for (int j = 0; j < 4; j++) {
            int cw = wn * 32 + j * 8 + 2 * tig;
            float p00 = __expf(c[j][0] - mn0), p01 = __expf(c[j][1] - mn0);
            float p10 = __expf(c[j][2] - mn1), p11 = __expf(c[j][3] - mn1);
            sum0 += p00 + p01; sum1 += p10 + p11;
            float2 q0; q0.x = p00; q0.y = p01;
            float2 q1; q1.x = p10; q1.y = p11;
            *(float2*)(sP + rw0 * SQ_LD + cw) = q0;
            *(float2*)(sP + rw1 * SQ_LD + cw) = q1;
        }
        sum0 += __shfl_xor_sync(0xffffffffu, sum0, 1);
        sum0 += __shfl_xor_sync(0xffffffffu, sum0, 2);
        sum1 += __shfl_xor_sync(0xffffffffu, sum1, 1);
        sum1 += __shfl_xor_sync(0xffffffffu, sum1, 2);
        if (tig == 0) { sSum[wn * 64 + rw0] = sum0; sSum[wn * 64 + rw1] = sum1; }
        __syncthreads();
        float sc0 = sSum[rw0] + sSum[64 + rw0];
        float sc1 = sSum[rw1] + sSum[64 + rw1];

        l0 = l0 * al0 + sc0;  l1 = l1 * al1 + sc1;
        m0r = mn0;  m1r = mn1;
        #pragma unroll
        for (int j = 0; j < 4; j++) {
            o[j][0] *= al0; o[j][1] *= al0;
            o[j][2] *= al1; o[j][3] *= al1;
        }

        if (t + 1 < ntiles) {
            int nj0 = (t + 1) * 64, nb = buf ^ 1;
            const float* kb_ = base + 768;
            const float* vb_ = base + 1536;
            for (int ch = tid; ch < 1024; ch += 256) {
                int r = ch >> 4, cc = (ch & 15) * 4;
                CP_ASYNC16(sKu + (nb * 64 * SQ_LD + r * SQ_LD + cc) * 4, kb_ + (size_t)(nj0 + r) * 2304 + cc);
                CP_ASYNC16(sVu + (nb * 64 * SV_LD + r * SV_LD + cc) * 4, vb_ + (size_t)(nj0 + r) * 2304 + cc);
            }
            CP_COMMIT();
        }

        const float* vS = sV + buf * 64 * SV_LD;
        #pragma unroll
        for (int kb = 0; kb < 64; kb += 8) {
            uint32_t a[4], bfr[4][2];
            int pr = wm * 16;
            a[0] = __float_as_uint(sP[(pr + g)     * SQ_LD + kb + tig]);
            a[1] = __float_as_uint(sP[(pr + 8 + g) * SQ_LD + kb + tig]);
            a[2] = __float_as_uint(sP[(pr + g)     * SQ_LD + kb + tig + 4]);
            a[3] = __float_as_uint(sP[(pr + 8 + g) * SQ_LD + kb + tig + 4]);
            #pragma unroll
            for (int j = 0; j < 4; j++) {
                int nc = wn * 32 + j * 8 + g;
                bfr[j][0] = __float_as_uint(vS[(kb + tig)     * SV_LD + nc]);
                bfr[j][1] = __float_as_uint(vS[(kb + tig + 4) * SV_LD + nc]);
            }
            #pragma unroll
            for (int j = 0; j < 4; j++)
                MMA_TF32(o[j][0], o[j][1], o[j][2], o[j][3],
                         a[0], a[1], a[2], a[3], bfr[j][0], bfr[j][1]);
        }
        __syncthreads();
    }

    float inv0 = 1.f / l0, inv1 = 1.f / l1;
    int gr0 = b * TT + i0 + wm * 16 + g, gr1 = gr0 + 8;
    #pragma unroll
    for (int j = 0; j < 4; j++) {
        int col = h * 64 + wn * 32 + j * 8 + 2 * tig;
        float2 o0, o1;
        o0.x = f2tf32f(o[j][0] * inv0); o0.y = f2tf32f(o[j][1] * inv0);
        o1.x = f2tf32f(o[j][2] * inv1); o1.y = f2tf32f(o[j][3] * inv1);
        *(float2*)(outA + (size_t)gr0 * DD + col) = o0;
        *(float2*)(outA + (size_t)gr1 * DD + col) = o1;
    }
}

// ---------------- launch ----------------
extern "C" void kernel_launch(void* const* d_in, const int* in_sizes, int n_in,
                              void* d_out, int out_size) {
    const float* x     = (const float*)d_in[0];
    const float* tmat  = (const float*)d_in[1];
    const int*   pm    = (const int*)d_in[2];
    const float* wq = (const float*)d_in[3],  *bq = (const float*)d_in[4];
    const float* wk = (const float*)d_in[5],  *bk = (const float*)d_in[6];
    const float* wv = (const float*)d_in[7],  *bv = (const float*)d_in[8];
    const float* wp = (const float*)d_in[9],  *bp = (const float*)d_in[10];
    const float* t1w = (const float*)d_in[11], *t1b = (const float*)d_in[12];
    const float* t2w = (const float*)d_in[13], *t2b = (const float*)d_in[14];
    const float* f1w = (const float*)d_in[15], *f1b = (const float*)d_in[16];
    const float* f2w = (const float*)d_in[17], *f2b = (const float*)d_in[18];
    const float* ln1g = (const float*)d_in[19], *ln1b = (const float*)d_in[20];
    const float* ln2g = (const float*)d_in[21], *ln2b = (const float*)d_in[22];
    float* out = (float*)d_out;

    float* sc = nullptr;
    cudaGetSymbolAddress((void**)&sc, g_scratch);
    float* gH    = sc + OF_H;
    float* gQKV  = sc + OF_QKV;
    float* gA    = sc + OF_A;
    float* gX2   = sc + OF_X2;
    float* gF    = sc + OF_F;
    float* wcT   = sc + OF_WQT;
    float* wpT   = sc + OF_WPT;
    float* f1T   = sc + OF_F1T;
    float* f2T   = sc + OF_F2T;

    static cudaStream_t sBias = nullptr, sTr = nullptr;
    static cudaEvent_t eFork = nullptr, eBias = nullptr, eTr = nullptr, eTr2 = nullptr;
    if (sBias == nullptr) {
        cudaStreamCreateWithFlags(&sBias, cudaStreamNonBlocking);
        cudaStreamCreateWithFlags(&sTr, cudaStreamNonBlocking);
        cudaEventCreateWithFlags(&eFork, cudaEventDisableTiming);
        cudaEventCreateWithFlags(&eBias, cudaEventDisableTiming);
        cudaEventCreateWithFlags(&eTr, cudaEventDisableTiming);
        cudaEventCreateWithFlags(&eTr2, cudaEventDisableTiming);
        cudaFuncSetAttribute(gemm_big<0>, cudaFuncAttributeMaxDynamicSharedMemorySize, GEMM_SMEM2);
        cudaFuncSetAttribute(gemm_big<2>, cudaFuncAttributeMaxDynamicSharedMemorySize, GEMM_SMEM2);
        cudaFuncSetAttribute(gemm_n96, cudaFuncAttributeMaxDynamicSharedMemorySize, GEMM_SMEM3);
        cudaFuncSetAttribute(flash_kernel, cudaFuncAttributeMaxDynamicSharedMemorySize, FS_TOT);
    }

    dim3 tb(32, 8);

    // fork
    cudaEventRecord(eFork, 0);
    cudaStreamWaitEvent(sBias, eFork, 0);
    cudaStreamWaitEvent(sTr, eFork, 0);

    // branch B: temporal bias (needed only by flash)
    bias_kernel<<<(BB * TT * TT) / 256, 256, 0, sBias>>>(tmat, pm, t1w, t1b, t2w, t2b);
    cudaEventRecord(eBias, sBias);

    // branch C: attn transpose first (QKV dep), then FFN transpose (FFN dep, hidden)
    transpose_attn<<<dim3(24, 24, 4), tb, 0, sTr>>>(wq, wk, wv, wp, wcT);
    cudaEventRecord(eTr, sTr);
    transpose_ffn<<<dim3(96, 24, 2), tb, 0, sTr>>>(f1w, f1T, f2w, f2T);
    cudaEventRecord(eTr2, sTr);

    // main chain
    ln_kernel<<<MROWS, 256>>>(x, ln1g, ln1b, gH);
    cudaStreamWaitEvent(0, eTr, 0);
    gemm_big<0><<<dim3(2304 / BN2, MROWS / BM), 256, GEMM_SMEM2>>>(gH, wcT, bq, bk, bv, gQKV, 2304, DD);

    cudaStreamWaitEvent(0, eBias, 0);
    flash_kernel<<<dim3(TT / 64, BB * HH), 256, FS_TOT>>>(gQKV, gA);

    gemm_n96<<<dim3(DD / BN3, MROWS / BM), 256, GEMM_SMEM3>>>(gA, wpT, bp, x, gX2, DD, DD);

    ln_kernel<<<MROWS, 256>>>(gX2, ln2g, ln2b, gH);
    cudaStreamWaitEvent(0, eTr2, 0);
    gemm_big<2><<<dim3(FFC / BN2, MROWS / BM), 256, GEMM_SMEM2>>>(gH, f1T, f1b, nullptr, nullptr, gF, FFC, DD);
    gemm_n96<<<dim3(DD / BN3, MROWS / BM), 256, GEMM_SMEM3>>>(gF, f2T, f2b, gX2, out, DD, FFC);
}

// round 13
// speedup vs baseline: 1.0545x; 1.0006x over previous
#include <cuda_runtime.h>
#include <math.h>
#include <stdint.h>

// ---------------- problem constants ----------------
#define BB 4
#define TT 512
#define DD 768
#define HH 12
#define DKC 64
#define FFC 3072
#define TBN 64
#define NEGV (-1e9f)
#define E_CONST 2.718281828459045f
#define MROWS (BB*TT)            // 2048

// ---------------- scratch layout (floats) ----------------
#define OF_H    0ull
#define OF_BIAS 6291456ull
#define OF_S    7340032ull
#define OF_QKV  OF_S
#define OF_A    19922944ull
#define OF_X2   21495808ull
#define OF_F    23068672ull
#define OF_WQT  29360128ull
#define OF_WPT  31129600ull
#define OF_F1T  31719424ull
#define OF_F2T  34078720ull
#define SCRATCH_TOTAL 36438016ull

__device__ float g_scratch[SCRATCH_TOTAL];

// ---------------- helpers ----------------
__device__ __forceinline__ uint32_t smem_u32(const void* p) {
    uint32_t a;
    asm("{ .reg .u64 t; cvta.to.shared.u64 t, %1; cvt.u32.u64 %0, t; }" : "=r"(a) : "l"(p));
    return a;
}
__device__ __forceinline__ float f2tf32f(float f) {
    uint32_t r; asm("cvt.rna.tf32.f32 %0, %1;" : "=r"(r) : "f"(f));
    return __uint_as_float(r);
}
#define CP_ASYNC16(dst_u32, src_ptr) \
    asm volatile("cp.async.cg.shared.global [%0], [%1], 16;\n" :: "r"(dst_u32), "l"(__cvta_generic_to_global(src_ptr)))
#define CP_COMMIT() asm volatile("cp.async.commit_group;\n" ::: "memory")
#define CP_WAIT2()  asm volatile("cp.async.wait_group 2;\n" ::: "memory")
#define CP_WAIT0()  asm volatile("cp.async.wait_group 0;\n" ::: "memory")

#define MMA_TF32(c0,c1,c2,c3,a0,a1,a2,a3,b0,b1) \
    asm volatile("mma.sync.aligned.m16n8k8.row.col.f32.tf32.tf32.f32 " \
                 "{%0,%1,%2,%3}, {%4,%5,%6,%7}, {%8,%9}, {%0,%1,%2,%3};\n" \
                 : "+f"(c0), "+f"(c1), "+f"(c2), "+f"(c3) \
                 : "r"(a0), "r"(a1), "r"(a2), "r"(a3), "r"(b0), "r"(b1))

#define LDSM_X4(d0,d1,d2,d3,addr) \
    asm volatile("ldmatrix.sync.aligned.m8n8.x4.shared.b16 {%0,%1,%2,%3}, [%4];\n" \
                 : "=r"(d0), "=r"(d1), "=r"(d2), "=r"(d3) : "r"(addr))

#define LDT 20
#define BM 128

// =======================================================================
// big-tile GEMM — 128x128, 4-stage, warp tile 32x64.
// EPI 0 = split QKV bias (bq|bk|bv by column); EPI 2 = bias+GELU+tf32round.
// =======================================================================
#define BN2 128
#define GST2 4
#define GEMM_SMEM2 ((GST2*(BM+BN2)*LDT)*4)   // 81920

template <int EPI>
__global__ __launch_bounds__(256, 2) void gemm_big(const float* __restrict__ A,
                                                   const float* __restrict__ Wt,
                                                   const float* __restrict__ bias0,
                                                   const float* __restrict__ bias1,
                                                   const float* __restrict__ bias2,
                                                   float* __restrict__ C,
                                                   int N, int K) {
    extern __shared__ float dsm[];
    float* AsBase = dsm;
    float* BsBase = dsm + GST2 * BM * LDT;

    int tid = threadIdx.x;
    int warp = tid >> 5, lane = tid & 31;
    int wm = warp >> 1, wn = warp & 1;
    int g = lane >> 2, tig = lane & 3;
    int m0 = blockIdx.y * BM, n0 = blockIdx.x * BN2;

    int r0 = tid >> 2,            c0_ = (tid & 3) * 4;
    int r1 = (tid + 256) >> 2,    c1_ = ((tid + 256) & 3) * 4;

    uint32_t sA = smem_u32(AsBase);
    uint32_t sB = smem_u32(BsBase);
    const uint32_t bufA = BM * LDT * 4, bufB = BN2 * LDT * 4;

    int q = lane >> 3, l7 = lane & 7;
    int a_row = wm * 32 + (q & 1) * 8 + l7,  a_col = (q >> 1) * 4;
    int b_row = wn * 64 + (q >> 1) * 8 + l7, b_col = (q & 1) * 4;
    uint32_t aAddr0 = sA + (uint32_t)(a_row * LDT + a_col) * 4;
    uint32_t bAddr0 = sB + (uint32_t)(b_row * LDT + b_col) * 4;

    const int nk = K >> 4;

    #pragma unroll
    for (int pf = 0; pf < 3; pf++) {
        int k0 = pf * 16;
        CP_ASYNC16(sA + pf * bufA + (r0 * LDT + c0_) * 4, A + (size_t)(m0 + r0) * K + k0 + c0_);
        CP_ASYNC16(sA + pf * bufA + (r1 * LDT + c1_) * 4, A + (size_t)(m0 + r1) * K + k0 + c1_);
        CP_ASYNC16(sB + pf * bufB + (r0 * LDT + c0_) * 4, Wt + (size_t)(n0 + r0) * K + k0 + c0_);
        CP_ASYNC16(sB + pf * bufB + (r1 * LDT + c1_) * 4, Wt + (size_t)(n0 + r1) * K + k0 + c1_);
        CP_COMMIT();
    }

    float c[2][8][4];
    #pragma unroll
    for (int i = 0; i < 2; i++)
        #pragma unroll
        for (int j = 0; j < 8; j++)
            #pragma unroll
            for (int e = 0; e < 4; e++) c[i][j][e] = 0.f;

    for (int kt = 0; kt < nk; kt++) {
        int buf = kt & (GST2 - 1);
        CP_WAIT2();
        __syncthreads();

        uint32_t aBuf = aAddr0 + buf * bufA;
        uint32_t bBuf = bAddr0 + buf * bufB;
        #pragma unroll
        for (int ks = 0; ks < 2; ks++) {
            uint32_t kOff = (uint32_t)(ks * 8) * 4;
            uint32_t a[2][4], b[8][2];
            #pragma unroll
            for (int i = 0; i < 2; i++)
                LDSM_X4(a[i][0], a[i][1], a[i][2], a[i][3],
                        aBuf + (uint32_t)(i * 16 * LDT) * 4 + kOff);
            #pragma unroll
            for (int p = 0; p < 4; p++)
                LDSM_X4(b[2*p][0], b[2*p][1], b[2*p+1][0], b[2*p+1][1],
                        bBuf + (uint32_t)(p * 16 * LDT) * 4 + kOff);
            #pragma unroll
            for (int i = 0; i < 2; i++)
                #pragma unroll
                for (int j = 0; j < 8; j++)
                    MMA_TF32(c[i][j][0], c[i][j][1], c[i][j][2], c[i][j][3],
                             a[i][0], a[i][1], a[i][2], a[i][3], b[j][0], b[j][1]);
        }

        if (kt + 3 < nk) {
            int k0 = (kt + 3) * 16;
            int nbuf = (kt + 3) & (GST2 - 1);
            CP_ASYNC16(sA + nbuf * bufA + (r0 * LDT + c0_) * 4, A + (size_t)(m0 + r0) * K + k0 + c0_);
            CP_ASYNC16(sA + nbuf * bufA + (r1 * LDT + c1_) * 4, A + (size_t)(m0 + r1) * K + k0 + c1_);
            CP_ASYNC16(sB + nbuf * bufB + (r0 * LDT + c0_) * 4, Wt + (size_t)(n0 + r0) * K + k0 + c0_);
            CP_ASYNC16(sB + nbuf * bufB + (r1 * LDT + c1_) * 4, Wt + (size_t)(n0 + r1) * K + k0 + c1_);
        }
        CP_COMMIT();
    }

    #pragma unroll
    for (int i = 0; i < 2; i++) {
        int row0 = m0 + wm * 32 + i * 16 + g;
        #pragma unroll
        for (int j = 0; j < 8; j++) {
            int col = n0 + wn * 64 + j * 8 + 2 * tig;
            float b0, b1;
            if (EPI == 0) {
                const float* bp = (col < 768) ? bias0 : (col < 1536) ? bias1 : bias2;
                int bo = (col < 768) ? col : (col < 1536) ? col - 768 : col - 1536;
                b0 = bp[bo]; b1 = bp[bo + 1];
            } else {
                b0 = bias0[col]; b1 = bias0[col + 1];
            }
            #pragma unroll
            for (int half = 0; half < 2; half++) {
                int r = row0 + half * 8;
                float v0 = c[i][j][half * 2 + 0] + b0;
                float v1 = c[i][j][half * 2 + 1] + b1;
                if (EPI == 2) {
                    v0 = 0.5f * v0 * (1.f + erff(v0 * 0.70710678118654752f));
                    v1 = 0.5f * v1 * (1.f + erff(v1 * 0.70710678118654752f));
                    v0 = f2tf32f(v0); v1 = f2tf32f(v1);
                }
                float2 o; o.x = v0; o.y = v1;
                *(float2*)(C + (size_t)r * N + col) = o;
            }
        }
    }
}

// =======================================================================
// n96 GEMM — 128x96 tile, 4-stage, warp tile 32x48, bias+residual.
// =======================================================================
#define BN3 96
#define GST3 4
#define GEMM_SMEM3 ((GST3*(BM+BN3)*LDT)*4)   // 71680

__global__ __launch_bounds__(256, 2) void gemm_n96(const float* __restrict__ A,
                                                   const float* __restrict__ Wt,
                                                   const float* __restrict__ bias,
                                                   const float* __restrict__ res,
                                                   float* __restrict__ C,
                                                   int N, int K) {
    extern __shared__ float dsm[];
    float* AsBase = dsm;
    float* BsBase = dsm + GST3 * BM * LDT;

    int tid = threadIdx.x;
    int warp = tid >> 5, lane = tid & 31;
    int wm = warp >> 1, wn = warp & 1;
    int g = lane >> 2, tig = lane & 3;
    int m0 = blockIdx.y * BM, n0 = blockIdx.x * BN3;

    int ar0 = tid >> 2,            ac0 = (tid & 3) * 4;
    int ar1 = (tid + 256) >> 2,    ac1 = ((tid + 256) & 3) * 4;
    int br0 = tid >> 2,            bc0 = (tid & 3) * 4;
    int br1 = (tid + 256) >> 2,    bc1 = ((tid + 256) & 3) * 4;
    bool hasB1 = (tid < 128);

    uint32_t sA = smem_u32(AsBase);
    uint32_t sB = smem_u32(BsBase);
    const uint32_t bufA = BM * LDT * 4, bufB = BN3 * LDT * 4;

    int q = lane >> 3, l7 = lane & 7;
    int a_row = wm * 32 + (q & 1) * 8 + l7,  a_col = (q >> 1) * 4;
    int b_row = wn * 48 + (q >> 1) * 8 + l7, b_col = (q & 1) * 4;
    uint32_t aAddr0 = sA + (uint32_t)(a_row * LDT + a_col) * 4;
    uint32_t bAddr0 = sB + (uint32_t)(b_row * LDT + b_col) * 4;

    const int nk = K >> 4;

    #pragma unroll
    for (int pf = 0; pf < 3; pf++) {
        int k0 = pf * 16;
        CP_ASYNC16(sA + pf * bufA + (ar0 * LDT + ac0) * 4, A + (size_t)(m0 + ar0) * K + k0 + ac0);
        CP_ASYNC16(sA + pf * bufA + (ar1 * LDT + ac1) * 4, A + (size_t)(m0 + ar1) * K + k0 + ac1);
        CP_ASYNC16(sB + pf * bufB + (br0 * LDT + bc0) * 4, Wt + (size_t)(n0 + br0) * K + k0 + bc0);
        if (hasB1)
            CP_ASYNC16(sB + pf * bufB + (br1 * LDT + bc1) * 4, Wt + (size_t)(n0 + br1) * K + k0 + bc1);
        CP_COMMIT();
    }

    float c[2][6][4];
    #pragma unroll
    for (int i = 0; i < 2; i++)
        #pragma unroll
        for (int j = 0; j < 6; j++)
            #pragma unroll
            for (int e = 0; e < 4; e++) c[i][j][e] = 0.f;

    for (int kt = 0; kt < nk; kt++) {
        int buf = kt & (GST3 - 1);
        CP_WAIT2();
        __syncthreads();

        uint32_t aBuf = aAddr0 + buf * bufA;
        uint32_t bBuf = bAddr0 + buf * bufB;
        #pragma unroll
        for (int ks = 0; ks < 2; ks++) {
            uint32_t kOff = (uint32_t)(ks * 8) * 4;
            uint32_t a[2][4], b[6][2];
            #pragma unroll
            for (int i = 0; i < 2; i++)
                LDSM_X4(a[i][0], a[i][1], a[i][2], a[i][3],
                        aBuf + (uint32_t)(i * 16 * LDT) * 4 + kOff);
            #pragma unroll
            for (int p = 0; p < 3; p++)
                LDSM_X4(b[2*p][0], b[2*p][1], b[2*p+1][0], b[2*p+1][1],
                        bBuf + (uint32_t)(p * 16 * LDT) * 4 + kOff);
            #pragma unroll
            for (int i = 0; i < 2; i++)
                #pragma unroll
                for (int j = 0; j < 6; j++)
                    MMA_TF32(c[i][j][0], c[i][j][1], c[i][j][2], c[i][j][3],
                             a[i][0], a[i][1], a[i][2], a[i][3], b[j][0], b[j][1]);
        }

        if (kt + 3 < nk) {
            int k0 = (kt + 3) * 16;
            int nbuf = (kt + 3) & (GST3 - 1);
            CP_ASYNC16(sA + nbuf * bufA + (ar0 * LDT + ac0) * 4, A + (size_t)(m0 + ar0) * K + k0 + ac0);
            CP_ASYNC16(sA + nbuf * bufA + (ar1 * LDT + ac1) * 4, A + (size_t)(m0 + ar1) * K + k0 + ac1);
            CP_ASYNC16(sB + nbuf * bufB + (br0 * LDT + bc0) * 4, Wt + (size_t)(n0 + br0) * K + k0 + bc0);
            if (hasB1)
                CP_ASYNC16(sB + nbuf * bufB + (br1 * LDT + bc1) * 4, Wt + (size_t)(n0 + br1) * K + k0 + bc1);
        }
        CP_COMMIT();
    }

    #pragma unroll
    for (int i = 0; i < 2; i++) {
        int row0 = m0 + wm * 32 + i * 16 + g;
        #pragma unroll
        for (int j = 0; j < 6; j++) {
            int col = n0 + wn * 48 + j * 8 + 2 * tig;
            float b0 = bias[col], b1 = bias[col + 1];
            #pragma unroll
            for (int half = 0; half < 2; half++) {
                int r = row0 + half * 8;
                float2 r2 = *(const float2*)(res + (size_t)r * N + col);
                float2 o;
                o.x = c[i][j][half * 2 + 0] + b0 + r2.x;
                o.y = c[i][j][half * 2 + 1] + b1 + r2.y;
                *(float2*)(C + (size_t)r * N + col) = o;
            }
        }
    }
}

// ---------------- transposes (tf32-rounded) ----------------
// attn: wq,wk,wv only (z<3) — gates QKV
__global__ __launch_bounds__(256) void transpose_attn(const float* __restrict__ wq,
                                                      const float* __restrict__ wk,
                                                      const float* __restrict__ wv,
                                                      float* __restrict__ dst) {
    __shared__ float t[32][33];
    int z = blockIdx.z;
    const float* W = (z == 0) ? wq : (z == 1) ? wk : wv;
    float* Wt = dst + (size_t)z * 589824;
    int n0 = blockIdx.x * 32, k0 = blockIdx.y * 32;
    int tx = threadIdx.x, ty = threadIdx.y;
    #pragma unroll
    for (int i = 0; i < 32; i += 8)
        t[ty + i][tx] = W[(size_t)(k0 + ty + i) * DD + n0 + tx];
    __syncthreads();
    #pragma unroll
    for (int i = 0; i < 32; i += 8)
        Wt[(size_t)(n0 + ty + i) * DD + k0 + tx] = f2tf32f(t[tx][ty + i]);
}

// ffn + wp: z=0: f1w; z=1: f2w; z=2: wp (gates proj/FFN only)
__global__ __launch_bounds__(256) void transpose_ffn(const float* __restrict__ f1w,
                                                     float* __restrict__ f1T,
                                                     const float* __restrict__ f2w,
                                                     float* __restrict__ f2T,
                                                     const float* __restrict__ wp,
                                                     float* __restrict__ wpT) {
    __shared__ float t[32][33];
    int z = blockIdx.z;
    const float* W; float* Wt; int K, N, n0, k0;
    if (z == 0)      { W = f1w; Wt = f1T; K = DD;  N = FFC; n0 = blockIdx.x * 32; k0 = blockIdx.y * 32; }
    else if (z == 1) { W = f2w; Wt = f2T; K = FFC; N = DD;  n0 = blockIdx.y * 32; k0 = blockIdx.x * 32; }
    else             { if (blockIdx.x >= 24) return;
                       W = wp;  Wt = wpT; K = DD;  N = DD;  n0 = blockIdx.x * 32; k0 = blockIdx.y * 32; }
    int tx = threadIdx.x, ty = threadIdx.y;
    #pragma unroll
    for (int i = 0; i < 32; i += 8)
        t[ty + i][tx] = W[(size_t)(k0 + ty + i) * N + n0 + tx];
    __syncthreads();
    #pragma unroll
    for (int i = 0; i < 32; i += 8)
        Wt[(size_t)(n0 + ty + i) * K + k0 + tx] = f2tf32f(t[tx][ty + i]);
}

// ---------------- LayerNorm — warp-per-row, no block barrier ----------------
__global__ __launch_bounds__(256) void ln_kernel(const float* __restrict__ x,
                                                 const float* __restrict__ gw,
                                                 const float* __restrict__ bw,
                                                 float* __restrict__ out) {
    int warp = threadIdx.x >> 5, lane = threadIdx.x & 31;
    int row = blockIdx.x * 8 + warp;
    const float4* xr = (const float4*)(x + (size_t)row * DD);   // 192 float4
    float4 v[6];
    float s = 0.f, s2 = 0.f;
    #pragma unroll
    for (int i = 0; i < 6; i++) {
        v[i] = xr[lane + 32 * i];
        s  += v[i].x + v[i].y + v[i].z + v[i].w;
        s2 += v[i].x * v[i].x + v[i].y * v[i].y + v[i].z * v[i].z + v[i].w * v[i].w;
    }
    #pragma unroll
    for (int o = 16; o > 0; o >>= 1) {
        s  += __shfl_xor_sync(0xffffffffu, s,  o);
        s2 += __shfl_xor_sync(0xffffffffu, s2, o);
    }
    float mean = s * (1.f / DD);
    float var  = s2 * (1.f / DD) - mean * mean;
    float inv  = rsqrtf(var + 1e-5f);
    float4* orow = (float4*)(out + (size_t)row * DD);
    #pragma unroll
    for (int i = 0; i < 6; i++) {
        float4 gg = ((const float4*)gw)[lane + 32 * i];
        float4 bb = ((const float4*)bw)[lane + 32 * i];
        float4 o;
        o.x = f2tf32f((v[i].x - mean) * inv * gg.x + bb.x);
        o.y = f2tf32f((v[i].y - mean) * inv * gg.y + bb.y);
        o.z = f2tf32f((v[i].z - mean) * inv * gg.z + bb.z);
        o.w = f2tf32f((v[i].w - mean) * inv * gg.w + bb.w);
        orow[lane + 32 * i] = o;
    }
}

// ---------------- temporal bias w/ masks baked in (fast math) ----------------
__global__ __launch_bounds__(256) void bias_kernel(const float* __restrict__ tm,
                                                   const int* __restrict__ pm,
                                                   const float* __restrict__ t1w,
                                                   const float* __restrict__ t1b,
                                                   const float* __restrict__ t2w,
                                                   const float* __restrict__ t2b) {
    __shared__ float w1[TBN], b1[TBN], w2[TBN];
    int t = threadIdx.x;
    if (t < TBN) { w1[t] = t1w[t]; b1[t] = t1b[t]; w2[t] = t2w[t]; }
    __syncthreads();
    size_t idx = (size_t)blockIdx.x * 256 + t;
    int rem = (int)(idx % (TT * TT));
    int i = rem / TT, j = rem % TT;
    float u = __fdividef(1.f, __logf(E_CONST + tm[idx]));
    float s = t2b[0];
    #pragma unroll
    for (int k = 0; k < TBN; k++) {
        float z = fmaf(u, w1[k], b1[k]);
        z = (z > 0.f) ? z : 0.2f * z;
        s = fmaf(z, w2[k], s);
    }
    bool masked = (pm[idx] == 0) || (j > i && i > 0);
    g_scratch[OF_BIAS + idx] = masked ? NEGV : s;
}

// =======================================================================
// flash attention (validated scalar version) — longest-first block order
// =======================================================================
#define SQ_LD 68
#define SV_LD 72
#define FS_Q    0
#define FS_K    (64*68)
#define FS_V    (FS_K + 2*64*68)
#define FS_P    (FS_V + 2*64*72)
#define FS_STAT (FS_P + 64*68)
#define FS_TOT  ((FS_STAT + 256) * 4)

__global__ __launch_bounds__(256, 2) void flash_kernel(const float* __restrict__ qkv,
                                                       float* __restrict__ outA) {
    extern __shared__ float fs[];
    float* sQ = fs + FS_Q;
    float* sK = fs + FS_K;
    float* sV = fs + FS_V;
    float* sP = fs + FS_P;
    float* sMax = fs + FS_STAT;
    float* sSum = fs + FS_STAT + 128;
    uint32_t sKu = smem_u32(sK), sVu = smem_u32(sV);

    int tid = threadIdx.x;
    int warp = tid >> 5, lane = tid & 31;
    int wm = warp >> 1, wn = warp & 1;
    int g = lane >> 2, tig = lane & 3;
    int i0 = (gridDim.x - 1 - blockIdx.x) * 64;   // longest-first
    int bh = blockIdx.y, b = bh / HH, h = bh % HH;

    const float* base = qkv + (size_t)b * TT * 2304 + h * 64;
    const float* biasB = g_scratch + OF_BIAS + (size_t)b * TT * TT;

    for (int ch = tid; ch < 1024; ch += 256) {
        int r = ch >> 4, cc = (ch & 15) * 4;
        float4 v = *(const float4*)(base + (size_t)(i0 + r) * 2304 + cc);
        float4 o;
        o.x = f2tf32f(v.x * 0.125f); o.y = f2tf32f(v.y * 0.125f);
        o.z = f2tf32f(v.z * 0.125f); o.w = f2tf32f(v.w * 0.125f);
        *(float4*)(sQ + r * SQ_LD + cc) = o;
    }

    float o[4][4];
    #pragma unroll
    for (int j = 0; j < 4; j++)
        #pragma unroll
        for (int e = 0; e < 4; e++) o[j][e] = 0.f;
    float m0r = -INFINITY, m1r = -INFINITY, l0 = 0.f, l1 = 0.f;

    int ntiles = (i0 == 0) ? (TT / 64) : (i0 >> 6) + 1;
    int rw0 = wm * 16 + g, rw1 = rw0 + 8;

    {
        const float* kb_ = base + 768;
        const float* vb_ = base + 1536;
        for (int ch = tid; ch < 1024; ch += 256) {
            int r = ch >> 4, cc = (ch & 15) * 4;
            CP_ASYNC16(sKu + (r * SQ_LD + cc) * 4, kb_ + (size_t)r * 2304 + cc);
            CP_ASYNC16(sVu + (r * SV_LD + cc) * 4, vb_ + (size_t)r * 2304 + cc);
        }
        CP_COMMIT();
    }

    for (int t = 0; t < ntiles; t++) {
        int j0 = t * 64, buf = t & 1;
        CP_WAIT0();
        __syncthreads();

        float c[4][4];
        #pragma unroll
        for (int j = 0; j < 4; j++)
            #pragma unroll
            for (int e = 0; e < 4; e++) c[j][e] = 0.f;
        const float* kS = sK + buf * 64 * SQ_LD;
        #pragma unroll
        for (int kb = 0; kb < 64; kb += 8) {
            uint32_t a[4], bfr[4][2];
            int qr = wm * 16;
            a[0] = __float_as_uint(sQ[(qr + g)     * SQ_LD + kb + tig]);
            a[1] = __float_as_uint(sQ[(qr + 8 + g) * SQ_LD + kb + tig]);
            a[2] = __float_as_uint(sQ[(qr + g)     * SQ_LD + kb + tig + 4]);
            a[3] = __float_as_uint(sQ[(qr + 8 + g) * SQ_LD + kb + tig + 4]);
            #pragma unroll
            for (int j = 0; j < 4; j++) {
                int r = wn * 32 + j * 8 + g;
                bfr[j][0] = __float_as_uint(kS[r * SQ_LD + kb + tig]);
                bfr[j][1] = __float_as_uint(kS[r * SQ_LD + kb + tig + 4]);
            }
            #pragma unroll
            for (int j = 0; j < 4; j++)
                MMA_TF32(c[j][0], c[j][1], c[j][2], c[j][3],
                         a[0], a[1], a[2], a[3], bfr[j][0], bfr[j][1]);
        }

        int gi0 = i0 + rw0, gi1 = i0 + rw1;
        #pragma unroll
        for (int j = 0; j < 4; j++) {
            int gj = j0 + wn * 32 + j * 8 + 2 * tig;
            float2 b0 = *(const float2*)(biasB + (size_t)gi0 * TT + gj);
            float2 b1 = *(const float2*)(biasB + (size_t)gi1 * TT + gj);
            c[j][0] += b0.x; c[j][1] += b0.y;
            c[j][2] += b1.x; c[j][3] += b1.y;
        }

        float mx0 = c[0][0], mx1 = c[0][2];
        #pragma unroll
        for (int j = 0; j < 4; j++) {
            mx0 = fmaxf(mx0, fmaxf(c[j][0], c[j][1]));
            mx1 = fmaxf(mx1, fmaxf(c[j][2], c[j][3]));
        }
        mx0 = fmaxf(mx0, __shfl_xor_sync(0xffffffffu, mx0, 1));
        mx0 = fmaxf(mx0, __shfl_xor_sync(0xffffffffu, mx0, 2));
        mx1 = fmaxf(mx1, __shfl_xor_sync(0xffffffffu, mx1, 1));
        mx1 = fmaxf(mx1, __shfl_xor_sync(0xffffffffu, mx1, 2));
        if (tig == 0) { sMax[wn * 64 + rw0] = mx0; sMax[wn * 64 + rw1] = mx1; }
        __syncthreads();
        float mxc0 = fmaxf(sMax[rw0], sMax[64 + rw0]);
        float mxc1 = fmaxf(sMax[rw1], sMax[64 + rw1]);

        float mn0 = fmaxf(m0r, mxc0), mn1 = fmaxf(m1r, mxc1);
        float al0 = __expf(m0r - mn0), al1 = __expf(m1r - mn1);

        float sum0 = 0.f, sum1 = 0.f;
        #pragma unroll
        for (int j = 0; j < 4; j++) {
            int cw = wn * 32 + j * 8 + 2 * tig;
            float p00 = __expf(c[j][0] - mn0), p01 = __expf(c[j][1] - mn0);
            float p10 = __expf(c[j][2] - mn1), p11 = __expf(c[j][3] - mn1);
            sum0 += p00 + p01; sum1 += p10 + p11;
            float2 q0; q0.x = p00; q0.y = p01;
            float2 q1; q1.x = p10; q1.y = p11;
            *(float2*)(sP + rw0 * SQ_LD + cw) = q0;
            *(float2*)(sP + rw1 * SQ_LD + cw) = q1;
        }
        sum0 += __shfl_xor_sync(0xffffffffu, sum0, 1);
        sum0 += __shfl_xor_sync(0xffffffffu, sum0, 2);
        sum1 += __shfl_xor_sync(0xffffffffu, sum1, 1);
        sum1 += __shfl_xor_sync(0xffffffffu, sum1, 2);
        if (tig == 0) { sSum[wn * 64 + rw0] = sum0; sSum[wn * 64 + rw1] = sum1; }
        __syncthreads();
        float sc0 = sSum[rw0] + sSum[64 + rw0];
        float sc1 = sSum[rw1] + sSum[64 + rw1];

        l0 = l0 * al0 + sc0;  l1 = l1 * al1 + sc1;
        m0r = mn0;  m1r = mn1;
        #pragma unroll
        for (int j = 0; j < 4; j++) {
            o[j][0] *= al0; o[j][1] *= al0;
            o[j][2] *= al1; o[j][3] *= al1;
        }

        if (t + 1 < ntiles) {
            int nj0 = (t + 1) * 64, nb = buf ^ 1;
            const float* kb_ = base + 768;
            const float* vb_ = base + 1536;
            for (int ch = tid; ch < 1024; ch += 256) {
                int r = ch >> 4, cc = (ch & 15) * 4;
                CP_ASYNC16(sKu + (nb * 64 * SQ_LD + r * SQ_LD + cc) * 4, kb_ + (size_t)(nj0 + r) * 2304 + cc);
                CP_ASYNC16(sVu + (nb * 64 * SV_LD + r * SV_LD + cc) * 4, vb_ + (size_t)(nj0 + r) * 2304 + cc);
            }
            CP_COMMIT();
        }

        const float* vS = sV + buf * 64 * SV_LD;
        #pragma unroll
        for (int kb = 0; kb < 64; kb += 8) {
            uint32_t a[4], bfr[4][2];
            int pr = wm * 16;
            a[0] = __float_as_uint(sP[(pr + g)     * SQ_LD + kb + tig]);
            a[1] = __float_as_uint(sP[(pr + 8 + g) * SQ_LD + kb + tig]);
            a[2] = __float_as_uint(sP[(pr + g)     * SQ_LD + kb + tig + 4]);
            a[3] = __float_as_uint(sP[(pr + 8 + g) * SQ_LD + kb + tig + 4]);
            #pragma unroll
            for (int j = 0; j < 4; j++) {
                int nc = wn * 32 + j * 8 + g;
                bfr[j][0] = __float_as_uint(vS[(kb + tig)     * SV_LD + nc]);
                bfr[j][1] = __float_as_uint(vS[(kb + tig + 4) * SV_LD + nc]);
            }
            #pragma unroll
            for (int j = 0; j < 4; j++)
                MMA_TF32(o[j][0], o[j][1], o[j][2], o[j][3],
                         a[0], a[1], a[2], a[3], bfr[j][0], bfr[j][1]);
        }
        __syncthreads();
    }

    float inv0 = 1.f / l0, inv1 = 1.f / l1;
    int gr0 = b * TT + i0 + wm * 16 + g, gr1 = gr0 + 8;
    #pragma unroll
    for (int j = 0; j < 4; j++) {
        int col = h * 64 + wn * 32 + j * 8 + 2 * tig;
        float2 o0, o1;
        o0.x = f2tf32f(o[j][0] * inv0); o0.y = f2tf32f(o[j][1] * inv0);
        o1.x = f2tf32f(o[j][2] * inv1); o1.y = f2tf32f(o[j][3] * inv1);
        *(float2*)(outA + (size_t)gr0 * DD + col) = o0;
        *(float2*)(outA + (size_t)gr1 * DD + col) = o1;
    }
}

// ---------------- launch ----------------
extern "C" void kernel_launch(void* const* d_in, const int* in_sizes, int n_in,
                              void* d_out, int out_size) {
    const float* x     = (const float*)d_in[0];
    const float* tmat  = (const float*)d_in[1];
    const int*   pm    = (const int*)d_in[2];
    const float* wq = (const float*)d_in[3],  *bq = (const float*)d_in[4];
    const float* wk = (const float*)d_in[5],  *bk = (const float*)d_in[6];
    const float* wv = (const float*)d_in[7],  *bv = (const float*)d_in[8];
    const float* wp = (const float*)d_in[9],  *bp = (const float*)d_in[10];
    const float* t1w = (const float*)d_in[11], *t1b = (const float*)d_in[12];
    const float* t2w = (const float*)d_in[13], *t2b = (const float*)d_in[14];
    const float* f1w = (const float*)d_in[15], *f1b = (const float*)d_in[16];
    const float* f2w = (const float*)d_in[17], *f2b = (const float*)d_in[18];
    const float* ln1g = (const float*)d_in[19], *ln1b = (const float*)d_in[20];
    const float* ln2g = (const float*)d_in[21], *ln2b = (const float*)d_in[22];
    float* out = (float*)d_out;

    float* sc = nullptr;
    cudaGetSymbolAddress((void**)&sc, g_scratch);
    float* gH    = sc + OF_H;
    float* gQKV  = sc + OF_QKV;
    float* gA    = sc + OF_A;
    float* gX2   = sc + OF_X2;
    float* gF    = sc + OF_F;
    float* wcT   = sc + OF_WQT;
    float* wpT   = sc + OF_WPT;
    float* f1T   = sc + OF_F1T;
    float* f2T   = sc + OF_F2T;

    static cudaStream_t sBias = nullptr, sTr = nullptr;
    static cudaEvent_t eFork = nullptr, eBias = nullptr, eTr = nullptr, eTr2 = nullptr;
    if (sBias == nullptr) {
        cudaStreamCreateWithFlags(&sBias, cudaStreamNonBlocking);
        cudaStreamCreateWithFlags(&sTr, cudaStreamNonBlocking);
        cudaEventCreateWithFlags(&eFork, cudaEventDisableTiming);
        cudaEventCreateWithFlags(&eBias, cudaEventDisableTiming);
        cudaEventCreateWithFlags(&eTr, cudaEventDisableTiming);
        cudaEventCreateWithFlags(&eTr2, cudaEventDisableTiming);
        cudaFuncSetAttribute(gemm_big<0>, cudaFuncAttributeMaxDynamicSharedMemorySize, GEMM_SMEM2);
        cudaFuncSetAttribute(gemm_big<2>, cudaFuncAttributeMaxDynamicSharedMemorySize, GEMM_SMEM2);
        cudaFuncSetAttribute(gemm_n96, cudaFuncAttributeMaxDynamicSharedMemorySize, GEMM_SMEM3);
        cudaFuncSetAttribute(flash_kernel, cudaFuncAttributeMaxDynamicSharedMemorySize, FS_TOT);
    }

    dim3 tb(32, 8);

    // fork
    cudaEventRecord(eFork, 0);
    cudaStreamWaitEvent(sBias, eFork, 0);
    cudaStreamWaitEvent(sTr, eFork, 0);

    // branch B: temporal bias (needed only by flash)
    bias_kernel<<<(BB * TT * TT) / 256, 256, 0, sBias>>>(tmat, pm, t1w, t1b, t2w, t2b);
    cudaEventRecord(eBias, sBias);

    // branch C: qkv transposes first (gate QKV), then ffn+wp (gate proj/FFN)
    transpose_attn<<<dim3(24, 24, 3), tb, 0, sTr>>>(wq, wk, wv, wcT);
    cudaEventRecord(eTr, sTr);
    transpose_ffn<<<dim3(96, 24, 3), tb, 0, sTr>>>(f1w, f1T, f2w, f2T, wp, wpT);
    cudaEventRecord(eTr2, sTr);

    // main chain
    ln_kernel<<<MROWS / 8, 256>>>(x, ln1g, ln1b, gH);
    cudaStreamWaitEvent(0, eTr, 0);
    gemm_big<0><<<dim3(2304 / BN2, MROWS / BM), 256, GEMM_SMEM2>>>(gH, wcT, bq, bk, bv, gQKV, 2304, DD);

    cudaStreamWaitEvent(0, eBias, 0);
    flash_kernel<<<dim3(TT / 64, BB * HH), 256, FS_TOT>>>(gQKV, gA);

    cudaStreamWaitEvent(0, eTr2, 0);
    gemm_n96<<<dim3(DD / BN3, MROWS / BM), 256, GEMM_SMEM3>>>(gA, wpT, bp, x, gX2, DD, DD);

    ln_kernel<<<MROWS / 8, 256>>>(gX2, ln2g, ln2b, gH);
    gemm_big<2><<<dim3(FFC / BN2, MROWS / BM), 256, GEMM_SMEM2>>>(gH, f1T, f1b, nullptr, nullptr, gF, FFC, DD);
    gemm_n96<<<dim3(DD / BN3, MROWS / BM), 256, GEMM_SMEM3>>>(gF, f2T, f2b, gX2, out, DD, FFC);
}

// round 14
// speedup vs baseline: 1.2135x; 1.1508x over previous
#include <cuda_runtime.h>
#include <cuda_bf16.h>
#include <math.h>
#include <stdint.h>

// ---------------- problem constants ----------------
#define BB 4
#define TT 512
#define DD 768
#define HH 12
#define FFC 3072
#define TBN 64
#define NEGV (-1e9f)
#define E_CONST 2.718281828459045f
#define MROWS (BB*TT)            // 2048

// ---------------- scratch layout (floats) ----------------
#define OF_H    0ull             // LN out, stored as bf16 (region sized for f32 = plenty)
#define OF_BIAS 6291456ull
#define OF_S    7340032ull
#define OF_QKV  OF_S
#define OF_A    19922944ull
#define OF_X2   21495808ull
#define OF_F    23068672ull
#define OF_WQT  29360128ull      // wq|wk|wv transposed, bf16
#define OF_WPT  31129600ull      // f32
#define OF_F1T  31719424ull      // bf16
#define OF_F2T  34078720ull      // f32
#define SCRATCH_TOTAL 36438016ull

__device__ float g_scratch[SCRATCH_TOTAL];

// ---------------- helpers ----------------
__device__ __forceinline__ uint32_t smem_u32(const void* p) {
    uint32_t a;
    asm("{ .reg .u64 t; cvta.to.shared.u64 t, %1; cvt.u32.u64 %0, t; }" : "=r"(a) : "l"(p));
    return a;
}
__device__ __forceinline__ float f2tf32f(float f) {
    uint32_t r; asm("cvt.rna.tf32.f32 %0, %1;" : "=r"(r) : "f"(f));
    return __uint_as_float(r);
}
#define CP_ASYNC16(dst_u32, src_ptr) \
    asm volatile("cp.async.cg.shared.global [%0], [%1], 16;\n" :: "r"(dst_u32), "l"(__cvta_generic_to_global(src_ptr)))
#define CP_COMMIT() asm volatile("cp.async.commit_group;\n" ::: "memory")
#define CP_WAIT2()  asm volatile("cp.async.wait_group 2;\n" ::: "memory")
#define CP_WAIT0()  asm volatile("cp.async.wait_group 0;\n" ::: "memory")

#define MMA_TF32(c0,c1,c2,c3,a0,a1,a2,a3,b0,b1) \
    asm volatile("mma.sync.aligned.m16n8k8.row.col.f32.tf32.tf32.f32 " \
                 "{%0,%1,%2,%3}, {%4,%5,%6,%7}, {%8,%9}, {%0,%1,%2,%3};\n" \
                 : "+f"(c0), "+f"(c1), "+f"(c2), "+f"(c3) \
                 : "r"(a0), "r"(a1), "r"(a2), "r"(a3), "r"(b0), "r"(b1))

#define MMA_BF16(c0,c1,c2,c3,a0,a1,a2,a3,b0,b1) \
    asm volatile("mma.sync.aligned.m16n8k16.row.col.f32.bf16.bf16.f32 " \
                 "{%0,%1,%2,%3}, {%4,%5,%6,%7}, {%8,%9}, {%0,%1,%2,%3};\n" \
                 : "+f"(c0), "+f"(c1), "+f"(c2), "+f"(c3) \
                 : "r"(a0), "r"(a1), "r"(a2), "r"(a3), "r"(b0), "r"(b1))

#define LDSM_X4(d0,d1,d2,d3,addr) \
    asm volatile("ldmatrix.sync.aligned.m8n8.x4.shared.b16 {%0,%1,%2,%3}, [%4];\n" \
                 : "=r"(d0), "=r"(d1), "=r"(d2), "=r"(d3) : "r"(addr))

#define LDT 20
#define BM 128

// =======================================================================
// bf16 GEMM — 128x128 tile, BK=32, 4-stage, warp tile 32x64.
// EPI 0 = split QKV bias; EPI 2 = bias+GELU+tf32round (FFN1 -> tf32 FFN2).
// A[M,K], Wt[N,K] both bf16 (pre-rounded rn). Accum f32.
// =======================================================================
#define LDTH 40                               // bf16 elems/row (80 B)
#define GSTH 4
#define GEMM_SMEMH (GSTH * 2 * BM * LDTH * 2) // 81920 B

template <int EPI>
__global__ __launch_bounds__(256, 2) void gemm_bf16(const __nv_bfloat16* __restrict__ A,
                                                    const __nv_bfloat16* __restrict__ Wt,
                                                    const float* __restrict__ bias0,
                                                    const float* __restrict__ bias1,
                                                    const float* __restrict__ bias2,
                                                    float* __restrict__ C,
                                                    int N, int K) {
    extern __shared__ char hsm[];
    char* AsBase = hsm;
    char* BsBase = hsm + GSTH * BM * LDTH * 2;

    int tid = threadIdx.x;
    int warp = tid >> 5, lane = tid & 31;
    int wm = warp >> 1, wn = warp & 1;
    int g = lane >> 2, tig = lane & 3;
    int m0 = blockIdx.y * BM, n0 = blockIdx.x * 128;

    // cp.async mapping: 512 16B-chunks per operand per stage; 2 each per thread
    int r0 = tid >> 2,       c0_ = (tid & 3) * 8;     // elems
    int r1 = r0 + 64,        c1_ = c0_;

    uint32_t sA = smem_u32(AsBase);
    uint32_t sB = smem_u32(BsBase);
    const uint32_t bufA = BM * LDTH * 2, bufB = 128 * LDTH * 2;

    int l15 = lane & 15, kh = lane >> 4;
    uint32_t aAddr0 = sA + (uint32_t)((wm * 32 + l15) * LDTH) * 2 + kh * 16;
    uint32_t bAddr0 = sB + (uint32_t)((wn * 64 + l15) * LDTH) * 2 + kh * 16;

    const int nk = K >> 5;

    #pragma unroll
    for (int pf = 0; pf < 3; pf++) {
        int k0 = pf * 32;
        CP_ASYNC16(sA + pf * bufA + (r0 * LDTH + c0_) * 2, A + (size_t)(m0 + r0) * K + k0 + c0_);
        CP_ASYNC16(sA + pf * bufA + (r1 * LDTH + c1_) * 2, A + (size_t)(m0 + r1) * K + k0 + c1_);
        CP_ASYNC16(sB + pf * bufB + (r0 * LDTH + c0_) * 2, Wt + (size_t)(n0 + r0) * K + k0 + c0_);
        CP_ASYNC16(sB + pf * bufB + (r1 * LDTH + c1_) * 2, Wt + (size_t)(n0 + r1) * K + k0 + c1_);
        CP_COMMIT();
    }

    float c[2][8][4];
    #pragma unroll
    for (int i = 0; i < 2; i++)
        #pragma unroll
        for (int j = 0; j < 8; j++)
            #pragma unroll
            for (int e = 0; e < 4; e++) c[i][j][e] = 0.f;

    for (int kt = 0; kt < nk; kt++) {
        int buf = kt & (GSTH - 1);
        CP_WAIT2();
        __syncthreads();

        uint32_t aBuf = aAddr0 + buf * bufA;
        uint32_t bBuf = bAddr0 + buf * bufB;
        #pragma unroll
        for (int ks = 0; ks < 2; ks++) {           // two k16 steps per 32-k stage
            uint32_t kOff = (uint32_t)(ks * 32);   // 16 bf16 = 32 bytes
            uint32_t a[2][4], b[8][2];
            #pragma unroll
            for (int i = 0; i < 2; i++)
                LDSM_X4(a[i][0], a[i][1], a[i][2], a[i][3],
                        aBuf + (uint32_t)(i * 16 * LDTH) * 2 + kOff);
            #pragma unroll
            for (int p = 0; p < 4; p++)
                LDSM_X4(b[2*p][0], b[2*p+1][0], b[2*p][1], b[2*p+1][1],
                        bBuf + (uint32_t)(p * 16 * LDTH) * 2 + kOff);
            #pragma unroll
            for (int i = 0; i < 2; i++)
                #pragma unroll
                for (int j = 0; j < 8; j++)
                    MMA_BF16(c[i][j][0], c[i][j][1], c[i][j][2], c[i][j][3],
                             a[i][0], a[i][1], a[i][2], a[i][3], b[j][0], b[j][1]);
        }

        if (kt + 3 < nk) {
            int k0 = (kt + 3) * 32;
            int nbuf = (kt + 3) & (GSTH - 1);
            CP_ASYNC16(sA + nbuf * bufA + (r0 * LDTH + c0_) * 2, A + (size_t)(m0 + r0) * K + k0 + c0_);
            CP_ASYNC16(sA + nbuf * bufA + (r1 * LDTH + c1_) * 2, A + (size_t)(m0 + r1) * K + k0 + c1_);
            CP_ASYNC16(sB + nbuf * bufB + (r0 * LDTH + c0_) * 2, Wt + (size_t)(n0 + r0) * K + k0 + c0_);
            CP_ASYNC16(sB + nbuf * bufB + (r1 * LDTH + c1_) * 2, Wt + (size_t)(n0 + r1) * K + k0 + c1_);
        }
        CP_COMMIT();
    }

    #pragma unroll
    for (int i = 0; i < 2; i++) {
        int row0 = m0 + wm * 32 + i * 16 + g;
        #pragma unroll
        for (int j = 0; j < 8; j++) {
            int col = n0 + wn * 64 + j * 8 + 2 * tig;
            float b0, b1;
            if (EPI == 0) {
                const float* bp = (col < 768) ? bias0 : (col < 1536) ? bias1 : bias2;
                int bo = (col < 768) ? col : (col < 1536) ? col - 768 : col - 1536;
                b0 = bp[bo]; b1 = bp[bo + 1];
            } else {
                b0 = bias0[col]; b1 = bias0[col + 1];
            }
            #pragma unroll
            for (int half = 0; half < 2; half++) {
                int r = row0 + half * 8;
                float v0 = c[i][j][half * 2 + 0] + b0;
                float v1 = c[i][j][half * 2 + 1] + b1;
                if (EPI == 2) {
                    v0 = 0.5f * v0 * (1.f + erff(v0 * 0.70710678118654752f));
                    v1 = 0.5f * v1 * (1.f + erff(v1 * 0.70710678118654752f));
                    v0 = f2tf32f(v0); v1 = f2tf32f(v1);
                }
                float2 o; o.x = v0; o.y = v1;
                *(float2*)(C + (size_t)r * N + col) = o;
            }
        }
    }
}

// =======================================================================
// n96 tf32 GEMM — 128x96, 4-stage, warp tile 32x48, bias+residual (proj/FFN2).
// =======================================================================
#define BN3 96
#define GST3 4
#define GEMM_SMEM3 ((GST3*(BM+BN3)*LDT)*4)   // 71680

__global__ __launch_bounds__(256, 2) void gemm_n96(const float* __restrict__ A,
                                                   const float* __restrict__ Wt,
                                                   const float* __restrict__ bias,
                                                   const float* __restrict__ res,
                                                   float* __restrict__ C,
                                                   int N, int K) {
    extern __shared__ float dsm[];
    float* AsBase = dsm;
    float* BsBase = dsm + GST3 * BM * LDT;

    int tid = threadIdx.x;
    int warp = tid >> 5, lane = tid & 31;
    int wm = warp >> 1, wn = warp & 1;
    int g = lane >> 2, tig = lane & 3;
    int m0 = blockIdx.y * BM, n0 = blockIdx.x * BN3;

    int ar0 = tid >> 2,            ac0 = (tid & 3) * 4;
    int ar1 = (tid + 256) >> 2,    ac1 = ((tid + 256) & 3) * 4;
    int br0 = tid >> 2,            bc0 = (tid & 3) * 4;
    int br1 = (tid + 256) >> 2,    bc1 = ((tid + 256) & 3) * 4;
    bool hasB1 = (tid < 128);

    uint32_t sA = smem_u32(AsBase);
    uint32_t sB = smem_u32(BsBase);
    const uint32_t bufA = BM * LDT * 4, bufB = BN3 * LDT * 4;

    int q = lane >> 3, l7 = lane & 7;
    int a_row = wm * 32 + (q & 1) * 8 + l7,  a_col = (q >> 1) * 4;
    int b_row = wn * 48 + (q >> 1) * 8 + l7, b_col = (q & 1) * 4;
    uint32_t aAddr0 = sA + (uint32_t)(a_row * LDT + a_col) * 4;
    uint32_t bAddr0 = sB + (uint32_t)(b_row * LDT + b_col) * 4;

    const int nk = K >> 4;

    #pragma unroll
    for (int pf = 0; pf < 3; pf++) {
        int k0 = pf * 16;
        CP_ASYNC16(sA + pf * bufA + (ar0 * LDT + ac0) * 4, A + (size_t)(m0 + ar0) * K + k0 + ac0);
        CP_ASYNC16(sA + pf * bufA + (ar1 * LDT + ac1) * 4, A + (size_t)(m0 + ar1) * K + k0 + ac1);
        CP_ASYNC16(sB + pf * bufB + (br0 * LDT + bc0) * 4, Wt + (size_t)(n0 + br0) * K + k0 + bc0);
        if (hasB1)
            CP_ASYNC16(sB + pf * bufB + (br1 * LDT + bc1) * 4, Wt + (size_t)(n0 + br1) * K + k0 + bc1);
        CP_COMMIT();
    }

    float c[2][6][4];
    #pragma unroll
    for (int i = 0; i < 2; i++)
        #pragma unroll
        for (int j = 0; j < 6; j++)
            #pragma unroll
            for (int e = 0; e < 4; e++) c[i][j][e] = 0.f;

    for (int kt = 0; kt < nk; kt++) {
        int buf = kt & (GST3 - 1);
        CP_WAIT2();
        __syncthreads();

        uint32_t aBuf = aAddr0 + buf * bufA;
        uint32_t bBuf = bAddr0 + buf * bufB;
        #pragma unroll
        for (int ks = 0; ks < 2; ks++) {
            uint32_t kOff = (uint32_t)(ks * 8) * 4;
            uint32_t a[2][4], b[6][2];
            #pragma unroll
            for (int i = 0; i < 2; i++)
                LDSM_X4(a[i][0], a[i][1], a[i][2], a[i][3],
                        aBuf + (uint32_t)(i * 16 * LDT) * 4 + kOff);
            #pragma unroll
            for (int p = 0; p < 3; p++)
                LDSM_X4(b[2*p][0], b[2*p][1], b[2*p+1][0], b[2*p+1][1],
                        bBuf + (uint32_t)(p * 16 * LDT) * 4 + kOff);
            #pragma unroll
            for (int i = 0; i < 2; i++)
                #pragma unroll
                for (int j = 0; j < 6; j++)
                    MMA_TF32(c[i][j][0], c[i][j][1], c[i][j][2], c[i][j][3],
                             a[i][0], a[i][1], a[i][2], a[i][3], b[j][0], b[j][1]);
        }

        if (kt + 3 < nk) {
            int k0 = (kt + 3) * 16;
            int nbuf = (kt + 3) & (GST3 - 1);
            CP_ASYNC16(sA + nbuf * bufA + (ar0 * LDT + ac0) * 4, A + (size_t)(m0 + ar0) * K + k0 + ac0);
            CP_ASYNC16(sA + nbuf * bufA + (ar1 * LDT + ac1) * 4, A + (size_t)(m0 + ar1) * K + k0 + ac1);
            CP_ASYNC16(sB + nbuf * bufB + (br0 * LDT + bc0) * 4, Wt + (size_t)(n0 + br0) * K + k0 + bc0);
            if (hasB1)
                CP_ASYNC16(sB + nbuf * bufB + (br1 * LDT + bc1) * 4, Wt + (size_t)(n0 + br1) * K + k0 + bc1);
        }
        CP_COMMIT();
    }

    #pragma unroll
    for (int i = 0; i < 2; i++) {
        int row0 = m0 + wm * 32 + i * 16 + g;
        #pragma unroll
        for (int j = 0; j < 6; j++) {
            int col = n0 + wn * 48 + j * 8 + 2 * tig;
            float b0 = bias[col], b1 = bias[col + 1];
            #pragma unroll
            for (int half = 0; half < 2; half++) {
                int r = row0 + half * 8;
                float2 r2 = *(const float2*)(res + (size_t)r * N + col);
                float2 o;
                o.x = c[i][j][half * 2 + 0] + b0 + r2.x;
                o.y = c[i][j][half * 2 + 1] + b1 + r2.y;
                *(float2*)(C + (size_t)r * N + col) = o;
            }
        }
    }
}

// ---------------- transposes ----------------
// attn: wq,wk,wv -> bf16 (gates QKV)
__global__ __launch_bounds__(256) void transpose_attn(const float* __restrict__ wq,
                                                      const float* __restrict__ wk,
                                                      const float* __restrict__ wv,
                                                      __nv_bfloat16* __restrict__ dst) {
    __shared__ float t[32][33];
    int z = blockIdx.z;
    const float* W = (z == 0) ? wq : (z == 1) ? wk : wv;
    __nv_bfloat16* Wt = dst + (size_t)z * 589824;
    int n0 = blockIdx.x * 32, k0 = blockIdx.y * 32;
    int tx = threadIdx.x, ty = threadIdx.y;
    #pragma unroll
    for (int i = 0; i < 32; i += 8)
        t[ty + i][tx] = W[(size_t)(k0 + ty + i) * DD + n0 + tx];
    __syncthreads();
    #pragma unroll
    for (int i = 0; i < 32; i += 8)
        Wt[(size_t)(n0 + ty + i) * DD + k0 + tx] = __float2bfloat16(t[tx][ty + i]);
}

// ffn + wp: z=0: f1w->bf16; z=1: f2w->f32 tf32; z=2: wp->f32 tf32
__global__ __launch_bounds__(256) void transpose_ffn(const float* __restrict__ f1w,
                                                     __nv_bfloat16* __restrict__ f1T,
                                                     const float* __restrict__ f2w,
                                                     float* __restrict__ f2T,
                                                     const float* __restrict__ wp,
                                                     float* __restrict__ wpT) {
    __shared__ float t[32][33];
    int z = blockIdx.z;
    const float* W; int K, N, n0, k0;
    if (z == 0)      { W = f1w; K = DD;  N = FFC; n0 = blockIdx.x * 32; k0 = blockIdx.y * 32; }
    else if (z == 1) { W = f2w; K = FFC; N = DD;  n0 = blockIdx.y * 32; k0 = blockIdx.x * 32; }
    else             { if (blockIdx.x >= 24) return;
                       W = wp;  K = DD;  N = DD;  n0 = blockIdx.x * 32; k0 = blockIdx.y * 32; }
    int tx = threadIdx.x, ty = threadIdx.y;
    #pragma unroll
    for (int i = 0; i < 32; i += 8)
        t[ty + i][tx] = W[(size_t)(k0 + ty + i) * N + n0 + tx];
    __syncthreads();
    #pragma unroll
    for (int i = 0; i < 32; i += 8) {
        float v = t[tx][ty + i];
        size_t off = (size_t)(n0 + ty + i) * K + k0 + tx;
        if (z == 0)      f1T[off] = __float2bfloat16(v);
        else if (z == 1) f2T[off] = f2tf32f(v);
        else             wpT[off] = f2tf32f(v);
    }
}

// ---------------- LayerNorm — warp-per-row, bf16 output ----------------
__global__ __launch_bounds__(256) void ln_kernel(const float* __restrict__ x,
                                                 const float* __restrict__ gw,
                                                 const float* __restrict__ bw,
                                                 __nv_bfloat16* __restrict__ out) {
    int warp = threadIdx.x >> 5, lane = threadIdx.x & 31;
    int row = blockIdx.x * 8 + warp;
    const float4* xr = (const float4*)(x + (size_t)row * DD);
    float4 v[6];
    float s = 0.f, s2 = 0.f;
    #pragma unroll
    for (int i = 0; i < 6; i++) {
        v[i] = xr[lane + 32 * i];
        s  += v[i].x + v[i].y + v[i].z + v[i].w;
        s2 += v[i].x * v[i].x + v[i].y * v[i].y + v[i].z * v[i].z + v[i].w * v[i].w;
    }
    #pragma unroll
    for (int o = 16; o > 0; o >>= 1) {
        s  += __shfl_xor_sync(0xffffffffu, s,  o);
        s2 += __shfl_xor_sync(0xffffffffu, s2, o);
    }
    float mean = s * (1.f / DD);
    float var  = s2 * (1.f / DD) - mean * mean;
    float inv  = rsqrtf(var + 1e-5f);
    __nv_bfloat162* orow = (__nv_bfloat162*)(out + (size_t)row * DD);
    #pragma unroll
    for (int i = 0; i < 6; i++) {
        float4 gg = ((const float4*)gw)[lane + 32 * i];
        float4 bb = ((const float4*)bw)[lane + 32 * i];
        float ox = (v[i].x - mean) * inv * gg.x + bb.x;
        float oy = (v[i].y - mean) * inv * gg.y + bb.y;
        float oz = (v[i].z - mean) * inv * gg.z + bb.z;
        float ow = (v[i].w - mean) * inv * gg.w + bb.w;
        orow[(lane + 32 * i) * 2]     = __floats2bfloat162_rn(ox, oy);
        orow[(lane + 32 * i) * 2 + 1] = __floats2bfloat162_rn(oz, ow);
    }
}

// ---------------- temporal bias w/ masks baked in ----------------
__global__ __launch_bounds__(256) void bias_kernel(const float* __restrict__ tm,
                                                   const int* __restrict__ pm,
                                                   const float* __restrict__ t1w,
                                                   const float* __restrict__ t1b,
                                                   const float* __restrict__ t2w,
                                                   const float* __restrict__ t2b) {
    __shared__ float w1[TBN], b1[TBN], w2[TBN];
    int t = threadIdx.x;
    if (t < TBN) { w1[t] = t1w[t]; b1[t] = t1b[t]; w2[t] = t2w[t]; }
    __syncthreads();
    size_t idx = (size_t)blockIdx.x * 256 + t;
    int rem = (int)(idx % (TT * TT));
    int i = rem / TT, j = rem % TT;
    float u = __fdividef(1.f, __logf(E_CONST + tm[idx]));
    float s = t2b[0];
    #pragma unroll
    for (int k = 0; k < TBN; k++) {
        float z = fmaf(u, w1[k], b1[k]);
        z = (z > 0.f) ? z : 0.2f * z;
        s = fmaf(z, w2[k], s);
    }
    bool masked = (pm[idx] == 0) || (j > i && i > 0);
    g_scratch[OF_BIAS + idx] = masked ? NEGV : s;
}

// =======================================================================
// flash attention (validated tf32 version, longest-first) — unchanged
// =======================================================================
#define SQ_LD 68
#define SV_LD 72
#define FS_Q    0
#define FS_K    (64*68)
#define FS_V    (FS_K + 2*64*68)
#define FS_P    (FS_V + 2*64*72)
#define FS_STAT (FS_P + 64*68)
#define FS_TOT  ((FS_STAT + 256) * 4)

__global__ __launch_bounds__(256, 2) void flash_kernel(const float* __restrict__ qkv,
                                                       float* __restrict__ outA) {
    extern __shared__ float fs[];
    float* sQ = fs + FS_Q;
    float* sK = fs + FS_K;
    float* sV = fs + FS_V;
    float* sP = fs + FS_P;
    float* sMax = fs + FS_STAT;
    float* sSum = fs + FS_STAT + 128;
    uint32_t sKu = smem_u32(sK), sVu = smem_u32(sV);

    int tid = threadIdx.x;
    int warp = tid >> 5, lane = tid & 31;
    int wm = warp >> 1, wn = warp & 1;
    int g = lane >> 2, tig = lane & 3;
    int i0 = (gridDim.x - 1 - blockIdx.x) * 64;
    int bh = blockIdx.y, b = bh / HH, h = bh % HH;

    const float* base = qkv + (size_t)b * TT * 2304 + h * 64;
    const float* biasB = g_scratch + OF_BIAS + (size_t)b * TT * TT;

    for (int ch = tid; ch < 1024; ch += 256) {
        int r = ch >> 4, cc = (ch & 15) * 4;
        float4 v = *(const float4*)(base + (size_t)(i0 + r) * 2304 + cc);
        float4 o;
        o.x = f2tf32f(v.x * 0.125f); o.y = f2tf32f(v.y * 0.125f);
        o.z = f2tf32f(v.z * 0.125f); o.w = f2tf32f(v.w * 0.125f);
        *(float4*)(sQ + r * SQ_LD + cc) = o;
    }

    float o[4][4];
    #pragma unroll
    for (int j = 0; j < 4; j++)
        #pragma unroll
        for (int e = 0; e < 4; e++) o[j][e] = 0.f;
    float m0r = -INFINITY, m1r = -INFINITY, l0 = 0.f, l1 = 0.f;

    int ntiles = (i0 == 0) ? (TT / 64) : (i0 >> 6) + 1;
    int rw0 = wm * 16 + g, rw1 = rw0 + 8;

    {
        const float* kb_ = base + 768;
        const float* vb_ = base + 1536;
        for (int ch = tid; ch < 1024; ch += 256) {
            int r = ch >> 4, cc = (ch & 15) * 4;
            CP_ASYNC16(sKu + (r * SQ_LD + cc) * 4, kb_ + (size_t)r * 2304 + cc);
            CP_ASYNC16(sVu + (r * SV_LD + cc) * 4, vb_ + (size_t)r * 2304 + cc);
        }
        CP_COMMIT();
    }

    for (int t = 0; t < ntiles; t++) {
        int j0 = t * 64, buf = t & 1;
        CP_WAIT0();
        __syncthreads();

        float c[4][4];
        #pragma unroll
        for (int j = 0; j < 4; j++)
            #pragma unroll
            for (int e = 0; e < 4; e++) c[j][e] = 0.f;
        const float* kS = sK + buf * 64 * SQ_LD;
        #pragma unroll
        for (int kb = 0; kb < 64; kb += 8) {
            uint32_t a[4], bfr[4][2];
            int qr = wm * 16;
            a[0] = __float_as_uint(sQ[(qr + g)     * SQ_LD + kb + tig]);
            a[1] = __float_as_uint(sQ[(qr + 8 + g) * SQ_LD + kb + tig]);
            a[2] = __float_as_uint(sQ[(qr + g)     * SQ_LD + kb + tig + 4]);
            a[3] = __float_as_uint(sQ[(qr + 8 + g) * SQ_LD + kb + tig + 4]);
            #pragma unroll
            for (int j = 0; j < 4; j++) {
                int r = wn * 32 + j * 8 + g;
                bfr[j][0] = __float_as_uint(kS[r * SQ_LD + kb + tig]);
                bfr[j][1] = __float_as_uint(kS[r * SQ_LD + kb + tig + 4]);
            }
            #pragma unroll
            for (int j = 0; j < 4; j++)
                MMA_TF32(c[j][0], c[j][1], c[j][2], c[j][3],
                         a[0], a[1], a[2], a[3], bfr[j][0], bfr[j][1]);
        }

        int gi0 = i0 + rw0, gi1 = i0 + rw1;
        #pragma unroll
        for (int j = 0; j < 4; j++) {
            int gj = j0 + wn * 32 + j * 8 + 2 * tig;
            float2 b0 = *(const float2*)(biasB + (size_t)gi0 * TT + gj);
            float2 b1 = *(const float2*)(biasB + (size_t)gi1 * TT + gj);
            c[j][0] += b0.x; c[j][1] += b0.y;
            c[j][2] += b1.x; c[j][3] += b1.y;
        }

        float mx0 = c[0][0], mx1 = c[0][2];
        #pragma unroll
        for (int j = 0; j < 4; j++) {
            mx0 = fmaxf(mx0, fmaxf(c[j][0], c[j][1]));
            mx1 = fmaxf(mx1, fmaxf(c[j][2], c[j][3]));
        }
        mx0 = fmaxf(mx0, __shfl_xor_sync(0xffffffffu, mx0, 1));
        mx0 = fmaxf(mx0, __shfl_xor_sync(0xffffffffu, mx0, 2));
        mx1 = fmaxf(mx1, __shfl_xor_sync(0xffffffffu, mx1, 1));
        mx1 = fmaxf(mx1, __shfl_xor_sync(0xffffffffu, mx1, 2));
        if (tig == 0) { sMax[wn * 64 + rw0] = mx0; sMax[wn * 64 + rw1] = mx1; }
        __syncthreads();
        float mxc0 = fmaxf(sMax[rw0], sMax[64 + rw0]);
        float mxc1 = fmaxf(sMax[rw1], sMax[64 + rw1]);

        float mn0 = fmaxf(m0r, mxc0), mn1 = fmaxf(m1r, mxc1);
        float al0 = __expf(m0r - mn0), al1 = __expf(m1r - mn1);

        float sum0 = 0.f, sum1 = 0.f;
        #pragma unroll
        for (int j = 0; j < 4; j++) {
            int cw = wn * 32 + j * 8 + 2 * tig;
            float p00 = __expf(c[j][0] - mn0), p01 = __expf(c[j][1] - mn0);
            float p10 = __expf(c[j][2] - mn1), p11 = __expf(c[j][3] - mn1);
            sum0 += p00 + p01; sum1 += p10 + p11;
            float2 q0; q0.x = p00; q0.y = p01;
            float2 q1; q1.x = p10; q1.y = p11;
            *(float2*)(sP + rw0 * SQ_LD + cw) = q0;
            *(float2*)(sP + rw1 * SQ_LD + cw) = q1;
        }
        sum0 += __shfl_xor_sync(0xffffffffu, sum0, 1);
        sum0 += __shfl_xor_sync(0xffffffffu, sum0, 2);
        sum1 += __shfl_xor_sync(0xffffffffu, sum1, 1);
        sum1 += __shfl_xor_sync(0xffffffffu, sum1, 2);
        if (tig == 0) { sSum[wn * 64 + rw0] = sum0; sSum[wn * 64 + rw1] = sum1; }
        __syncthreads();
        float sc0 = sSum[rw0] + sSum[64 + rw0];
        float sc1 = sSum[rw1] + sSum[64 + rw1];

        l0 = l0 * al0 + sc0;  l1 = l1 * al1 + sc1;
        m0r = mn0;  m1r = mn1;
        #pragma unroll
        for (int j = 0; j < 4; j++) {
            o[j][0] *= al0; o[j][1] *= al0;
            o[j][2] *= al1; o[j][3] *= al1;
        }

        if (t + 1 < ntiles) {
            int nj0 = (t + 1) * 64, nb = buf ^ 1;
            const float* kb_ = base + 768;
            const float* vb_ = base + 1536;
            for (int ch = tid; ch < 1024; ch += 256) {
                int r = ch >> 4, cc = (ch & 15) * 4;
                CP_ASYNC16(sKu + (nb * 64 * SQ_LD + r * SQ_LD + cc) * 4, kb_ + (size_t)(nj0 + r) * 2304 + cc);
                CP_ASYNC16(sVu + (nb * 64 * SV_LD + r * SV_LD + cc) * 4, vb_ + (size_t)(nj0 + r) * 2304 + cc);
            }
            CP_COMMIT();
        }

        const float* vS = sV + buf * 64 * SV_LD;
        #pragma unroll
        for (int kb = 0; kb < 64; kb += 8) {
            uint32_t a[4], bfr[4][2];
            int pr = wm * 16;
            a[0] = __float_as_uint(sP[(pr + g)     * SQ_LD + kb + tig]);
            a[1] = __float_as_uint(sP[(pr + 8 + g) * SQ_LD + kb + tig]);
            a[2] = __float_as_uint(sP[(pr + g)     * SQ_LD + kb + tig + 4]);
            a[3] = __float_as_uint(sP[(pr + 8 + g) * SQ_LD + kb + tig + 4]);
            #pragma unroll
            for (int j = 0; j < 4; j++) {
                int nc = wn * 32 + j * 8 + g;
                bfr[j][0] = __float_as_uint(vS[(kb + tig)     * SV_LD + nc]);
                bfr[j][1] = __float_as_uint(vS[(kb + tig + 4) * SV_LD + nc]);
            }
            #pragma unroll
            for (int j = 0; j < 4; j++)
                MMA_TF32(o[j][0], o[j][1], o[j][2], o[j][3],
                         a[0], a[1], a[2], a[3], bfr[j][0], bfr[j][1]);
        }
        __syncthreads();
    }

    float inv0 = 1.f / l0, inv1 = 1.f / l1;
    int gr0 = b * TT + i0 + wm * 16 + g, gr1 = gr0 + 8;
    #pragma unroll
    for (int j = 0; j < 4; j++) {
        int col = h * 64 + wn * 32 + j * 8 + 2 * tig;
        float2 o0, o1;
        o0.x = f2tf32f(o[j][0] * inv0); o0.y = f2tf32f(o[j][1] * inv0);
        o1.x = f2tf32f(o[j][2] * inv1); o1.y = f2tf32f(o[j][3] * inv1);
        *(float2*)(outA + (size_t)gr0 * DD + col) = o0;
        *(float2*)(outA + (size_t)gr1 * DD + col) = o1;
    }
}

// ---------------- launch ----------------
extern "C" void kernel_launch(void* const* d_in, const int* in_sizes, int n_in,
                              void* d_out, int out_size) {
    const float* x     = (const float*)d_in[0];
    const float* tmat  = (const float*)d_in[1];
    const int*   pm    = (const int*)d_in[2];
    const float* wq = (const float*)d_in[3],  *bq = (const float*)d_in[4];
    const float* wk = (const float*)d_in[5],  *bk = (const float*)d_in[6];
    const float* wv = (const float*)d_in[7],  *bv = (const float*)d_in[8];
    const float* wp = (const float*)d_in[9],  *bp = (const float*)d_in[10];
    const float* t1w = (const float*)d_in[11], *t1b = (const float*)d_in[12];
    const float* t2w = (const float*)d_in[13], *t2b = (const float*)d_in[14];
    const float* f1w = (const float*)d_in[15], *f1b = (const float*)d_in[16];
    const float* f2w = (const float*)d_in[17], *f2b = (const float*)d_in[18];
    const float* ln1g = (const float*)d_in[19], *ln1b = (const float*)d_in[20];
    const float* ln2g = (const float*)d_in[21], *ln2b = (const float*)d_in[22];
    float* out = (float*)d_out;

    float* sc = nullptr;
    cudaGetSymbolAddress((void**)&sc, g_scratch);
    __nv_bfloat16* gH  = (__nv_bfloat16*)(sc + OF_H);
    float* gQKV  = sc + OF_QKV;
    float* gA    = sc + OF_A;
    float* gX2   = sc + OF_X2;
    float* gF    = sc + OF_F;
    __nv_bfloat16* wcT = (__nv_bfloat16*)(sc + OF_WQT);
    float* wpT   = sc + OF_WPT;
    __nv_bfloat16* f1T = (__nv_bfloat16*)(sc + OF_F1T);
    float* f2T   = sc + OF_F2T;

    static cudaStream_t sBias = nullptr, sTr = nullptr;
    static cudaEvent_t eFork = nullptr, eBias = nullptr, eTr = nullptr, eTr2 = nullptr;
    if (sBias == nullptr) {
        cudaStreamCreateWithFlags(&sBias, cudaStreamNonBlocking);
        cudaStreamCreateWithFlags(&sTr, cudaStreamNonBlocking);
        cudaEventCreateWithFlags(&eFork, cudaEventDisableTiming);
        cudaEventCreateWithFlags(&eBias, cudaEventDisableTiming);
        cudaEventCreateWithFlags(&eTr, cudaEventDisableTiming);
        cudaEventCreateWithFlags(&eTr2, cudaEventDisableTiming);
        cudaFuncSetAttribute(gemm_bf16<0>, cudaFuncAttributeMaxDynamicSharedMemorySize, GEMM_SMEMH);
        cudaFuncSetAttribute(gemm_bf16<2>, cudaFuncAttributeMaxDynamicSharedMemorySize, GEMM_SMEMH);
        cudaFuncSetAttribute(gemm_n96, cudaFuncAttributeMaxDynamicSharedMemorySize, GEMM_SMEM3);
        cudaFuncSetAttribute(flash_kernel, cudaFuncAttributeMaxDynamicSharedMemorySize, FS_TOT);
    }

    dim3 tb(32, 8);

    // fork
    cudaEventRecord(eFork, 0);
    cudaStreamWaitEvent(sBias, eFork, 0);
    cudaStreamWaitEvent(sTr, eFork, 0);

    bias_kernel<<<(BB * TT * TT) / 256, 256, 0, sBias>>>(tmat, pm, t1w, t1b, t2w, t2b);
    cudaEventRecord(eBias, sBias);

    transpose_attn<<<dim3(24, 24, 3), tb, 0, sTr>>>(wq, wk, wv, wcT);
    cudaEventRecord(eTr, sTr);
    transpose_ffn<<<dim3(96, 24, 3), tb, 0, sTr>>>(f1w, f1T, f2w, f2T, wp, wpT);
    cudaEventRecord(eTr2, sTr);

    // main chain
    ln_kernel<<<MROWS / 8, 256>>>(x, ln1g, ln1b, gH);
    cudaStreamWaitEvent(0, eTr, 0);
    gemm_bf16<0><<<dim3(2304 / 128, MROWS / BM), 256, GEMM_SMEMH>>>(gH, wcT, bq, bk, bv, gQKV, 2304, DD);

    cudaStreamWaitEvent(0, eBias, 0);
    flash_kernel<<<dim3(TT / 64, BB * HH), 256, FS_TOT>>>(gQKV, gA);

    cudaStreamWaitEvent(0, eTr2, 0);
    gemm_n96<<<dim3(DD / BN3, MROWS / BM), 256, GEMM_SMEM3>>>(gA, wpT, bp, x, gX2, DD, DD);

    ln_kernel<<<MROWS / 8, 256>>>(gX2, ln2g, ln2b, gH);
    gemm_bf16<2><<<dim3(FFC / 128, MROWS / BM), 256, GEMM_SMEMH>>>(gH, f1T, f1b, nullptr, nullptr, gF, FFC, DD);
    gemm_n96<<<dim3(DD / BN3, MROWS / BM), 256, GEMM_SMEM3>>>(gF, f2T, f2b, gX2, out, DD, FFC);
}

// round 15
// speedup vs baseline: 1.2158x; 1.0018x over previous
#include <cuda_runtime.h>
#include <cuda_bf16.h>
#include <math.h>
#include <stdint.h>

// ---------------- problem constants ----------------
#define BB 4
#define TT 512
#define DD 768
#define HH 12
#define FFC 3072
#define TBN 64
#define NEGV (-1e9f)
#define E_CONST 2.718281828459045f
#define MROWS (BB*TT)            // 2048

// ---------------- scratch layout (float offsets) ----------------
#define OF_H    0ull             // LN out (bf16)
#define OF_BIAS 6291456ull       // temporal bias w/ masks (bf16)
#define OF_S    7340032ull
#define OF_QKV  OF_S
#define OF_A    19922944ull
#define OF_X2   21495808ull
#define OF_F    23068672ull
#define OF_WQT  29360128ull      // wq|wk|wv transposed, bf16
#define OF_WPT  31129600ull      // f32 tf32
#define OF_F1T  31719424ull      // bf16
#define OF_F2T  34078720ull      // f32 tf32
#define SCRATCH_TOTAL 36438016ull

__device__ float g_scratch[SCRATCH_TOTAL];

// ---------------- helpers ----------------
__device__ __forceinline__ uint32_t smem_u32(const void* p) {
    uint32_t a;
    asm("{ .reg .u64 t; cvta.to.shared.u64 t, %1; cvt.u32.u64 %0, t; }" : "=r"(a) : "l"(p));
    return a;
}
__device__ __forceinline__ float f2tf32f(float f) {
    uint32_t r; asm("cvt.rna.tf32.f32 %0, %1;" : "=r"(r) : "f"(f));
    return __uint_as_float(r);
}
#define CP_ASYNC16(dst_u32, src_ptr) \
    asm volatile("cp.async.cg.shared.global [%0], [%1], 16;\n" :: "r"(dst_u32), "l"(__cvta_generic_to_global(src_ptr)))
#define CP_COMMIT() asm volatile("cp.async.commit_group;\n" ::: "memory")
#define CP_WAIT2()  asm volatile("cp.async.wait_group 2;\n" ::: "memory")
#define CP_WAIT0()  asm volatile("cp.async.wait_group 0;\n" ::: "memory")

#define MMA_TF32(c0,c1,c2,c3,a0,a1,a2,a3,b0,b1) \
    asm volatile("mma.sync.aligned.m16n8k8.row.col.f32.tf32.tf32.f32 " \
                 "{%0,%1,%2,%3}, {%4,%5,%6,%7}, {%8,%9}, {%0,%1,%2,%3};\n" \
                 : "+f"(c0), "+f"(c1), "+f"(c2), "+f"(c3) \
                 : "r"(a0), "r"(a1), "r"(a2), "r"(a3), "r"(b0), "r"(b1))

#define MMA_BF16(c0,c1,c2,c3,a0,a1,a2,a3,b0,b1) \
    asm volatile("mma.sync.aligned.m16n8k16.row.col.f32.bf16.bf16.f32 " \
                 "{%0,%1,%2,%3}, {%4,%5,%6,%7}, {%8,%9}, {%0,%1,%2,%3};\n" \
                 : "+f"(c0), "+f"(c1), "+f"(c2), "+f"(c3) \
                 : "r"(a0), "r"(a1), "r"(a2), "r"(a3), "r"(b0), "r"(b1))

#define LDSM_X4(d0,d1,d2,d3,addr) \
    asm volatile("ldmatrix.sync.aligned.m8n8.x4.shared.b16 {%0,%1,%2,%3}, [%4];\n" \
                 : "=r"(d0), "=r"(d1), "=r"(d2), "=r"(d3) : "r"(addr))

#define LDT 20
#define BM 128

// =======================================================================
// bf16 GEMM — 128x128 tile, BK=32, 4-stage, warp tile 32x64. (validated R14)
// =======================================================================
#define LDTH 40
#define GSTH 4
#define GEMM_SMEMH (GSTH * 2 * BM * LDTH * 2) // 81920 B

template <int EPI>
__global__ __launch_bounds__(256, 2) void gemm_bf16(const __nv_bfloat16* __restrict__ A,
                                                    const __nv_bfloat16* __restrict__ Wt,
                                                    const float* __restrict__ bias0,
                                                    const float* __restrict__ bias1,
                                                    const float* __restrict__ bias2,
                                                    float* __restrict__ C,
                                                    int N, int K) {
    extern __shared__ char hsm[];
    char* AsBase = hsm;
    char* BsBase = hsm + GSTH * BM * LDTH * 2;

    int tid = threadIdx.x;
    int warp = tid >> 5, lane = tid & 31;
    int wm = warp >> 1, wn = warp & 1;
    int g = lane >> 2, tig = lane & 3;
    int m0 = blockIdx.y * BM, n0 = blockIdx.x * 128;

    int r0 = tid >> 2,       c0_ = (tid & 3) * 8;
    int r1 = r0 + 64,        c1_ = c0_;

    uint32_t sA = smem_u32(AsBase);
    uint32_t sB = smem_u32(BsBase);
    const uint32_t bufA = BM * LDTH * 2, bufB = 128 * LDTH * 2;

    int l15 = lane & 15, kh = lane >> 4;
    uint32_t aAddr0 = sA + (uint32_t)((wm * 32 + l15) * LDTH) * 2 + kh * 16;
    uint32_t bAddr0 = sB + (uint32_t)((wn * 64 + l15) * LDTH) * 2 + kh * 16;

    const int nk = K >> 5;

    #pragma unroll
    for (int pf = 0; pf < 3; pf++) {
        int k0 = pf * 32;
        CP_ASYNC16(sA + pf * bufA + (r0 * LDTH + c0_) * 2, A + (size_t)(m0 + r0) * K + k0 + c0_);
        CP_ASYNC16(sA + pf * bufA + (r1 * LDTH + c1_) * 2, A + (size_t)(m0 + r1) * K + k0 + c1_);
        CP_ASYNC16(sB + pf * bufB + (r0 * LDTH + c0_) * 2, Wt + (size_t)(n0 + r0) * K + k0 + c0_);
        CP_ASYNC16(sB + pf * bufB + (r1 * LDTH + c1_) * 2, Wt + (size_t)(n0 + r1) * K + k0 + c1_);
        CP_COMMIT();
    }

    float c[2][8][4];
    #pragma unroll
    for (int i = 0; i < 2; i++)
        #pragma unroll
        for (int j = 0; j < 8; j++)
            #pragma unroll
            for (int e = 0; e < 4; e++) c[i][j][e] = 0.f;

    for (int kt = 0; kt < nk; kt++) {
        int buf = kt & (GSTH - 1);
        CP_WAIT2();
        __syncthreads();

        uint32_t aBuf = aAddr0 + buf * bufA;
        uint32_t bBuf = bAddr0 + buf * bufB;
        #pragma unroll
        for (int ks = 0; ks < 2; ks++) {
            uint32_t kOff = (uint32_t)(ks * 32);
            uint32_t a[2][4], b[8][2];
            #pragma unroll
            for (int i = 0; i < 2; i++)
                LDSM_X4(a[i][0], a[i][1], a[i][2], a[i][3],
                        aBuf + (uint32_t)(i * 16 * LDTH) * 2 + kOff);
            #pragma unroll
            for (int p = 0; p < 4; p++)
                LDSM_X4(b[2*p][0], b[2*p+1][0], b[2*p][1], b[2*p+1][1],
                        bBuf + (uint32_t)(p * 16 * LDTH) * 2 + kOff);
            #pragma unroll
            for (int i = 0; i < 2; i++)
                #pragma unroll
                for (int j = 0; j < 8; j++)
                    MMA_BF16(c[i][j][0], c[i][j][1], c[i][j][2], c[i][j][3],
                             a[i][0], a[i][1], a[i][2], a[i][3], b[j][0], b[j][1]);
        }

        if (kt + 3 < nk) {
            int k0 = (kt + 3) * 32;
            int nbuf = (kt + 3) & (GSTH - 1);
            CP_ASYNC16(sA + nbuf * bufA + (r0 * LDTH + c0_) * 2, A + (size_t)(m0 + r0) * K + k0 + c0_);
            CP_ASYNC16(sA + nbuf * bufA + (r1 * LDTH + c1_) * 2, A + (size_t)(m0 + r1) * K + k0 + c1_);
            CP_ASYNC16(sB + nbuf * bufB + (r0 * LDTH + c0_) * 2, Wt + (size_t)(n0 + r0) * K + k0 + c0_);
            CP_ASYNC16(sB + nbuf * bufB + (r1 * LDTH + c1_) * 2, Wt + (size_t)(n0 + r1) * K + k0 + c1_);
        }
        CP_COMMIT();
    }

    #pragma unroll
    for (int i = 0; i < 2; i++) {
        int row0 = m0 + wm * 32 + i * 16 + g;
        #pragma unroll
        for (int j = 0; j < 8; j++) {
            int col = n0 + wn * 64 + j * 8 + 2 * tig;
            float b0, b1;
            if (EPI == 0) {
                const float* bp = (col < 768) ? bias0 : (col < 1536) ? bias1 : bias2;
                int bo = (col < 768) ? col : (col < 1536) ? col - 768 : col - 1536;
                b0 = bp[bo]; b1 = bp[bo + 1];
            } else {
                b0 = bias0[col]; b1 = bias0[col + 1];
            }
            #pragma unroll
            for (int half = 0; half < 2; half++) {
                int r = row0 + half * 8;
                float v0 = c[i][j][half * 2 + 0] + b0;
                float v1 = c[i][j][half * 2 + 1] + b1;
                if (EPI == 2) {
                    v0 = 0.5f * v0 * (1.f + erff(v0 * 0.70710678118654752f));
                    v1 = 0.5f * v1 * (1.f + erff(v1 * 0.70710678118654752f));
                    v0 = f2tf32f(v0); v1 = f2tf32f(v1);
                }
                float2 o; o.x = v0; o.y = v1;
                *(float2*)(C + (size_t)r * N + col) = o;
            }
        }
    }
}

// =======================================================================
// n96 tf32 GEMM — 128x96, 4-stage, warp tile 32x48, bias+residual. (validated)
// =======================================================================
#define BN3 96
#define GST3 4
#define GEMM_SMEM3 ((GST3*(BM+BN3)*LDT)*4)   // 71680

__global__ __launch_bounds__(256, 2) void gemm_n96(const float* __restrict__ A,
                                                   const float* __restrict__ Wt,
                                                   const float* __restrict__ bias,
                                                   const float* __restrict__ res,
                                                   float* __restrict__ C,
                                                   int N, int K) {
    extern __shared__ float dsm[];
    float* AsBase = dsm;
    float* BsBase = dsm + GST3 * BM * LDT;

    int tid = threadIdx.x;
    int warp = tid >> 5, lane = tid & 31;
    int wm = warp >> 1, wn = warp & 1;
    int g = lane >> 2, tig = lane & 3;
    int m0 = blockIdx.y * BM, n0 = blockIdx.x * BN3;

    int ar0 = tid >> 2,            ac0 = (tid & 3) * 4;
    int ar1 = (tid + 256) >> 2,    ac1 = ((tid + 256) & 3) * 4;
    int br0 = tid >> 2,            bc0 = (tid & 3) * 4;
    int br1 = (tid + 256) >> 2,    bc1 = ((tid + 256) & 3) * 4;
    bool hasB1 = (tid < 128);

    uint32_t sA = smem_u32(AsBase);
    uint32_t sB = smem_u32(BsBase);
    const uint32_t bufA = BM * LDT * 4, bufB = BN3 * LDT * 4;

    int q = lane >> 3, l7 = lane & 7;
    int a_row = wm * 32 + (q & 1) * 8 + l7,  a_col = (q >> 1) * 4;
    int b_row = wn * 48 + (q >> 1) * 8 + l7, b_col = (q & 1) * 4;
    uint32_t aAddr0 = sA + (uint32_t)(a_row * LDT + a_col) * 4;
    uint32_t bAddr0 = sB + (uint32_t)(b_row * LDT + b_col) * 4;

    const int nk = K >> 4;

    #pragma unroll
    for (int pf = 0; pf < 3; pf++) {
        int k0 = pf * 16;
        CP_ASYNC16(sA + pf * bufA + (ar0 * LDT + ac0) * 4, A + (size_t)(m0 + ar0) * K + k0 + ac0);
        CP_ASYNC16(sA + pf * bufA + (ar1 * LDT + ac1) * 4, A + (size_t)(m0 + ar1) * K + k0 + ac1);
        CP_ASYNC16(sB + pf * bufB + (br0 * LDT + bc0) * 4, Wt + (size_t)(n0 + br0) * K + k0 + bc0);
        if (hasB1)
            CP_ASYNC16(sB + pf * bufB + (br1 * LDT + bc1) * 4, Wt + (size_t)(n0 + br1) * K + k0 + bc1);
        CP_COMMIT();
    }

    float c[2][6][4];
    #pragma unroll
    for (int i = 0; i < 2; i++)
        #pragma unroll
        for (int j = 0; j < 6; j++)
            #pragma unroll
            for (int e = 0; e < 4; e++) c[i][j][e] = 0.f;

    for (int kt = 0; kt < nk; kt++) {
        int buf = kt & (GST3 - 1);
        CP_WAIT2();
        __syncthreads();

        uint32_t aBuf = aAddr0 + buf * bufA;
        uint32_t bBuf = bAddr0 + buf * bufB;
        #pragma unroll
        for (int ks = 0; ks < 2; ks++) {
            uint32_t kOff = (uint32_t)(ks * 8) * 4;
            uint32_t a[2][4], b[6][2];
            #pragma unroll
            for (int i = 0; i < 2; i++)
                LDSM_X4(a[i][0], a[i][1], a[i][2], a[i][3],
                        aBuf + (uint32_t)(i * 16 * LDT) * 4 + kOff);
            #pragma unroll
            for (int p = 0; p < 3; p++)
                LDSM_X4(b[2*p][0], b[2*p][1], b[2*p+1][0], b[2*p+1][1],
                        bBuf + (uint32_t)(p * 16 * LDT) * 4 + kOff);
            #pragma unroll
            for (int i = 0; i < 2; i++)
                #pragma unroll
                for (int j = 0; j < 6; j++)
                    MMA_TF32(c[i][j][0], c[i][j][1], c[i][j][2], c[i][j][3],
                             a[i][0], a[i][1], a[i][2], a[i][3], b[j][0], b[j][1]);
        }

        if (kt + 3 < nk) {
            int k0 = (kt + 3) * 16;
            int nbuf = (kt + 3) & (GST3 - 1);
            CP_ASYNC16(sA + nbuf * bufA + (ar0 * LDT + ac0) * 4, A + (size_t)(m0 + ar0) * K + k0 + ac0);
            CP_ASYNC16(sA + nbuf * bufA + (ar1 * LDT + ac1) * 4, A + (size_t)(m0 + ar1) * K + k0 + ac1);
            CP_ASYNC16(sB + nbuf * bufB + (br0 * LDT + bc0) * 4, Wt + (size_t)(n0 + br0) * K + k0 + bc0);
            if (hasB1)
                CP_ASYNC16(sB + nbuf * bufB + (br1 * LDT + bc1) * 4, Wt + (size_t)(n0 + br1) * K + k0 + bc1);
        }
        CP_COMMIT();
    }

    #pragma unroll
    for (int i = 0; i < 2; i++) {
        int row0 = m0 + wm * 32 + i * 16 + g;
        #pragma unroll
        for (int j = 0; j < 6; j++) {
            int col = n0 + wn * 48 + j * 8 + 2 * tig;
            float b0 = bias[col], b1 = bias[col + 1];
            #pragma unroll
            for (int half = 0; half < 2; half++) {
                int r = row0 + half * 8;
                float2 r2 = *(const float2*)(res + (size_t)r * N + col);
                float2 o;
                o.x = c[i][j][half * 2 + 0] + b0 + r2.x;
                o.y = c[i][j][half * 2 + 1] + b1 + r2.y;
                *(float2*)(C + (size_t)r * N + col) = o;
            }
        }
    }
}

// ---------------- transposes ----------------
__global__ __launch_bounds__(256) void transpose_attn(const float* __restrict__ wq,
                                                      const float* __restrict__ wk,
                                                      const float* __restrict__ wv,
                                                      __nv_bfloat16* __restrict__ dst) {
    __shared__ float t[32][33];
    int z = blockIdx.z;
    const float* W = (z == 0) ? wq : (z == 1) ? wk : wv;
    __nv_bfloat16* Wt = dst + (size_t)z * 589824;
    int n0 = blockIdx.x * 32, k0 = blockIdx.y * 32;
    int tx = threadIdx.x, ty = threadIdx.y;
    #pragma unroll
    for (int i = 0; i < 32; i += 8)
        t[ty + i][tx] = W[(size_t)(k0 + ty + i) * DD + n0 + tx];
    __syncthreads();
    #pragma unroll
    for (int i = 0; i < 32; i += 8)
        Wt[(size_t)(n0 + ty + i) * DD + k0 + tx] = __float2bfloat16(t[tx][ty + i]);
}

__global__ __launch_bounds__(256) void transpose_ffn(const float* __restrict__ f1w,
                                                     __nv_bfloat16* __restrict__ f1T,
                                                     const float* __restrict__ f2w,
                                                     float* __restrict__ f2T,
                                                     const float* __restrict__ wp,
                                                     float* __restrict__ wpT) {
    __shared__ float t[32][33];
    int z = blockIdx.z;
    const float* W; int K, N, n0, k0;
    if (z == 0)      { W = f1w; K = DD;  N = FFC; n0 = blockIdx.x * 32; k0 = blockIdx.y * 32; }
    else if (z == 1) { W = f2w; K = FFC; N = DD;  n0 = blockIdx.y * 32; k0 = blockIdx.x * 32; }
    else             { if (blockIdx.x >= 24) return;
                       W = wp;  K = DD;  N = DD;  n0 = blockIdx.x * 32; k0 = blockIdx.y * 32; }
    int tx = threadIdx.x, ty = threadIdx.y;
    #pragma unroll
    for (int i = 0; i < 32; i += 8)
        t[ty + i][tx] = W[(size_t)(k0 + ty + i) * N + n0 + tx];
    __syncthreads();
    #pragma unroll
    for (int i = 0; i < 32; i += 8) {
        float v = t[tx][ty + i];
        size_t off = (size_t)(n0 + ty + i) * K + k0 + tx;
        if (z == 0)      f1T[off] = __float2bfloat16(v);
        else if (z == 1) f2T[off] = f2tf32f(v);
        else             wpT[off] = f2tf32f(v);
    }
}

// ---------------- LayerNorm — warp-per-row, bf16 output ----------------
__global__ __launch_bounds__(256) void ln_kernel(const float* __restrict__ x,
                                                 const float* __restrict__ gw,
                                                 const float* __restrict__ bw,
                                                 __nv_bfloat16* __restrict__ out) {
    int warp = threadIdx.x >> 5, lane = threadIdx.x & 31;
    int row = blockIdx.x * 8 + warp;
    const float4* xr = (const float4*)(x + (size_t)row * DD);
    float4 v[6];
    float s = 0.f, s2 = 0.f;
    #pragma unroll
    for (int i = 0; i < 6; i++) {
        v[i] = xr[lane + 32 * i];
        s  += v[i].x + v[i].y + v[i].z + v[i].w;
        s2 += v[i].x * v[i].x + v[i].y * v[i].y + v[i].z * v[i].z + v[i].w * v[i].w;
    }
    #pragma unroll
    for (int o = 16; o > 0; o >>= 1) {
        s  += __shfl_xor_sync(0xffffffffu, s,  o);
        s2 += __shfl_xor_sync(0xffffffffu, s2, o);
    }
    float mean = s * (1.f / DD);
    float var  = s2 * (1.f / DD) - mean * mean;
    float inv  = rsqrtf(var + 1e-5f);
    __nv_bfloat162* orow = (__nv_bfloat162*)(out + (size_t)row * DD);
    #pragma unroll
    for (int i = 0; i < 6; i++) {
        float4 gg = ((const float4*)gw)[lane + 32 * i];
        float4 bb = ((const float4*)bw)[lane + 32 * i];
        float ox = (v[i].x - mean) * inv * gg.x + bb.x;
        float oy = (v[i].y - mean) * inv * gg.y + bb.y;
        float oz = (v[i].z - mean) * inv * gg.z + bb.z;
        float ow = (v[i].w - mean) * inv * gg.w + bb.w;
        orow[(lane + 32 * i) * 2]     = __floats2bfloat162_rn(ox, oy);
        orow[(lane + 32 * i) * 2 + 1] = __floats2bfloat162_rn(oz, ow);
    }
}

// ---------------- temporal bias w/ masks baked in -> bf16 ----------------
__global__ __launch_bounds__(256) void bias_kernel(const float* __restrict__ tm,
                                                   const int* __restrict__ pm,
                                                   const float* __restrict__ t1w,
                                                   const float* __restrict__ t1b,
                                                   const float* __restrict__ t2w,
                                                   const float* __restrict__ t2b) {
    __shared__ float w1[TBN], b1[TBN], w2[TBN];
    int t = threadIdx.x;
    if (t < TBN) { w1[t] = t1w[t]; b1[t] = t1b[t]; w2[t] = t2w[t]; }
    __syncthreads();
    size_t idx = (size_t)blockIdx.x * 256 + t;
    int rem = (int)(idx % (TT * TT));
    int i = rem / TT, j = rem % TT;
    float u = __fdividef(1.f, __logf(E_CONST + tm[idx]));
    float s = t2b[0];
    #pragma unroll
    for (int k = 0; k < TBN; k++) {
        float z = fmaf(u, w1[k], b1[k]);
        z = (z > 0.f) ? z : 0.2f * z;
        s = fmaf(z, w2[k], s);
    }
    bool masked = (pm[idx] == 0) || (j > i && i > 0);
    ((__nv_bfloat16*)(g_scratch + OF_BIAS))[idx] = __float2bfloat16(masked ? NEGV : s);
}

// =======================================================================
// flash attention — bf16 bias reads; otherwise validated tf32 version
// =======================================================================
#define SQ_LD 68
#define SV_LD 72
#define FS_Q    0
#define FS_K    (64*68)
#define FS_V    (FS_K + 2*64*68)
#define FS_P    (FS_V + 2*64*72)
#define FS_STAT (FS_P + 64*68)
#define FS_TOT  ((FS_STAT + 256) * 4)

__global__ __launch_bounds__(256, 2) void flash_kernel(const float* __restrict__ qkv,
                                                       float* __restrict__ outA) {
    extern __shared__ float fs[];
    float* sQ = fs + FS_Q;
    float* sK = fs + FS_K;
    float* sV = fs + FS_V;
    float* sP = fs + FS_P;
    float* sMax = fs + FS_STAT;
    float* sSum = fs + FS_STAT + 128;
    uint32_t sKu = smem_u32(sK), sVu = smem_u32(sV);

    int tid = threadIdx.x;
    int warp = tid >> 5, lane = tid & 31;
    int wm = warp >> 1, wn = warp & 1;
    int g = lane >> 2, tig = lane & 3;
    int i0 = (gridDim.x - 1 - blockIdx.x) * 64;
    int bh = blockIdx.y, b = bh / HH, h = bh % HH;

    const float* base = qkv + (size_t)b * TT * 2304 + h * 64;
    const __nv_bfloat16* biasB = (const __nv_bfloat16*)(g_scratch + OF_BIAS) + (size_t)b * TT * TT;

    for (int ch = tid; ch < 1024; ch += 256) {
        int r = ch >> 4, cc = (ch & 15) * 4;
        float4 v = *(const float4*)(base + (size_t)(i0 + r) * 2304 + cc);
        float4 o;
        o.x = f2tf32f(v.x * 0.125f); o.y = f2tf32f(v.y * 0.125f);
        o.z = f2tf32f(v.z * 0.125f); o.w = f2tf32f(v.w * 0.125f);
        *(float4*)(sQ + r * SQ_LD + cc) = o;
    }

    float o[4][4];
    #pragma unroll
    for (int j = 0; j < 4; j++)
        #pragma unroll
        for (int e = 0; e < 4; e++) o[j][e] = 0.f;
    float m0r = -INFINITY, m1r = -INFINITY, l0 = 0.f, l1 = 0.f;

    int ntiles = (i0 == 0) ? (TT / 64) : (i0 >> 6) + 1;
    int rw0 = wm * 16 + g, rw1 = rw0 + 8;

    {
        const float* kb_ = base + 768;
        const float* vb_ = base + 1536;
        for (int ch = tid; ch < 1024; ch += 256) {
            int r = ch >> 4, cc = (ch & 15) * 4;
            CP_ASYNC16(sKu + (r * SQ_LD + cc) * 4, kb_ + (size_t)r * 2304 + cc);
            CP_ASYNC16(sVu + (r * SV_LD + cc) * 4, vb_ + (size_t)r * 2304 + cc);
        }
        CP_COMMIT();
    }

    for (int t = 0; t < ntiles; t++) {
        int j0 = t * 64, buf = t & 1;
        CP_WAIT0();
        __syncthreads();

        float c[4][4];
        #pragma unroll
        for (int j = 0; j < 4; j++)
            #pragma unroll
            for (int e = 0; e < 4; e++) c[j][e] = 0.f;
        const float* kS = sK + buf * 64 * SQ_LD;
        #pragma unroll
        for (int kb = 0; kb < 64; kb += 8) {
            uint32_t a[4], bfr[4][2];
            int qr = wm * 16;
            a[0] = __float_as_uint(sQ[(qr + g)     * SQ_LD + kb + tig]);
            a[1] = __float_as_uint(sQ[(qr + 8 + g) * SQ_LD + kb + tig]);
            a[2] = __float_as_uint(sQ[(qr + g)     * SQ_LD + kb + tig + 4]);
            a[3] = __float_as_uint(sQ[(qr + 8 + g) * SQ_LD + kb + tig + 4]);
            #pragma unroll
            for (int j = 0; j < 4; j++) {
                int r = wn * 32 + j * 8 + g;
                bfr[j][0] = __float_as_uint(kS[r * SQ_LD + kb + tig]);
                bfr[j][1] = __float_as_uint(kS[r * SQ_LD + kb + tig + 4]);
            }
            #pragma unroll
            for (int j = 0; j < 4; j++)
                MMA_TF32(c[j][0], c[j][1], c[j][2], c[j][3],
                         a[0], a[1], a[2], a[3], bfr[j][0], bfr[j][1]);
        }

        int gi0 = i0 + rw0, gi1 = i0 + rw1;
        #pragma unroll
        for (int j = 0; j < 4; j++) {
            int gj = j0 + wn * 32 + j * 8 + 2 * tig;
            __nv_bfloat162 hb0 = *(const __nv_bfloat162*)(biasB + (size_t)gi0 * TT + gj);
            __nv_bfloat162 hb1 = *(const __nv_bfloat162*)(biasB + (size_t)gi1 * TT + gj);
            float2 b0 = __bfloat1622float2(hb0);
            float2 b1 = __bfloat1622float2(hb1);
            c[j][0] += b0.x; c[j][1] += b0.y;
            c[j][2] += b1.x; c[j][3] += b1.y;
        }

        float mx0 = c[0][0], mx1 = c[0][2];
        #pragma unroll
        for (int j = 0; j < 4; j++) {
            mx0 = fmaxf(mx0, fmaxf(c[j][0], c[j][1]));
            mx1 = fmaxf(mx1, fmaxf(c[j][2], c[j][3]));
        }
        mx0 = fmaxf(mx0, __shfl_xor_sync(0xffffffffu, mx0, 1));
        mx0 = fmaxf(mx0, __shfl_xor_sync(0xffffffffu, mx0, 2));
        mx1 = fmaxf(mx1, __shfl_xor_sync(0xffffffffu, mx1, 1));
        mx1 = fmaxf(mx1, __shfl_xor_sync(0xffffffffu, mx1, 2));
        if (tig == 0) { sMax[wn * 64 + rw0] = mx0; sMax[wn * 64 + rw1] = mx1; }
        __syncthreads();
        float mxc0 = fmaxf(sMax[rw0], sMax[64 + rw0]);
        float mxc1 = fmaxf(sMax[rw1], sMax[64 + rw1]);

        float mn0 = fmaxf(m0r, mxc0), mn1 = fmaxf(m1r, mxc1);
        float al0 = __expf(m0r - mn0), al1 = __expf(m1r - mn1);

        float sum0 = 0.f, sum1 = 0.f;
        #pragma unroll
        for (int j = 0; j < 4; j++) {
            int cw = wn * 32 + j * 8 + 2 * tig;
            float p00 = __expf(c[j][0] - mn0), p01 = __expf(c[j][1] - mn0);
            float p10 = __expf(c[j][2] - mn1), p11 = __expf(c[j][3] - mn1);
            sum0 += p00 + p01; sum1 += p10 + p11;
            float2 q0; q0.x = p00; q0.y = p01;
            float2 q1; q1.x = p10; q1.y = p11;
            *(float2*)(sP + rw0 * SQ_LD + cw) = q0;
            *(float2*)(sP + rw1 * SQ_LD + cw) = q1;
        }
        sum0 += __shfl_xor_sync(0xffffffffu, sum0, 1);
        sum0 += __shfl_xor_sync(0xffffffffu, sum0, 2);
        sum1 += __shfl_xor_sync(0xffffffffu, sum1, 1);
        sum1 += __shfl_xor_sync(0xffffffffu, sum1, 2);
        if (tig == 0) { sSum[wn * 64 + rw0] = sum0; sSum[wn * 64 + rw1] = sum1; }
        __syncthreads();
        float sc0 = sSum[rw0] + sSum[64 + rw0];
        float sc1 = sSum[rw1] + sSum[64 + rw1];

        l0 = l0 * al0 + sc0;  l1 = l1 * al1 + sc1;
        m0r = mn0;  m1r = mn1;
        #pragma unroll
        for (int j = 0; j < 4; j++) {
            o[j][0] *= al0; o[j][1] *= al0;
            o[j][2] *= al1; o[j][3] *= al1;
        }

        if (t + 1 < ntiles) {
            int nj0 = (t + 1) * 64, nb = buf ^ 1;
            const float* kb_ = base + 768;
            const float* vb_ = base + 1536;
            for (int ch = tid; ch < 1024; ch += 256) {
                int r = ch >> 4, cc = (ch & 15) * 4;
                CP_ASYNC16(sKu + (nb * 64 * SQ_LD + r * SQ_LD + cc) * 4, kb_ + (size_t)(nj0 + r) * 2304 + cc);
                CP_ASYNC16(sVu + (nb * 64 * SV_LD + r * SV_LD + cc) * 4, vb_ + (size_t)(nj0 + r) * 2304 + cc);
            }
            CP_COMMIT();
        }

        const float* vS = sV + buf * 64 * SV_LD;
        #pragma unroll
        for (int kb = 0; kb < 64; kb += 8) {
            uint32_t a[4], bfr[4][2];
            int pr = wm * 16;
            a[0] = __float_as_uint(sP[(pr + g)     * SQ_LD + kb + tig]);
            a[1] = __float_as_uint(sP[(pr + 8 + g) * SQ_LD + kb + tig]);
            a[2] = __float_as_uint(sP[(pr + g)     * SQ_LD + kb + tig + 4]);
            a[3] = __float_as_uint(sP[(pr + 8 + g) * SQ_LD + kb + tig + 4]);
            #pragma unroll
            for (int j = 0; j < 4; j++) {
                int nc = wn * 32 + j * 8 + g;
                bfr[j][0] = __float_as_uint(vS[(kb + tig)     * SV_LD + nc]);
                bfr[j][1] = __float_as_uint(vS[(kb + tig + 4) * SV_LD + nc]);
            }
            #pragma unroll
            for (int j = 0; j < 4; j++)
                MMA_TF32(o[j][0], o[j][1], o[j][2], o[j][3],
                         a[0], a[1], a[2], a[3], bfr[j][0], bfr[j][1]);
        }
        __syncthreads();
    }

    float inv0 = 1.f / l0, inv1 = 1.f / l1;
    int gr0 = b * TT + i0 + wm * 16 + g, gr1 = gr0 + 8;
    #pragma unroll
    for (int j = 0; j < 4; j++) {
        int col = h * 64 + wn * 32 + j * 8 + 2 * tig;
        float2 o0, o1;
        o0.x = f2tf32f(o[j][0] * inv0); o0.y = f2tf32f(o[j][1] * inv0);
        o1.x = f2tf32f(o[j][2] * inv1); o1.y = f2tf32f(o[j][3] * inv1);
        *(float2*)(outA + (size_t)gr0 * DD + col) = o0;
        *(float2*)(outA + (size_t)gr1 * DD + col) = o1;
    }
}

// ---------------- launch ----------------
extern "C" void kernel_launch(void* const* d_in, const int* in_sizes, int n_in,
                              void* d_out, int out_size) {
    const float* x     = (const float*)d_in[0];
    const float* tmat  = (const float*)d_in[1];
    const int*   pm    = (const int*)d_in[2];
    const float* wq = (const float*)d_in[3],  *bq = (const float*)d_in[4];
    const float* wk = (const float*)d_in[5],  *bk = (const float*)d_in[6];
    const float* wv = (const float*)d_in[7],  *bv = (const float*)d_in[8];
    const float* wp = (const float*)d_in[9],  *bp = (const float*)d_in[10];
    const float* t1w = (const float*)d_in[11], *t1b = (const float*)d_in[12];
    const float* t2w = (const float*)d_in[13], *t2b = (const float*)d_in[14];
    const float* f1w = (const float*)d_in[15], *f1b = (const float*)d_in[16];
    const float* f2w = (const float*)d_in[17], *f2b = (const float*)d_in[18];
    const float* ln1g = (const float*)d_in[19], *ln1b = (const float*)d_in[20];
    const float* ln2g = (const float*)d_in[21], *ln2b = (const float*)d_in[22];
    float* out = (float*)d_out;

    float* sc = nullptr;
    cudaGetSymbolAddress((void**)&sc, g_scratch);
    __nv_bfloat16* gH  = (__nv_bfloat16*)(sc + OF_H);
    float* gQKV  = sc + OF_QKV;
    float* gA    = sc + OF_A;
    float* gX2   = sc + OF_X2;
    float* gF    = sc + OF_F;
    __nv_bfloat16* wcT = (__nv_bfloat16*)(sc + OF_WQT);
    float* wpT   = sc + OF_WPT;
    __nv_bfloat16* f1T = (__nv_bfloat16*)(sc + OF_F1T);
    float* f2T   = sc + OF_F2T;

    static cudaStream_t sBias = nullptr, sTr = nullptr;
    static cudaEvent_t eFork = nullptr, eBias = nullptr, eTr = nullptr, eTr2 = nullptr;
    if (sBias == nullptr) {
        cudaStreamCreateWithFlags(&sBias, cudaStreamNonBlocking);
        cudaStreamCreateWithFlags(&sTr, cudaStreamNonBlocking);
        cudaEventCreateWithFlags(&eFork, cudaEventDisableTiming);
        cudaEventCreateWithFlags(&eBias, cudaEventDisableTiming);
        cudaEventCreateWithFlags(&eTr, cudaEventDisableTiming);
        cudaEventCreateWithFlags(&eTr2, cudaEventDisableTiming);
        cudaFuncSetAttribute(gemm_bf16<0>, cudaFuncAttributeMaxDynamicSharedMemorySize, GEMM_SMEMH);
        cudaFuncSetAttribute(gemm_bf16<2>, cudaFuncAttributeMaxDynamicSharedMemorySize, GEMM_SMEMH);
        cudaFuncSetAttribute(gemm_n96, cudaFuncAttributeMaxDynamicSharedMemorySize, GEMM_SMEM3);
        cudaFuncSetAttribute(flash_kernel, cudaFuncAttributeMaxDynamicSharedMemorySize, FS_TOT);
    }

    dim3 tb(32, 8);

    // fork
    cudaEventRecord(eFork, 0);
    cudaStreamWaitEvent(sBias, eFork, 0);
    cudaStreamWaitEvent(sTr, eFork, 0);

    bias_kernel<<<(BB * TT * TT) / 256, 256, 0, sBias>>>(tmat, pm, t1w, t1b, t2w, t2b);
    cudaEventRecord(eBias, sBias);

    transpose_attn<<<dim3(24, 24, 3), tb, 0, sTr>>>(wq, wk, wv, wcT);
    cudaEventRecord(eTr, sTr);
    transpose_ffn<<<dim3(96, 24, 3), tb, 0, sTr>>>(f1w, f1T, f2w, f2T, wp, wpT);
    cudaEventRecord(eTr2, sTr);

    // main chain
    ln_kernel<<<MROWS / 8, 256>>>(x, ln1g, ln1b, gH);
    cudaStreamWaitEvent(0, eTr, 0);
    gemm_bf16<0><<<dim3(2304 / 128, MROWS / BM), 256, GEMM_SMEMH>>>(gH, wcT, bq, bk, bv, gQKV, 2304, DD);

    cudaStreamWaitEvent(0, eBias, 0);
    flash_kernel<<<dim3(TT / 64, BB * HH), 256, FS_TOT>>>(gQKV, gA);

    cudaStreamWaitEvent(0, eTr2, 0);
    gemm_n96<<<dim3(DD / BN3, MROWS / BM), 256, GEMM_SMEM3>>>(gA, wpT, bp, x, gX2, DD, DD);

    ln_kernel<<<MROWS / 8, 256>>>(gX2, ln2g, ln2b, gH);
    gemm_bf16<2><<<dim3(FFC / 128, MROWS / BM), 256, GEMM_SMEMH>>>(gH, f1T, f1b, nullptr, nullptr, gF, FFC, DD);
    gemm_n96<<<dim3(DD / BN3, MROWS / BM), 256, GEMM_SMEM3>>>(gF, f2T, f2b, gX2, out, DD, FFC);
}